// round 11
// baseline (speedup 1.0000x reference)
#include <cuda_runtime.h>
#include <cuda_bf16.h>
#include <cstdint>
#include <cstddef>

#define Nn 8
#define Bb 4
#define Tt 1024
#define Dd 512
#define Hh 4
#define HDc 128
#define Rr 64
#define BTc (Bb*Tt)
#define NROWS (Nn*BTc)
#define EPSV 1e-5f
#define INV_SQRT_HD 0.08838834764831845f
#define L2E 1.4426950408889634f
#define FSTR 136
#define NT (Tt/64)
#define FLASH_SMEM_HALF (5*64*FSTR)   // bf16 elements per group

// ---------------- device scratch ----------------
__device__ float g_mu[NROWS];
__device__ float g_rs[NROWS];
__device__ float g_maskf[Nn];
__device__ float g_invna;
__device__ __nv_bfloat16 g_xh[(size_t)NROWS*Dd];
__device__ __nv_bfloat16 g_xl[(size_t)NROWS*Dd];
__device__ __nv_bfloat16 g_Wqh[Nn*Dd*Dd];
__device__ __nv_bfloat16 g_Woh[Nn*Dd*Dd];
__device__ float g_Sq[Nn*Dd];
__device__ float g_Cq[Nn*Dd];
__device__ float g_M[Nn*128*Dd];
__device__ __nv_bfloat16 g_Mbh[Nn*128*Dd];
__device__ __nv_bfloat16 g_Mbl[Nn*128*Dd];
__device__ float g_SM[Nn*128];
__device__ float g_CM[Nn*128];
__device__ float g_kq[(size_t)NROWS*Rr];
__device__ float g_vq[(size_t)NROWS*Rr];
__device__ float g_kdecT[Rr*Dd];
__device__ float g_vdecT[Rr*Dd];
__device__ __nv_bfloat16 g_Kh[(size_t)Bb*Hh*Tt*HDc];
__device__ __nv_bfloat16 g_Vh[(size_t)Bb*Hh*Tt*HDc];
__device__ __nv_bfloat16 g_Qh[(size_t)NROWS*Dd];
__device__ __nv_bfloat16 g_AOh[(size_t)NROWS*Dd];

// ---------------- helpers ----------------
__device__ __forceinline__ uint32_t pk2(float x, float y)
{
    __nv_bfloat162 h = __float22bfloat162_rn(make_float2(x, y));
    return *reinterpret_cast<uint32_t*>(&h);
}

__device__ __forceinline__ void ldsm4(uint32_t* r, const __nv_bfloat16* p)
{
    uint32_t a = (uint32_t)__cvta_generic_to_shared((void*)p);
    asm volatile("ldmatrix.sync.aligned.m8n8.x4.shared.b16 {%0,%1,%2,%3}, [%4];\n"
                 : "=r"(r[0]), "=r"(r[1]), "=r"(r[2]), "=r"(r[3]) : "r"(a));
}

__device__ __forceinline__ void ldsm4t(uint32_t* r, const __nv_bfloat16* p)
{
    uint32_t a = (uint32_t)__cvta_generic_to_shared((void*)p);
    asm volatile("ldmatrix.sync.aligned.m8n8.x4.trans.shared.b16 {%0,%1,%2,%3}, [%4];\n"
                 : "=r"(r[0]), "=r"(r[1]), "=r"(r[2]), "=r"(r[3]) : "r"(a));
}

__device__ __forceinline__ void mmabf(float* d, const uint32_t* a, uint32_t b0, uint32_t b1)
{
    asm volatile("mma.sync.aligned.m16n8k16.row.col.f32.bf16.bf16.f32 "
                 "{%0,%1,%2,%3},{%4,%5,%6,%7},{%8,%9},{%0,%1,%2,%3};\n"
                 : "+f"(d[0]), "+f"(d[1]), "+f"(d[2]), "+f"(d[3])
                 : "r"(a[0]), "r"(a[1]), "r"(a[2]), "r"(a[3]), "r"(b0), "r"(b1));
}

__device__ __forceinline__ void cpa16(const void* smem_dst, const void* gsrc)
{
    uint32_t ds = (uint32_t)__cvta_generic_to_shared((void*)smem_dst);
    asm volatile("cp.async.cg.shared.global [%0], [%1], 16;\n" :: "r"(ds), "l"(gsrc));
}
#define CPCOMMIT() asm volatile("cp.async.commit_group;\n" ::: "memory")
#define CPWAIT0()  asm volatile("cp.async.wait_group 0;\n" ::: "memory")

// ---------------- mask decode ----------------
__global__ void k_mask(const unsigned char* __restrict__ p)
{
    if (threadIdx.x == 0) {
        bool isF = (p[0]==0 && p[1]==0 && p[2]==0x80 && p[3]==0x3f);
        bool isI = (!isF && p[1]==0 && p[2]==0 && p[3]==0 && (p[4]!=0 || p[5]==0));
        float na = 0.f;
        for (int n = 0; n < Nn; n++) {
            bool bit;
            if (isF)      bit = (((const float*)p)[n] != 0.f);
            else if (isI) bit = (((const int*)p)[n]   != 0);
            else          bit = (p[n] != 0);
            g_maskf[n] = bit ? 1.f : 0.f;
            na += bit ? 1.f : 0.f;
        }
        g_invna = 1.f / fmaxf(na, 1.f);
    }
}

// ---------------- LN row stats + bf16 hi/lo copy of x ----------------
__global__ __launch_bounds__(256) void k_lnstats(const float* __restrict__ x)
{
    int row  = blockIdx.x * 8 + (threadIdx.x >> 5);
    int lane = threadIdx.x & 31;
    const float4* xp = (const float4*)(x + (size_t)row * Dd);
    float s = 0.f, sq = 0.f;
    #pragma unroll
    for (int i = 0; i < 4; i++) {
        int j = lane + 32*i;
        float4 v = xp[j];
        s  += v.x + v.y + v.z + v.w;
        sq += v.x*v.x + v.y*v.y + v.z*v.z + v.w*v.w;
        __nv_bfloat16 bx = __float2bfloat16(v.x);
        __nv_bfloat16 by = __float2bfloat16(v.y);
        __nv_bfloat16 bz = __float2bfloat16(v.z);
        __nv_bfloat16 bw = __float2bfloat16(v.w);
        __nv_bfloat162 h01; h01.x = bx; h01.y = by;
        __nv_bfloat162 h23; h23.x = bz; h23.y = bw;
        uint2 uh = make_uint2(*(uint32_t*)&h01, *(uint32_t*)&h23);
        uint2 ul = make_uint2(pk2(v.x - __bfloat162float(bx), v.y - __bfloat162float(by)),
                              pk2(v.z - __bfloat162float(bz), v.w - __bfloat162float(bw)));
        *(uint2*)(g_xh + (size_t)row*Dd + 4*j) = uh;
        *(uint2*)(g_xl + (size_t)row*Dd + 4*j) = ul;
    }
    #pragma unroll
    for (int o = 16; o > 0; o >>= 1) {
        s  += __shfl_xor_sync(0xffffffffu, s,  o);
        sq += __shfl_xor_sync(0xffffffffu, sq, o);
    }
    if (lane == 0) {
        float mu  = s * (1.f / Dd);
        float var = sq * (1.f / Dd) - mu * mu;
        g_mu[row] = mu;
        g_rs[row] = rsqrtf(var + EPSV);
    }
}

// ---------------- w_o -> bf16 ----------------
__global__ __launch_bounds__(256) void k_convwo(const float* __restrict__ wo)
{
    int idx = blockIdx.x * 256 + threadIdx.x;
    float4 v = ((const float4*)wo)[idx];
    ((uint2*)g_Woh)[idx] = make_uint2(pk2(v.x, v.y), pk2(v.z, v.w));
}

// ---------------- M_raw[n] = comp @ w ----------------
__global__ __launch_bounds__(256) void k_compgemm(
    const float* __restrict__ kcomp, const float* __restrict__ vcomp,
    const float* __restrict__ wk,    const float* __restrict__ wv)
{
    __shared__ float As[32*68];
    __shared__ float Bs[32*68];
    const int n    = blockIdx.x;
    const int half = blockIdx.y;
    const int i0   = blockIdx.z * 64;
    const float* comp = (half == 0 ? kcomp : vcomp) + (size_t)n * Rr * Dd;
    const float* w    = (half == 0 ? wk    : wv   ) + (size_t)n * Dd * Dd;
    const int tid = threadIdx.x, ty = tid >> 4, tx = tid & 15;
    const int arA = tid & 63, acA = (tid >> 6) * 8;
    const int arB = tid & 31, acB = (tid >> 5) * 8;

    float acc[4][4] = {};
    for (int k0 = 0; k0 < Dd; k0 += 32) {
        float4 a0 = *(const float4*)(comp + (size_t)arA*Dd + k0 + acA);
        float4 a1 = *(const float4*)(comp + (size_t)arA*Dd + k0 + acA + 4);
        float4 b0 = *(const float4*)(w + (size_t)(k0+arB)*Dd + i0 + acB);
        float4 b1 = *(const float4*)(w + (size_t)(k0+arB)*Dd + i0 + acB + 4);
        __syncthreads();
        As[(acA+0)*68+arA]=a0.x; As[(acA+1)*68+arA]=a0.y; As[(acA+2)*68+arA]=a0.z; As[(acA+3)*68+arA]=a0.w;
        As[(acA+4)*68+arA]=a1.x; As[(acA+5)*68+arA]=a1.y; As[(acA+6)*68+arA]=a1.z; As[(acA+7)*68+arA]=a1.w;
        *(float4*)&Bs[arB*68 + acB]     = b0;
        *(float4*)&Bs[arB*68 + acB + 4] = b1;
        __syncthreads();
        #pragma unroll
        for (int kk = 0; kk < 32; kk++) {
            float4 a  = *(const float4*)&As[kk*68 + ty*4];
            float4 bb = *(const float4*)&Bs[kk*68 + tx*4];
            float av[4] = {a.x,a.y,a.z,a.w};
            float bv[4] = {bb.x,bb.y,bb.z,bb.w};
            #pragma unroll
            for (int i = 0; i < 4; i++)
                #pragma unroll
                for (int j = 0; j < 4; j++)
                    acc[i][j] = fmaf(av[i], bv[j], acc[i][j]);
        }
    }
    #pragma unroll
    for (int i = 0; i < 4; i++) {
        int row = n*128 + half*64 + ty*4 + i;
        float4 o = make_float4(acc[i][0], acc[i][1], acc[i][2], acc[i][3]);
        *(float4*)(g_M + (size_t)row*Dd + i0 + tx*4) = o;
    }
}

// ---------------- fold LN(kv) into M -> bf16 hi/lo; SM/CM ----------------
__global__ __launch_bounds__(256) void k_foldM(const float* __restrict__ lnw,
                                               const float* __restrict__ lnb)
{
    int row  = blockIdx.x * 8 + (threadIdx.x >> 5);
    int lane = threadIdx.x & 31;
    int n = row >> 7;
    const float* lw = lnw + n*Dd;
    const float* lb = lnb + n*Dd;
    const float* Mrow = g_M + (size_t)row * Dd;
    float sm = 0.f, cm = 0.f;
    for (int i = lane; i < Dd; i += 32) {
        float m = Mrow[i], w = lw[i], b = lb[i];
        float p = w * m;
        sm += p; cm += b * m;
        __nv_bfloat16 hb = __float2bfloat16(p);
        g_Mbh[(size_t)row*Dd + i] = hb;
        g_Mbl[(size_t)row*Dd + i] = __float2bfloat16(p - __bfloat162float(hb));
    }
    #pragma unroll
    for (int o = 16; o > 0; o >>= 1) {
        sm += __shfl_xor_sync(0xffffffffu, sm, o);
        cm += __shfl_xor_sync(0xffffffffu, cm, o);
    }
    if (lane == 0) { g_SM[row] = sm; g_CM[row] = cm; }
}

// ---------------- fold LN(q) into w_q -> bf16 ----------------
__global__ __launch_bounds__(256) void k_foldQ(const float* __restrict__ lnw,
                                               const float* __restrict__ lnb,
                                               const float* __restrict__ wq)
{
    int row  = blockIdx.x * 8 + (threadIdx.x >> 5);
    int lane = threadIdx.x & 31;
    int n = row >> 9;
    const float* lw = lnw + n*Dd;
    const float* lb = lnb + n*Dd;
    const float* wr = wq + (size_t)row * Dd;
    float sm = 0.f, cm = 0.f;
    for (int i = lane; i < Dd; i += 32) {
        float m = wr[i], w = lw[i], b = lb[i];
        float p = w * m;
        sm += p; cm += b * m;
        g_Wqh[(size_t)row*Dd + i] = __float2bfloat16(p);
    }
    #pragma unroll
    for (int o = 16; o > 0; o >>= 1) {
        sm += __shfl_xor_sync(0xffffffffu, sm, o);
        cm += __shfl_xor_sync(0xffffffffu, cm, o);
    }
    if (lane == 0) { g_Sq[row] = sm; g_Cq[row] = cm; }
}

// ------- bf16 GEMM 128x128xK512 with cp.async pipeline. MODE 0 = Q, 1 = O -------
template<int MODE>
__global__ __launch_bounds__(256, 2) void k_hgemm(const float* __restrict__ X,
                                                  float* __restrict__ Out)
{
    __shared__ __nv_bfloat16 As[2][128*40];
    __shared__ __nv_bfloat16 Bs[2][128*40];
    const int m0 = blockIdx.y * 128;
    const int o0 = blockIdx.x * 128;
    const int n  = m0 >> 12;
    const __nv_bfloat16* A = (MODE == 0) ? g_xh : g_AOh;
    const __nv_bfloat16* B = ((MODE == 0) ? g_Wqh : g_Woh) + (size_t)n * Dd * Dd;

    const int tid = threadIdx.x, lane = tid & 31, warp = tid >> 5;
    const int wm = warp & 3, wn = warp >> 2;

    auto copyAB = [&](int st, int k0) {
        #pragma unroll
        for (int i = 0; i < 2; i++) {
            int idx = tid + i*256;
            int r = idx >> 2, c = (idx & 3) * 8;
            cpa16(&As[st][r*40 + c], A + (size_t)(m0 + r)*Dd + k0 + c);
            cpa16(&Bs[st][r*40 + c], B + (size_t)(o0 + r)*Dd + k0 + c);
        }
    };

    copyAB(0, 0);
    CPCOMMIT();

    float acc[2][8][4];
    #pragma unroll
    for (int i = 0; i < 2; i++)
        #pragma unroll
        for (int j = 0; j < 8; j++)
            #pragma unroll
            for (int k = 0; k < 4; k++) acc[i][j][k] = 0.f;

    const int arow = wm*32 + (lane & 15);
    const int acol = ((lane >> 4) & 1) * 8;
    const int brow = wn*64 + (lane & 7) + ((lane >> 4) & 1) * 8;
    const int bcol = ((lane >> 3) & 1) * 8;

    for (int ks = 0; ks < 16; ks++) {
        int st = ks & 1;
        CPWAIT0();
        __syncthreads();
        if (ks < 15) { copyAB(st ^ 1, (ks+1)*32); CPCOMMIT(); }

        const __nv_bfloat16* Asb = As[st];
        const __nv_bfloat16* Bsb = Bs[st];

        uint32_t af[2][2][4];
        #pragma unroll
        for (int mf = 0; mf < 2; mf++)
            #pragma unroll
            for (int kf = 0; kf < 2; kf++)
                ldsm4(af[mf][kf], Asb + (arow + mf*16)*40 + kf*16 + acol);

        #pragma unroll
        for (int ng = 0; ng < 4; ng++) {
            uint32_t bfr[2][4];
            #pragma unroll
            for (int kf = 0; kf < 2; kf++)
                ldsm4(bfr[kf], Bsb + (brow + ng*16)*40 + kf*16 + bcol);
            #pragma unroll
            for (int s = 0; s < 2; s++) {
                int nf = ng*2 + s;
                #pragma unroll
                for (int mf = 0; mf < 2; mf++) {
                    mmabf(acc[mf][nf], af[mf][0], bfr[0][2*s], bfr[0][2*s+1]);
                    mmabf(acc[mf][nf], af[mf][1], bfr[1][2*s], bfr[1][2*s+1]);
                }
            }
        }
    }

    const int mrow = m0 + wm*32 + (lane >> 2);
    const int ocol = o0 + wn*64 + (lane & 3)*2;
    if (MODE == 0) {
        #pragma unroll
        for (int mf = 0; mf < 2; mf++) {
            int r0 = mrow + mf*16, r1 = r0 + 8;
            float rs0 = g_rs[r0], mr0 = g_mu[r0]*rs0;
            float rs1 = g_rs[r1], mr1 = g_mu[r1]*rs1;
            #pragma unroll
            for (int nf = 0; nf < 8; nf++) {
                int c = ocol + nf*8;
                float sq0 = g_Sq[n*Dd + c], sq1 = g_Sq[n*Dd + c + 1];
                float cq0 = g_Cq[n*Dd + c], cq1 = g_Cq[n*Dd + c + 1];
                float* d = acc[mf][nf];
                *(uint32_t*)(g_Qh + (size_t)r0*Dd + c) =
                    pk2(rs0*d[0] - mr0*sq0 + cq0, rs0*d[1] - mr0*sq1 + cq1);
                *(uint32_t*)(g_Qh + (size_t)r1*Dd + c) =
                    pk2(rs1*d[2] - mr1*sq0 + cq0, rs1*d[3] - mr1*sq1 + cq1);
            }
        }
    } else {
        float mfv = g_maskf[n];
        #pragma unroll
        for (int mf = 0; mf < 2; mf++) {
            int r0 = mrow + mf*16, r1 = r0 + 8;
            #pragma unroll
            for (int nf = 0; nf < 8; nf++) {
                int c = ocol + nf*8;
                float* d = acc[mf][nf];
                float2 x0 = *(const float2*)(X + (size_t)r0*Dd + c);
                float2 x1 = *(const float2*)(X + (size_t)r1*Dd + c);
                *(float2*)(Out + (size_t)r0*Dd + c) =
                    make_float2(x0.x + mfv*d[0], x0.y + mfv*d[1]);
                *(float2*)(Out + (size_t)r1*Dd + c) =
                    make_float2(x1.x + mfv*d[2], x1.y + mfv*d[3]);
            }
        }
    }
}

// ------- kv-compress: bf16x3 tensor cores, cp.async, + LN + mask + quant --------
__global__ __launch_bounds__(256) void k_kvmma()
{
    extern __shared__ __nv_bfloat16 kvs[];
    const int m0 = blockIdx.x * 128;
    const int n  = m0 >> 12;
    const int tid = threadIdx.x, lane = tid & 31, warp = tid >> 5;
    const int wm = warp & 3, wn = warp >> 2;

    const __nv_bfloat16* srcs[4] = {
        g_xh + (size_t)m0*Dd, g_xl + (size_t)m0*Dd,
        g_Mbh + (size_t)(n*128)*Dd, g_Mbl + (size_t)(n*128)*Dd };

    auto copyS = [&](int st, int k0) {
        __nv_bfloat16* base = kvs + (size_t)st*4*5120;
        #pragma unroll
        for (int op = 0; op < 4; op++) {
            #pragma unroll
            for (int i = 0; i < 2; i++) {
                int idx = tid + i*256;
                int r = idx >> 2, c = (idx & 3) * 8;
                cpa16(base + op*5120 + r*40 + c, srcs[op] + (size_t)r*Dd + k0 + c);
            }
        }
    };

    copyS(0, 0);
    CPCOMMIT();

    float acc[2][8][4];
    #pragma unroll
    for (int i = 0; i < 2; i++)
        #pragma unroll
        for (int j = 0; j < 8; j++)
            #pragma unroll
            for (int k = 0; k < 4; k++) acc[i][j][k] = 0.f;

    const int arow = wm*32 + (lane & 15);
    const int acol = ((lane >> 4) & 1) * 8;
    const int brow = wn*64 + (lane & 7) + ((lane >> 4) & 1) * 8;
    const int bcol = ((lane >> 3) & 1) * 8;

    for (int ks = 0; ks < 16; ks++) {
        int st = ks & 1;
        CPWAIT0();
        __syncthreads();
        if (ks < 15) { copyS(st ^ 1, (ks+1)*32); CPCOMMIT(); }

        const __nv_bfloat16* Ahs = kvs + (size_t)st*4*5120;
        const __nv_bfloat16* Als = Ahs + 5120;
        const __nv_bfloat16* Bhs = Ahs + 2*5120;
        const __nv_bfloat16* Bls = Ahs + 3*5120;

        uint32_t ah[2][2][4], al[2][2][4];
        #pragma unroll
        for (int mf = 0; mf < 2; mf++)
            #pragma unroll
            for (int kf = 0; kf < 2; kf++) {
                ldsm4(ah[mf][kf], Ahs + (arow + mf*16)*40 + kf*16 + acol);
                ldsm4(al[mf][kf], Als + (arow + mf*16)*40 + kf*16 + acol);
            }

        #pragma unroll
        for (int ng = 0; ng < 4; ng++) {
            uint32_t bh[2][4], bl[2][4];
            #pragma unroll
            for (int kf = 0; kf < 2; kf++) {
                ldsm4(bh[kf], Bhs + (brow + ng*16)*40 + kf*16 + bcol);
                ldsm4(bl[kf], Bls + (brow + ng*16)*40 + kf*16 + bcol);
            }
            #pragma unroll
            for (int s = 0; s < 2; s++) {
                int nf = ng*2 + s;
                #pragma unroll
                for (int mf = 0; mf < 2; mf++) {
                    mmabf(acc[mf][nf], ah[mf][0], bh[0][2*s], bh[0][2*s+1]);
                    mmabf(acc[mf][nf], ah[mf][1], bh[1][2*s], bh[1][2*s+1]);
                    mmabf(acc[mf][nf], ah[mf][0], bl[0][2*s], bl[0][2*s+1]);
                    mmabf(acc[mf][nf], ah[mf][1], bl[1][2*s], bl[1][2*s+1]);
                    mmabf(acc[mf][nf], al[mf][0], bh[0][2*s], bh[0][2*s+1]);
                    mmabf(acc[mf][nf], al[mf][1], bh[1][2*s], bh[1][2*s+1]);
                }
            }
        }
    }

    const float mfv = g_maskf[n];
    const int mrow = m0 + wm*32 + (lane >> 2);
    float smv[16], cmv[16];
    #pragma unroll
    for (int nf = 0; nf < 8; nf++) {
        int o = wn*64 + nf*8 + (lane & 3)*2;
        smv[2*nf]   = g_SM[n*128 + o];   smv[2*nf+1] = g_SM[n*128 + o + 1];
        cmv[2*nf]   = g_CM[n*128 + o];   cmv[2*nf+1] = g_CM[n*128 + o + 1];
    }
    float* dstb = (wn == 0) ? g_kq : g_vq;
    #pragma unroll
    for (int mf2 = 0; mf2 < 2; mf2++) {
        #pragma unroll
        for (int rr = 0; rr < 2; rr++) {
            int r = mrow + mf2*16 + rr*8;
            float rsv = g_rs[r], murs = g_mu[r]*rsv;
            float v[16]; float am = 0.f;
            #pragma unroll
            for (int nf = 0; nf < 8; nf++) {
                #pragma unroll
                for (int t = 0; t < 2; t++) {
                    float val = (rsv*acc[mf2][nf][2*rr+t] - murs*smv[2*nf+t] + cmv[2*nf+t]) * mfv;
                    v[2*nf+t] = val;
                    am = fmaxf(am, fabsf(val));
                }
            }
            am = fmaxf(am, __shfl_xor_sync(0xffffffffu, am, 1));
            am = fmaxf(am, __shfl_xor_sync(0xffffffffu, am, 2));
            am = fmaxf(am, 1e-8f);
            float scq = 127.f / am;
            float inv = am * (1.f / 127.f);
            #pragma unroll
            for (int nf = 0; nf < 8; nf++) {
                float q0 = rintf(v[2*nf]   * scq) * inv;
                float q1 = rintf(v[2*nf+1] * scq) * inv;
                *(float2*)(dstb + (size_t)r*64 + nf*8 + (lane & 3)*2) = make_float2(q0, q1);
            }
        }
    }
}

// ---------------- transpose decoders ----------------
__global__ void k_transdec(const float* __restrict__ kd, const float* __restrict__ vd)
{
    int idx = blockIdx.x * 256 + threadIdx.x;
    int d = idx >> 6, r = idx & 63;
    g_kdecT[r*Dd + d] = kd[idx];
    g_vdecT[r*Dd + d] = vd[idx];
}

// ---------------- average over n + decompress -> bf16 K/V ----------------
__global__ __launch_bounds__(256) void k_decomp()
{
    __shared__ float avg[16][64];
    int bt0 = blockIdx.x * 16;
    int isv = blockIdx.y;
    const float* src = isv ? g_vq : g_kq;
    const float* dec = isv ? g_vdecT : g_kdecT;
    __nv_bfloat16* dstb = isv ? g_Vh : g_Kh;
    float invna = g_invna;
    int tid = threadIdx.x;
    #pragma unroll
    for (int j = 0; j < 4; j++) {
        int p = j*256 + tid;
        int row = p >> 6, r = p & 63;
        float s = 0.f;
        #pragma unroll
        for (int n = 0; n < Nn; n++)
            s += src[((size_t)(n*BTc + bt0 + row))*64 + r];
        avg[row][r] = s * invna;
    }
    __syncthreads();
    int d0 = tid * 2;
    float2 acc[16];
    #pragma unroll
    for (int row = 0; row < 16; row++) { acc[row].x = 0.f; acc[row].y = 0.f; }
    for (int r = 0; r < 64; r++) {
        float2 kd = *(const float2*)(dec + r*Dd + d0);
        #pragma unroll
        for (int row = 0; row < 16; row++) {
            float a = avg[row][r];
            acc[row].x = fmaf(a, kd.x, acc[row].x);
            acc[row].y = fmaf(a, kd.y, acc[row].y);
        }
    }
    float sc = isv ? 1.f : INV_SQRT_HD;
    int h = d0 >> 7, hd = d0 & 127;
    #pragma unroll
    for (int row = 0; row < 16; row++) {
        int bt = bt0 + row;
        int b = bt >> 10, t = bt & 1023;
        __nv_bfloat16* dst = dstb + (((size_t)(b*Hh+h)*Tt + t)*HDc + hd);
        *(uint32_t*)dst = pk2(acc[row].x * sc, acc[row].y * sc);
    }
}

// ---- causal flash attention: bf16 mma, paired q-tiles, dual 4-warp groups ----
__global__ __launch_bounds__(256) void k_flash()
{
    extern __shared__ __nv_bfloat16 smb[];
    const int grp = threadIdx.x >> 7;              // 0 or 1
    const int tid = threadIdx.x & 127;
    const int lane = tid & 31, warp = tid >> 5;    // warp within group: 0..3
    __nv_bfloat16* Qs = smb + (size_t)grp * FLASH_SMEM_HALF;
    __nv_bfloat16* KV = Qs + 64*FSTR;
    const int nbh = blockIdx.y * 2 + grp;
    const int n = nbh >> 4, b = (nbh >> 2) & 3, h = nbh & 3;

    const size_t kvbase = (size_t)(b*Hh + h) * Tt * HDc;
    const int r0q = warp*16 + (lane >> 2);
    const int c0q = (lane & 3) * 2;

    auto copyKV = [&](int buf, int k0) {
        __nv_bfloat16* Kb = KV + (size_t)buf * 2*64*FSTR;
        __nv_bfloat16* Vb = Kb + 64*FSTR;
        #pragma unroll
        for (int i = 0; i < 8; i++) {
            int idx = tid + i*128;
            int r = idx >> 4, c = (idx & 15)*8;
            size_t src = kvbase + (size_t)(k0 + r)*HDc + c;
            cpa16(&Kb[r*FSTR + c], g_Kh + src);
            cpa16(&Vb[r*FSTR + c], g_Vh + src);
        }
    };

    #pragma unroll
    for (int phase = 0; phase < 2; phase++) {
        const int qt = phase ? (NT - 1 - (int)blockIdx.x) : (int)blockIdx.x;
        const int q0 = qt * 64;
        const size_t qbase = ((size_t)(n*Bb + b)*Tt + q0) * Dd + h*HDc;

        if (phase) __syncthreads();

        #pragma unroll
        for (int i = 0; i < 8; i++) {
            int idx = tid + i*128;
            int r = idx >> 4, c = (idx & 15) * 8;
            cpa16(&Qs[r*FSTR + c], g_Qh + qbase + (size_t)r*Dd + c);
        }
        CPCOMMIT();
        copyKV(0, 0);
        CPCOMMIT();
        CPWAIT0();
        __syncthreads();

        uint32_t qf[8][4];
        {
            const __nv_bfloat16* qp = Qs + (warp*16 + (lane & 15))*FSTR + (lane >> 4)*8;
            #pragma unroll
            for (int kf = 0; kf < 8; kf++) ldsm4(qf[kf], qp + kf*16);
        }

        float accO[16][4];
        #pragma unroll
        for (int i = 0; i < 16; i++)
            #pragma unroll
            for (int j = 0; j < 4; j++) accO[i][j] = 0.f;
        float mrow[2] = {-1e30f, -1e30f};
        float lrow[2] = {0.f, 0.f};

        for (int kt = 0; kt <= qt; kt++) {
            if (kt > 0) { CPWAIT0(); __syncthreads(); }
            if (kt < qt) { copyKV((kt+1) & 1, (kt+1)*64); CPCOMMIT(); }

            const __nv_bfloat16* Kb = KV + (size_t)(kt & 1) * 2*64*FSTR;
            const __nv_bfloat16* Vb = Kb + 64*FSTR;

            float sfr[8][4];
            #pragma unroll
            for (int i = 0; i < 8; i++)
                #pragma unroll
                for (int j = 0; j < 4; j++) sfr[i][j] = 0.f;

            {
                const __nv_bfloat16* kp = Kb + ((lane & 7) + ((lane >> 4) & 1)*8)*FSTR
                                             + ((lane >> 3) & 1)*8;
                #pragma unroll
                for (int ng = 0; ng < 4; ng++) {
                    #pragma unroll
                    for (int kf = 0; kf < 8; kf++) {
                        uint32_t bf[4];
                        ldsm4(bf, kp + ng*16*FSTR + kf*16);
                        mmabf(sfr[2*ng],   qf[kf], bf[0], bf[1]);
                        mmabf(sfr[2*ng+1], qf[kf], bf[2], bf[3]);
                    }
                }
            }

            if (kt == qt) {
                #pragma unroll
                for (int j = 0; j < 8; j++) {
                    int cj = 8*j + c0q;
                    #pragma unroll
                    for (int rr = 0; rr < 2; rr++) {
                        int ri = r0q + 8*rr;
                        if (cj     > ri) sfr[j][2*rr]   = -1e30f;
                        if (cj + 1 > ri) sfr[j][2*rr+1] = -1e30f;
                    }
                }
            }

            #pragma unroll
            for (int rr = 0; rr < 2; rr++) {
                float tm = -1e30f;
                #pragma unroll
                for (int j = 0; j < 8; j++)
                    tm = fmaxf(tm, fmaxf(sfr[j][2*rr], sfr[j][2*rr+1]));
                tm = fmaxf(tm, __shfl_xor_sync(0xffffffffu, tm, 1));
                tm = fmaxf(tm, __shfl_xor_sync(0xffffffffu, tm, 2));
                float mnew = fmaxf(mrow[rr], tm);
                float scl = exp2f((mrow[rr] - mnew) * L2E);
                float ps = 0.f;
                #pragma unroll
                for (int j = 0; j < 8; j++) {
                    float e0 = exp2f((sfr[j][2*rr]   - mnew) * L2E);
                    float e1 = exp2f((sfr[j][2*rr+1] - mnew) * L2E);
                    sfr[j][2*rr] = e0; sfr[j][2*rr+1] = e1;
                    ps += e0 + e1;
                }
                ps += __shfl_xor_sync(0xffffffffu, ps, 1);
                ps += __shfl_xor_sync(0xffffffffu, ps, 2);
                lrow[rr] = lrow[rr]*scl + ps;
                mrow[rr] = mnew;
                #pragma unroll
                for (int nf = 0; nf < 16; nf++) {
                    accO[nf][2*rr]   *= scl;
                    accO[nf][2*rr+1] *= scl;
                }
            }

            uint32_t pa[4][4];
            #pragma unroll
            for (int kg = 0; kg < 4; kg++) {
                pa[kg][0] = pk2(sfr[2*kg][0],   sfr[2*kg][1]);
                pa[kg][1] = pk2(sfr[2*kg][2],   sfr[2*kg][3]);
                pa[kg][2] = pk2(sfr[2*kg+1][0], sfr[2*kg+1][1]);
                pa[kg][3] = pk2(sfr[2*kg+1][2], sfr[2*kg+1][3]);
            }

            {
                const __nv_bfloat16* vp = Vb + (lane & 15)*FSTR + (lane >> 4)*8;
                #pragma unroll
                for (int dg = 0; dg < 8; dg++) {
                    #pragma unroll
                    for (int kg = 0; kg < 4; kg++) {
                        uint32_t vb[4];
                        ldsm4t(vb, vp + kg*16*FSTR + dg*16);
                        mmabf(accO[2*dg],   pa[kg], vb[0], vb[1]);
                        mmabf(accO[2*dg+1], pa[kg], vb[2], vb[3]);
                    }
                }
            }
        }

        #pragma unroll
        for (int rr = 0; rr < 2; rr++) {
            float inv = 1.f / lrow[rr];
            size_t row = (size_t)(n*Bb + b)*Tt + q0 + r0q + 8*rr;
            __nv_bfloat16* dst = g_AOh + row*Dd + h*HDc;
            #pragma unroll
            for (int nf = 0; nf < 16; nf++) {
                *(uint32_t*)(dst + 8*nf + c0q) =
                    pk2(accO[nf][2*rr]*inv, accO[nf][2*rr+1]*inv);
            }
        }
    }
}

// ---------------- launch (R6 schedule) ----------------
extern "C" void kernel_launch(void* const* d_in, const int* in_sizes, int n_in,
                              void* d_out, int out_size)
{
    (void)in_sizes; (void)n_in; (void)out_size;
    const float* x     = (const float*)d_in[0];
    const unsigned char* mask = (const unsigned char*)d_in[1];
    const float* lnkw  = (const float*)d_in[2];
    const float* lnkb  = (const float*)d_in[3];
    const float* lnqw  = (const float*)d_in[4];
    const float* lnqb  = (const float*)d_in[5];
    const float* wk    = (const float*)d_in[6];
    const float* wv    = (const float*)d_in[7];
    const float* wq    = (const float*)d_in[8];
    const float* wo    = (const float*)d_in[9];
    const float* kcomp = (const float*)d_in[10];
    const float* vcomp = (const float*)d_in[11];
    const float* kdec  = (const float*)d_in[12];
    const float* vdec  = (const float*)d_in[13];
    float* out = (float*)d_out;

    static cudaStream_t s1 = nullptr, s2 = nullptr;
    static cudaEvent_t eRoot, eLn, eTd, eH0;
    static bool init_done = false;
    if (!init_done) {
        cudaStreamCreateWithFlags(&s1, cudaStreamNonBlocking);
        cudaStreamCreateWithFlags(&s2, cudaStreamNonBlocking);
        cudaEventCreateWithFlags(&eRoot, cudaEventDisableTiming);
        cudaEventCreateWithFlags(&eLn,   cudaEventDisableTiming);
        cudaEventCreateWithFlags(&eTd,   cudaEventDisableTiming);
        cudaEventCreateWithFlags(&eH0,   cudaEventDisableTiming);
        cudaFuncSetAttribute(k_flash, cudaFuncAttributeMaxDynamicSharedMemorySize,
                             2*FLASH_SMEM_HALF*2);
        cudaFuncSetAttribute(k_kvmma, cudaFuncAttributeMaxDynamicSharedMemorySize,
                             2*4*5120*2);
        init_done = true;
    }

    // fork
    cudaEventRecord(eRoot, 0);
    cudaStreamWaitEvent(s1, eRoot, 0);
    cudaStreamWaitEvent(s2, eRoot, 0);

    // s1: LN stats + x bf16 split, decoder transpose, w_o convert
    k_lnstats<<<NROWS/8, 256, 0, s1>>>(x);
    cudaEventRecord(eLn, s1);
    k_transdec<<<128, 256, 0, s1>>>(kdec, vdec);
    k_convwo<<<Nn*Dd*Dd/4/256, 256, 0, s1>>>(wo);
    cudaEventRecord(eTd, s1);

    // s2: Q-branch fold + Q projection
    k_foldQ<<<Nn*Dd/8, 256, 0, s2>>>(lnqw, lnqb, wq);
    cudaStreamWaitEvent(s2, eLn, 0);
    k_hgemm<0><<<dim3(4, NROWS/128), 256, 0, s2>>>(nullptr, nullptr);
    cudaEventRecord(eH0, s2);

    // s0: KV chain
    k_mask<<<1, 32>>>(mask);
    k_compgemm<<<dim3(Nn, 2, 8), 256>>>(kcomp, vcomp, wk, wv);
    k_foldM<<<Nn*128/8, 256>>>(lnkw, lnkb);
    cudaStreamWaitEvent(0, eLn, 0);
    k_kvmma<<<NROWS/128, 256, 2*4*5120*2>>>();
    cudaStreamWaitEvent(0, eTd, 0);
    k_decomp<<<dim3(BTc/16, 2), 256>>>();
    cudaStreamWaitEvent(0, eH0, 0);
    k_flash<<<dim3(NT/2, Nn*Bb*Hh/2), 256, 2*FLASH_SMEM_HALF*2>>>();
    k_hgemm<1><<<dim3(4, NROWS/128), 256>>>(x, out);
}

// round 12
// speedup vs baseline: 1.1388x; 1.1388x over previous
#include <cuda_runtime.h>
#include <cuda_bf16.h>
#include <cstdint>
#include <cstddef>

#define Nn 8
#define Bb 4
#define Tt 1024
#define Dd 512
#define Hh 4
#define HDc 128
#define Rr 64
#define BTc (Bb*Tt)
#define NROWS (Nn*BTc)
#define EPSV 1e-5f
#define INV_SQRT_HD 0.08838834764831845f
#define L2E 1.4426950408889634f
#define FSTR 136
#define NT (Tt/64)

// ---------------- device scratch ----------------
__device__ float g_mu[NROWS];
__device__ float g_rs[NROWS];
__device__ float g_maskf[Nn];
__device__ float g_invna;
__device__ __nv_bfloat16 g_xh[(size_t)NROWS*Dd];
__device__ __nv_bfloat16 g_Wqh[Nn*Dd*Dd];
__device__ __nv_bfloat16 g_Woh[Nn*Dd*Dd];
__device__ float g_Sq[Nn*Dd];
__device__ float g_Cq[Nn*Dd];
__device__ float g_M[Nn*128*Dd];
__device__ __nv_bfloat16 g_Mbh[Nn*128*Dd];
__device__ __nv_bfloat16 g_Mbl[Nn*128*Dd];
__device__ float g_SM[Nn*128];
__device__ float g_CM[Nn*128];
__device__ float g_kq[(size_t)NROWS*Rr];
__device__ float g_vq[(size_t)NROWS*Rr];
__device__ float g_kdecT[Rr*Dd];
__device__ float g_vdecT[Rr*Dd];
__device__ __nv_bfloat16 g_Kh[(size_t)Bb*Hh*Tt*HDc];
__device__ __nv_bfloat16 g_Vh[(size_t)Bb*Hh*Tt*HDc];
__device__ __nv_bfloat16 g_Qh[(size_t)NROWS*Dd];
__device__ __nv_bfloat16 g_AOh[(size_t)NROWS*Dd];

// ---------------- helpers ----------------
__device__ __forceinline__ uint32_t pk2(float x, float y)
{
    __nv_bfloat162 h = __float22bfloat162_rn(make_float2(x, y));
    return *reinterpret_cast<uint32_t*>(&h);
}

__device__ __forceinline__ void ldsm4(uint32_t* r, const __nv_bfloat16* p)
{
    uint32_t a = (uint32_t)__cvta_generic_to_shared((void*)p);
    asm volatile("ldmatrix.sync.aligned.m8n8.x4.shared.b16 {%0,%1,%2,%3}, [%4];\n"
                 : "=r"(r[0]), "=r"(r[1]), "=r"(r[2]), "=r"(r[3]) : "r"(a));
}

__device__ __forceinline__ void ldsm4t(uint32_t* r, const __nv_bfloat16* p)
{
    uint32_t a = (uint32_t)__cvta_generic_to_shared((void*)p);
    asm volatile("ldmatrix.sync.aligned.m8n8.x4.trans.shared.b16 {%0,%1,%2,%3}, [%4];\n"
                 : "=r"(r[0]), "=r"(r[1]), "=r"(r[2]), "=r"(r[3]) : "r"(a));
}

__device__ __forceinline__ void mmabf(float* d, const uint32_t* a, uint32_t b0, uint32_t b1)
{
    asm volatile("mma.sync.aligned.m16n8k16.row.col.f32.bf16.bf16.f32 "
                 "{%0,%1,%2,%3},{%4,%5,%6,%7},{%8,%9},{%0,%1,%2,%3};\n"
                 : "+f"(d[0]), "+f"(d[1]), "+f"(d[2]), "+f"(d[3])
                 : "r"(a[0]), "r"(a[1]), "r"(a[2]), "r"(a[3]), "r"(b0), "r"(b1));
}

__device__ __forceinline__ void cpa16(const void* smem_dst, const void* gsrc)
{
    uint32_t ds = (uint32_t)__cvta_generic_to_shared((void*)smem_dst);
    asm volatile("cp.async.cg.shared.global [%0], [%1], 16;\n" :: "r"(ds), "l"(gsrc));
}
#define CPCOMMIT() asm volatile("cp.async.commit_group;\n" ::: "memory")
#define CPWAIT0()  asm volatile("cp.async.wait_group 0;\n" ::: "memory")

// ---------------- mask decode ----------------
__global__ void k_mask(const unsigned char* __restrict__ p)
{
    if (threadIdx.x == 0) {
        bool isF = (p[0]==0 && p[1]==0 && p[2]==0x80 && p[3]==0x3f);
        bool isI = (!isF && p[1]==0 && p[2]==0 && p[3]==0 && (p[4]!=0 || p[5]==0));
        float na = 0.f;
        for (int n = 0; n < Nn; n++) {
            bool bit;
            if (isF)      bit = (((const float*)p)[n] != 0.f);
            else if (isI) bit = (((const int*)p)[n]   != 0);
            else          bit = (p[n] != 0);
            g_maskf[n] = bit ? 1.f : 0.f;
            na += bit ? 1.f : 0.f;
        }
        g_invna = 1.f / fmaxf(na, 1.f);
    }
}

// ---------------- LN row stats + bf16 copy of x ----------------
__global__ __launch_bounds__(256) void k_lnstats(const float* __restrict__ x)
{
    int row  = blockIdx.x * 8 + (threadIdx.x >> 5);
    int lane = threadIdx.x & 31;
    const float4* xp = (const float4*)(x + (size_t)row * Dd);
    float s = 0.f, sq = 0.f;
    #pragma unroll
    for (int i = 0; i < 4; i++) {
        int j = lane + 32*i;
        float4 v = xp[j];
        s  += v.x + v.y + v.z + v.w;
        sq += v.x*v.x + v.y*v.y + v.z*v.z + v.w*v.w;
        uint2 uh = make_uint2(pk2(v.x, v.y), pk2(v.z, v.w));
        *(uint2*)(g_xh + (size_t)row*Dd + 4*j) = uh;
    }
    #pragma unroll
    for (int o = 16; o > 0; o >>= 1) {
        s  += __shfl_xor_sync(0xffffffffu, s,  o);
        sq += __shfl_xor_sync(0xffffffffu, sq, o);
    }
    if (lane == 0) {
        float mu  = s * (1.f / Dd);
        float var = sq * (1.f / Dd) - mu * mu;
        g_mu[row] = mu;
        g_rs[row] = rsqrtf(var + EPSV);
    }
}

// ---------------- w_o -> bf16 ----------------
__global__ __launch_bounds__(256) void k_convwo(const float* __restrict__ wo)
{
    int idx = blockIdx.x * 256 + threadIdx.x;
    float4 v = ((const float4*)wo)[idx];
    ((uint2*)g_Woh)[idx] = make_uint2(pk2(v.x, v.y), pk2(v.z, v.w));
}

// ---------------- M_raw[n] = comp @ w ----------------
__global__ __launch_bounds__(256) void k_compgemm(
    const float* __restrict__ kcomp, const float* __restrict__ vcomp,
    const float* __restrict__ wk,    const float* __restrict__ wv)
{
    __shared__ float As[32*68];
    __shared__ float Bs[32*68];
    const int n    = blockIdx.x;
    const int half = blockIdx.y;
    const int i0   = blockIdx.z * 64;
    const float* comp = (half == 0 ? kcomp : vcomp) + (size_t)n * Rr * Dd;
    const float* w    = (half == 0 ? wk    : wv   ) + (size_t)n * Dd * Dd;
    const int tid = threadIdx.x, ty = tid >> 4, tx = tid & 15;
    const int arA = tid & 63, acA = (tid >> 6) * 8;
    const int arB = tid & 31, acB = (tid >> 5) * 8;

    float acc[4][4] = {};
    for (int k0 = 0; k0 < Dd; k0 += 32) {
        float4 a0 = *(const float4*)(comp + (size_t)arA*Dd + k0 + acA);
        float4 a1 = *(const float4*)(comp + (size_t)arA*Dd + k0 + acA + 4);
        float4 b0 = *(const float4*)(w + (size_t)(k0+arB)*Dd + i0 + acB);
        float4 b1 = *(const float4*)(w + (size_t)(k0+arB)*Dd + i0 + acB + 4);
        __syncthreads();
        As[(acA+0)*68+arA]=a0.x; As[(acA+1)*68+arA]=a0.y; As[(acA+2)*68+arA]=a0.z; As[(acA+3)*68+arA]=a0.w;
        As[(acA+4)*68+arA]=a1.x; As[(acA+5)*68+arA]=a1.y; As[(acA+6)*68+arA]=a1.z; As[(acA+7)*68+arA]=a1.w;
        *(float4*)&Bs[arB*68 + acB]     = b0;
        *(float4*)&Bs[arB*68 + acB + 4] = b1;
        __syncthreads();
        #pragma unroll
        for (int kk = 0; kk < 32; kk++) {
            float4 a  = *(const float4*)&As[kk*68 + ty*4];
            float4 bb = *(const float4*)&Bs[kk*68 + tx*4];
            float av[4] = {a.x,a.y,a.z,a.w};
            float bv[4] = {bb.x,bb.y,bb.z,bb.w};
            #pragma unroll
            for (int i = 0; i < 4; i++)
                #pragma unroll
                for (int j = 0; j < 4; j++)
                    acc[i][j] = fmaf(av[i], bv[j], acc[i][j]);
        }
    }
    #pragma unroll
    for (int i = 0; i < 4; i++) {
        int row = n*128 + half*64 + ty*4 + i;
        float4 o = make_float4(acc[i][0], acc[i][1], acc[i][2], acc[i][3]);
        *(float4*)(g_M + (size_t)row*Dd + i0 + tx*4) = o;
    }
}

// ---------------- fold LN(kv) into M -> bf16 hi/lo; SM/CM ----------------
__global__ __launch_bounds__(256) void k_foldM(const float* __restrict__ lnw,
                                               const float* __restrict__ lnb)
{
    int row  = blockIdx.x * 8 + (threadIdx.x >> 5);
    int lane = threadIdx.x & 31;
    int n = row >> 7;
    const float* lw = lnw + n*Dd;
    const float* lb = lnb + n*Dd;
    const float* Mrow = g_M + (size_t)row * Dd;
    float sm = 0.f, cm = 0.f;
    for (int i = lane; i < Dd; i += 32) {
        float m = Mrow[i], w = lw[i], b = lb[i];
        float p = w * m;
        sm += p; cm += b * m;
        __nv_bfloat16 hb = __float2bfloat16(p);
        g_Mbh[(size_t)row*Dd + i] = hb;
        g_Mbl[(size_t)row*Dd + i] = __float2bfloat16(p - __bfloat162float(hb));
    }
    #pragma unroll
    for (int o = 16; o > 0; o >>= 1) {
        sm += __shfl_xor_sync(0xffffffffu, sm, o);
        cm += __shfl_xor_sync(0xffffffffu, cm, o);
    }
    if (lane == 0) { g_SM[row] = sm; g_CM[row] = cm; }
}

// ---------------- fold LN(q) into w_q -> bf16 ----------------
__global__ __launch_bounds__(256) void k_foldQ(const float* __restrict__ lnw,
                                               const float* __restrict__ lnb,
                                               const float* __restrict__ wq)
{
    int row  = blockIdx.x * 8 + (threadIdx.x >> 5);
    int lane = threadIdx.x & 31;
    int n = row >> 9;
    const float* lw = lnw + n*Dd;
    const float* lb = lnb + n*Dd;
    const float* wr = wq + (size_t)row * Dd;
    float sm = 0.f, cm = 0.f;
    for (int i = lane; i < Dd; i += 32) {
        float m = wr[i], w = lw[i], b = lb[i];
        float p = w * m;
        sm += p; cm += b * m;
        g_Wqh[(size_t)row*Dd + i] = __float2bfloat16(p);
    }
    #pragma unroll
    for (int o = 16; o > 0; o >>= 1) {
        sm += __shfl_xor_sync(0xffffffffu, sm, o);
        cm += __shfl_xor_sync(0xffffffffu, cm, o);
    }
    if (lane == 0) { g_Sq[row] = sm; g_Cq[row] = cm; }
}

// ------- bf16 GEMM 128x128xK512 with cp.async pipeline. MODE 0 = Q, 1 = O -------
template<int MODE>
__global__ __launch_bounds__(256, 2) void k_hgemm(const float* __restrict__ X,
                                                  float* __restrict__ Out)
{
    __shared__ __nv_bfloat16 As[2][128*40];
    __shared__ __nv_bfloat16 Bs[2][128*40];
    const int m0 = blockIdx.y * 128;
    const int o0 = blockIdx.x * 128;
    const int n  = m0 >> 12;
    const __nv_bfloat16* A = (MODE == 0) ? g_xh : g_AOh;
    const __nv_bfloat16* B = ((MODE == 0) ? g_Wqh : g_Woh) + (size_t)n * Dd * Dd;

    const int tid = threadIdx.x, lane = tid & 31, warp = tid >> 5;
    const int wm = warp & 3, wn = warp >> 2;

    auto copyAB = [&](int st, int k0) {
        #pragma unroll
        for (int i = 0; i < 2; i++) {
            int idx = tid + i*256;
            int r = idx >> 2, c = (idx & 3) * 8;
            cpa16(&As[st][r*40 + c], A + (size_t)(m0 + r)*Dd + k0 + c);
            cpa16(&Bs[st][r*40 + c], B + (size_t)(o0 + r)*Dd + k0 + c);
        }
    };

    copyAB(0, 0);
    CPCOMMIT();

    float acc[2][8][4];
    #pragma unroll
    for (int i = 0; i < 2; i++)
        #pragma unroll
        for (int j = 0; j < 8; j++)
            #pragma unroll
            for (int k = 0; k < 4; k++) acc[i][j][k] = 0.f;

    const int arow = wm*32 + (lane & 15);
    const int acol = ((lane >> 4) & 1) * 8;
    const int brow = wn*64 + (lane & 7) + ((lane >> 4) & 1) * 8;
    const int bcol = ((lane >> 3) & 1) * 8;

    for (int ks = 0; ks < 16; ks++) {
        int st = ks & 1;
        CPWAIT0();
        __syncthreads();
        if (ks < 15) { copyAB(st ^ 1, (ks+1)*32); CPCOMMIT(); }

        const __nv_bfloat16* Asb = As[st];
        const __nv_bfloat16* Bsb = Bs[st];

        uint32_t af[2][2][4];
        #pragma unroll
        for (int mf = 0; mf < 2; mf++)
            #pragma unroll
            for (int kf = 0; kf < 2; kf++)
                ldsm4(af[mf][kf], Asb + (arow + mf*16)*40 + kf*16 + acol);

        #pragma unroll
        for (int ng = 0; ng < 4; ng++) {
            uint32_t bfr[2][4];
            #pragma unroll
            for (int kf = 0; kf < 2; kf++)
                ldsm4(bfr[kf], Bsb + (brow + ng*16)*40 + kf*16 + bcol);
            #pragma unroll
            for (int s = 0; s < 2; s++) {
                int nf = ng*2 + s;
                #pragma unroll
                for (int mf = 0; mf < 2; mf++) {
                    mmabf(acc[mf][nf], af[mf][0], bfr[0][2*s], bfr[0][2*s+1]);
                    mmabf(acc[mf][nf], af[mf][1], bfr[1][2*s], bfr[1][2*s+1]);
                }
            }
        }
    }

    const int mrow = m0 + wm*32 + (lane >> 2);
    const int ocol = o0 + wn*64 + (lane & 3)*2;
    if (MODE == 0) {
        #pragma unroll
        for (int mf = 0; mf < 2; mf++) {
            int r0 = mrow + mf*16, r1 = r0 + 8;
            float rs0 = g_rs[r0], mr0 = g_mu[r0]*rs0;
            float rs1 = g_rs[r1], mr1 = g_mu[r1]*rs1;
            #pragma unroll
            for (int nf = 0; nf < 8; nf++) {
                int c = ocol + nf*8;
                float sq0 = g_Sq[n*Dd + c], sq1 = g_Sq[n*Dd + c + 1];
                float cq0 = g_Cq[n*Dd + c], cq1 = g_Cq[n*Dd + c + 1];
                float* d = acc[mf][nf];
                *(uint32_t*)(g_Qh + (size_t)r0*Dd + c) =
                    pk2(rs0*d[0] - mr0*sq0 + cq0, rs0*d[1] - mr0*sq1 + cq1);
                *(uint32_t*)(g_Qh + (size_t)r1*Dd + c) =
                    pk2(rs1*d[2] - mr1*sq0 + cq0, rs1*d[3] - mr1*sq1 + cq1);
            }
        }
    } else {
        float mfv = g_maskf[n];
        #pragma unroll
        for (int mf = 0; mf < 2; mf++) {
            int r0 = mrow + mf*16, r1 = r0 + 8;
            #pragma unroll
            for (int nf = 0; nf < 8; nf++) {
                int c = ocol + nf*8;
                float* d = acc[mf][nf];
                float2 x0 = *(const float2*)(X + (size_t)r0*Dd + c);
                float2 x1 = *(const float2*)(X + (size_t)r1*Dd + c);
                *(float2*)(Out + (size_t)r0*Dd + c) =
                    make_float2(x0.x + mfv*d[0], x0.y + mfv*d[1]);
                *(float2*)(Out + (size_t)r1*Dd + c) =
                    make_float2(x1.x + mfv*d[2], x1.y + mfv*d[3]);
            }
        }
    }
}

// ------- kv-compress: 2-term bf16 tensor cores (xh x (Mh+Ml)) + quant ----------
__global__ __launch_bounds__(256) void k_kvmma()
{
    extern __shared__ __nv_bfloat16 kvs[];   // 2 stages x 3 operands x 128*40
    const int m0 = blockIdx.x * 128;
    const int n  = m0 >> 12;
    const int tid = threadIdx.x, lane = tid & 31, warp = tid >> 5;
    const int wm = warp & 3, wn = warp >> 2;

    const __nv_bfloat16* srcs[3] = {
        g_xh + (size_t)m0*Dd,
        g_Mbh + (size_t)(n*128)*Dd, g_Mbl + (size_t)(n*128)*Dd };

    auto copyS = [&](int st, int k0) {
        __nv_bfloat16* base = kvs + (size_t)st*3*5120;
        #pragma unroll
        for (int op = 0; op < 3; op++) {
            #pragma unroll
            for (int i = 0; i < 2; i++) {
                int idx = tid + i*256;
                int r = idx >> 2, c = (idx & 3) * 8;
                cpa16(base + op*5120 + r*40 + c, srcs[op] + (size_t)r*Dd + k0 + c);
            }
        }
    };

    copyS(0, 0);
    CPCOMMIT();

    float acc[2][8][4];
    #pragma unroll
    for (int i = 0; i < 2; i++)
        #pragma unroll
        for (int j = 0; j < 8; j++)
            #pragma unroll
            for (int k = 0; k < 4; k++) acc[i][j][k] = 0.f;

    const int arow = wm*32 + (lane & 15);
    const int acol = ((lane >> 4) & 1) * 8;
    const int brow = wn*64 + (lane & 7) + ((lane >> 4) & 1) * 8;
    const int bcol = ((lane >> 3) & 1) * 8;

    for (int ks = 0; ks < 16; ks++) {
        int st = ks & 1;
        CPWAIT0();
        __syncthreads();
        if (ks < 15) { copyS(st ^ 1, (ks+1)*32); CPCOMMIT(); }

        const __nv_bfloat16* Ahs = kvs + (size_t)st*3*5120;
        const __nv_bfloat16* Bhs = Ahs + 5120;
        const __nv_bfloat16* Bls = Ahs + 2*5120;

        uint32_t ah[2][2][4];
        #pragma unroll
        for (int mf = 0; mf < 2; mf++)
            #pragma unroll
            for (int kf = 0; kf < 2; kf++)
                ldsm4(ah[mf][kf], Ahs + (arow + mf*16)*40 + kf*16 + acol);

        #pragma unroll
        for (int ng = 0; ng < 4; ng++) {
            uint32_t bh[2][4], bl[2][4];
            #pragma unroll
            for (int kf = 0; kf < 2; kf++) {
                ldsm4(bh[kf], Bhs + (brow + ng*16)*40 + kf*16 + bcol);
                ldsm4(bl[kf], Bls + (brow + ng*16)*40 + kf*16 + bcol);
            }
            #pragma unroll
            for (int s = 0; s < 2; s++) {
                int nf = ng*2 + s;
                #pragma unroll
                for (int mf = 0; mf < 2; mf++) {
                    mmabf(acc[mf][nf], ah[mf][0], bh[0][2*s], bh[0][2*s+1]);
                    mmabf(acc[mf][nf], ah[mf][1], bh[1][2*s], bh[1][2*s+1]);
                    mmabf(acc[mf][nf], ah[mf][0], bl[0][2*s], bl[0][2*s+1]);
                    mmabf(acc[mf][nf], ah[mf][1], bl[1][2*s], bl[1][2*s+1]);
                }
            }
        }
    }

    const float mfv = g_maskf[n];
    const int mrow = m0 + wm*32 + (lane >> 2);
    float smv[16], cmv[16];
    #pragma unroll
    for (int nf = 0; nf < 8; nf++) {
        int o = wn*64 + nf*8 + (lane & 3)*2;
        smv[2*nf]   = g_SM[n*128 + o];   smv[2*nf+1] = g_SM[n*128 + o + 1];
        cmv[2*nf]   = g_CM[n*128 + o];   cmv[2*nf+1] = g_CM[n*128 + o + 1];
    }
    float* dstb = (wn == 0) ? g_kq : g_vq;
    #pragma unroll
    for (int mf2 = 0; mf2 < 2; mf2++) {
        #pragma unroll
        for (int rr = 0; rr < 2; rr++) {
            int r = mrow + mf2*16 + rr*8;
            float rsv = g_rs[r], murs = g_mu[r]*rsv;
            float v[16]; float am = 0.f;
            #pragma unroll
            for (int nf = 0; nf < 8; nf++) {
                #pragma unroll
                for (int t = 0; t < 2; t++) {
                    float val = (rsv*acc[mf2][nf][2*rr+t] - murs*smv[2*nf+t] + cmv[2*nf+t]) * mfv;
                    v[2*nf+t] = val;
                    am = fmaxf(am, fabsf(val));
                }
            }
            am = fmaxf(am, __shfl_xor_sync(0xffffffffu, am, 1));
            am = fmaxf(am, __shfl_xor_sync(0xffffffffu, am, 2));
            am = fmaxf(am, 1e-8f);
            float scq = 127.f / am;
            float inv = am * (1.f / 127.f);
            #pragma unroll
            for (int nf = 0; nf < 8; nf++) {
                float q0 = rintf(v[2*nf]   * scq) * inv;
                float q1 = rintf(v[2*nf+1] * scq) * inv;
                *(float2*)(dstb + (size_t)r*64 + nf*8 + (lane & 3)*2) = make_float2(q0, q1);
            }
        }
    }
}

// ---------------- transpose decoders ----------------
__global__ void k_transdec(const float* __restrict__ kd, const float* __restrict__ vd)
{
    int idx = blockIdx.x * 256 + threadIdx.x;
    int d = idx >> 6, r = idx & 63;
    g_kdecT[r*Dd + d] = kd[idx];
    g_vdecT[r*Dd + d] = vd[idx];
}

// ---------------- average over n + decompress -> bf16 K/V ----------------
__global__ __launch_bounds__(256) void k_decomp()
{
    __shared__ float avg[16][64];
    int bt0 = blockIdx.x * 16;
    int isv = blockIdx.y;
    const float* src = isv ? g_vq : g_kq;
    const float* dec = isv ? g_vdecT : g_kdecT;
    __nv_bfloat16* dstb = isv ? g_Vh : g_Kh;
    float invna = g_invna;
    int tid = threadIdx.x;
    #pragma unroll
    for (int j = 0; j < 4; j++) {
        int p = j*256 + tid;
        int row = p >> 6, r = p & 63;
        float s = 0.f;
        #pragma unroll
        for (int n = 0; n < Nn; n++)
            s += src[((size_t)(n*BTc + bt0 + row))*64 + r];
        avg[row][r] = s * invna;
    }
    __syncthreads();
    int d0 = tid * 2;
    float2 acc[16];
    #pragma unroll
    for (int row = 0; row < 16; row++) { acc[row].x = 0.f; acc[row].y = 0.f; }
    for (int r = 0; r < 64; r++) {
        float2 kd = *(const float2*)(dec + r*Dd + d0);
        #pragma unroll
        for (int row = 0; row < 16; row++) {
            float a = avg[row][r];
            acc[row].x = fmaf(a, kd.x, acc[row].x);
            acc[row].y = fmaf(a, kd.y, acc[row].y);
        }
    }
    float sc = isv ? 1.f : INV_SQRT_HD;
    int h = d0 >> 7, hd = d0 & 127;
    #pragma unroll
    for (int row = 0; row < 16; row++) {
        int bt = bt0 + row;
        int b = bt >> 10, t = bt & 1023;
        __nv_bfloat16* dst = dstb + (((size_t)(b*Hh+h)*Tt + t)*HDc + hd);
        *(uint32_t*)dst = pk2(acc[row].x * sc, acc[row].y * sc);
    }
}

// -------- causal flash attention: bf16 mma, paired q-tiles (R6 version) ---------
__global__ __launch_bounds__(128) void k_flash()
{
    extern __shared__ __nv_bfloat16 smb[];
    __nv_bfloat16* Qs = smb;
    __nv_bfloat16* KV = Qs + 64*FSTR;
    const int nbh = blockIdx.y;
    const int n = nbh >> 4, b = (nbh >> 2) & 3, h = nbh & 3;
    const int tid = threadIdx.x, lane = tid & 31, warp = tid >> 5;

    const size_t kvbase = (size_t)(b*Hh + h) * Tt * HDc;
    const int r0q = warp*16 + (lane >> 2);
    const int c0q = (lane & 3) * 2;

    auto copyKV = [&](int buf, int k0) {
        __nv_bfloat16* Kb = KV + (size_t)buf * 2*64*FSTR;
        __nv_bfloat16* Vb = Kb + 64*FSTR;
        #pragma unroll
        for (int i = 0; i < 8; i++) {
            int idx = tid + i*128;
            int r = idx >> 4, c = (idx & 15)*8;
            size_t src = kvbase + (size_t)(k0 + r)*HDc + c;
            cpa16(&Kb[r*FSTR + c], g_Kh + src);
            cpa16(&Vb[r*FSTR + c], g_Vh + src);
        }
    };

    #pragma unroll
    for (int phase = 0; phase < 2; phase++) {
        const int qt = phase ? (NT - 1 - (int)blockIdx.x) : (int)blockIdx.x;
        const int q0 = qt * 64;
        const size_t qbase = ((size_t)(n*Bb + b)*Tt + q0) * Dd + h*HDc;

        if (phase) __syncthreads();

        #pragma unroll
        for (int i = 0; i < 8; i++) {
            int idx = tid + i*128;
            int r = idx >> 4, c = (idx & 15) * 8;
            cpa16(&Qs[r*FSTR + c], g_Qh + qbase + (size_t)r*Dd + c);
        }
        CPCOMMIT();
        copyKV(0, 0);
        CPCOMMIT();
        CPWAIT0();
        __syncthreads();

        uint32_t qf[8][4];
        {
            const __nv_bfloat16* qp = Qs + (warp*16 + (lane & 15))*FSTR + (lane >> 4)*8;
            #pragma unroll
            for (int kf = 0; kf < 8; kf++) ldsm4(qf[kf], qp + kf*16);
        }

        float accO[16][4];
        #pragma unroll
        for (int i = 0; i < 16; i++)
            #pragma unroll
            for (int j = 0; j < 4; j++) accO[i][j] = 0.f;
        float mrow[2] = {-1e30f, -1e30f};
        float lrow[2] = {0.f, 0.f};

        for (int kt = 0; kt <= qt; kt++) {
            if (kt > 0) { CPWAIT0(); __syncthreads(); }
            if (kt < qt) { copyKV((kt+1) & 1, (kt+1)*64); CPCOMMIT(); }

            const __nv_bfloat16* Kb = KV + (size_t)(kt & 1) * 2*64*FSTR;
            const __nv_bfloat16* Vb = Kb + 64*FSTR;

            float sfr[8][4];
            #pragma unroll
            for (int i = 0; i < 8; i++)
                #pragma unroll
                for (int j = 0; j < 4; j++) sfr[i][j] = 0.f;

            {
                const __nv_bfloat16* kp = Kb + ((lane & 7) + ((lane >> 4) & 1)*8)*FSTR
                                             + ((lane >> 3) & 1)*8;
                #pragma unroll
                for (int ng = 0; ng < 4; ng++) {
                    #pragma unroll
                    for (int kf = 0; kf < 8; kf++) {
                        uint32_t bf[4];
                        ldsm4(bf, kp + ng*16*FSTR + kf*16);
                        mmabf(sfr[2*ng],   qf[kf], bf[0], bf[1]);
                        mmabf(sfr[2*ng+1], qf[kf], bf[2], bf[3]);
                    }
                }
            }

            if (kt == qt) {
                #pragma unroll
                for (int j = 0; j < 8; j++) {
                    int cj = 8*j + c0q;
                    #pragma unroll
                    for (int rr = 0; rr < 2; rr++) {
                        int ri = r0q + 8*rr;
                        if (cj     > ri) sfr[j][2*rr]   = -1e30f;
                        if (cj + 1 > ri) sfr[j][2*rr+1] = -1e30f;
                    }
                }
            }

            #pragma unroll
            for (int rr = 0; rr < 2; rr++) {
                float tm = -1e30f;
                #pragma unroll
                for (int j = 0; j < 8; j++)
                    tm = fmaxf(tm, fmaxf(sfr[j][2*rr], sfr[j][2*rr+1]));
                tm = fmaxf(tm, __shfl_xor_sync(0xffffffffu, tm, 1));
                tm = fmaxf(tm, __shfl_xor_sync(0xffffffffu, tm, 2));
                float mnew = fmaxf(mrow[rr], tm);
                float scl = exp2f((mrow[rr] - mnew) * L2E);
                float ps = 0.f;
                #pragma unroll
                for (int j = 0; j < 8; j++) {
                    float e0 = exp2f((sfr[j][2*rr]   - mnew) * L2E);
                    float e1 = exp2f((sfr[j][2*rr+1] - mnew) * L2E);
                    sfr[j][2*rr] = e0; sfr[j][2*rr+1] = e1;
                    ps += e0 + e1;
                }
                ps += __shfl_xor_sync(0xffffffffu, ps, 1);
                ps += __shfl_xor_sync(0xffffffffu, ps, 2);
                lrow[rr] = lrow[rr]*scl + ps;
                mrow[rr] = mnew;
                #pragma unroll
                for (int nf = 0; nf < 16; nf++) {
                    accO[nf][2*rr]   *= scl;
                    accO[nf][2*rr+1] *= scl;
                }
            }

            uint32_t pa[4][4];
            #pragma unroll
            for (int kg = 0; kg < 4; kg++) {
                pa[kg][0] = pk2(sfr[2*kg][0],   sfr[2*kg][1]);
                pa[kg][1] = pk2(sfr[2*kg][2],   sfr[2*kg][3]);
                pa[kg][2] = pk2(sfr[2*kg+1][0], sfr[2*kg+1][1]);
                pa[kg][3] = pk2(sfr[2*kg+1][2], sfr[2*kg+1][3]);
            }

            {
                const __nv_bfloat16* vp = Vb + (lane & 15)*FSTR + (lane >> 4)*8;
                #pragma unroll
                for (int dg = 0; dg < 8; dg++) {
                    #pragma unroll
                    for (int kg = 0; kg < 4; kg++) {
                        uint32_t vb[4];
                        ldsm4t(vb, vp + kg*16*FSTR + dg*16);
                        mmabf(accO[2*dg],   pa[kg], vb[0], vb[1]);
                        mmabf(accO[2*dg+1], pa[kg], vb[2], vb[3]);
                    }
                }
            }
        }

        #pragma unroll
        for (int rr = 0; rr < 2; rr++) {
            float inv = 1.f / lrow[rr];
            size_t row = (size_t)(n*Bb + b)*Tt + q0 + r0q + 8*rr;
            __nv_bfloat16* dst = g_AOh + row*Dd + h*HDc;
            #pragma unroll
            for (int nf = 0; nf < 16; nf++) {
                *(uint32_t*)(dst + 8*nf + c0q) =
                    pk2(accO[nf][2*rr]*inv, accO[nf][2*rr+1]*inv);
            }
        }
    }
}

// ---------------- launch (R6 schedule) ----------------
extern "C" void kernel_launch(void* const* d_in, const int* in_sizes, int n_in,
                              void* d_out, int out_size)
{
    (void)in_sizes; (void)n_in; (void)out_size;
    const float* x     = (const float*)d_in[0];
    const unsigned char* mask = (const unsigned char*)d_in[1];
    const float* lnkw  = (const float*)d_in[2];
    const float* lnkb  = (const float*)d_in[3];
    const float* lnqw  = (const float*)d_in[4];
    const float* lnqb  = (const float*)d_in[5];
    const float* wk    = (const float*)d_in[6];
    const float* wv    = (const float*)d_in[7];
    const float* wq    = (const float*)d_in[8];
    const float* wo    = (const float*)d_in[9];
    const float* kcomp = (const float*)d_in[10];
    const float* vcomp = (const float*)d_in[11];
    const float* kdec  = (const float*)d_in[12];
    const float* vdec  = (const float*)d_in[13];
    float* out = (float*)d_out;

    static cudaStream_t s1 = nullptr, s2 = nullptr;
    static cudaEvent_t eRoot, eLn, eTd, eH0;
    static bool init_done = false;
    if (!init_done) {
        cudaStreamCreateWithFlags(&s1, cudaStreamNonBlocking);
        cudaStreamCreateWithFlags(&s2, cudaStreamNonBlocking);
        cudaEventCreateWithFlags(&eRoot, cudaEventDisableTiming);
        cudaEventCreateWithFlags(&eLn,   cudaEventDisableTiming);
        cudaEventCreateWithFlags(&eTd,   cudaEventDisableTiming);
        cudaEventCreateWithFlags(&eH0,   cudaEventDisableTiming);
        cudaFuncSetAttribute(k_flash, cudaFuncAttributeMaxDynamicSharedMemorySize,
                             5*64*FSTR*2);
        cudaFuncSetAttribute(k_kvmma, cudaFuncAttributeMaxDynamicSharedMemorySize,
                             2*3*5120*2);
        init_done = true;
    }

    // fork
    cudaEventRecord(eRoot, 0);
    cudaStreamWaitEvent(s1, eRoot, 0);
    cudaStreamWaitEvent(s2, eRoot, 0);

    // s1: LN stats + x bf16, decoder transpose, w_o convert
    k_lnstats<<<NROWS/8, 256, 0, s1>>>(x);
    cudaEventRecord(eLn, s1);
    k_transdec<<<128, 256, 0, s1>>>(kdec, vdec);
    k_convwo<<<Nn*Dd*Dd/4/256, 256, 0, s1>>>(wo);
    cudaEventRecord(eTd, s1);

    // s2: Q-branch fold + Q projection
    k_foldQ<<<Nn*Dd/8, 256, 0, s2>>>(lnqw, lnqb, wq);
    cudaStreamWaitEvent(s2, eLn, 0);
    k_hgemm<0><<<dim3(4, NROWS/128), 256, 0, s2>>>(nullptr, nullptr);
    cudaEventRecord(eH0, s2);

    // s0: KV chain
    k_mask<<<1, 32>>>(mask);
    k_compgemm<<<dim3(Nn, 2, 8), 256>>>(kcomp, vcomp, wk, wv);
    k_foldM<<<Nn*128/8, 256>>>(lnkw, lnkb);
    cudaStreamWaitEvent(0, eLn, 0);
    k_kvmma<<<NROWS/128, 256, 2*3*5120*2>>>();
    cudaStreamWaitEvent(0, eTd, 0);
    k_decomp<<<dim3(BTc/16, 2), 256>>>();
    cudaStreamWaitEvent(0, eH0, 0);
    k_flash<<<dim3(NT/2, Nn*Bb*Hh), 128, 5*64*FSTR*2>>>();
    k_hgemm<1><<<dim3(4, NROWS/128), 256>>>(x, out);
}

// round 13
// speedup vs baseline: 1.1796x; 1.0358x over previous
#include <cuda_runtime.h>
#include <cuda_bf16.h>
#include <cstdint>
#include <cstddef>

#define Nn 8
#define Bb 4
#define Tt 1024
#define Dd 512
#define Hh 4
#define HDc 128
#define Rr 64
#define BTc (Bb*Tt)
#define NROWS (Nn*BTc)
#define EPSV 1e-5f
#define INV_SQRT_HD 0.08838834764831845f
#define L2E 1.4426950408889634f
#define FSTR 136
#define NT (Tt/64)

// ---------------- device scratch ----------------
__device__ float g_mu[NROWS];
__device__ float g_rs[NROWS];
__device__ float g_maskf[Nn];
__device__ float g_invna;
__device__ __nv_bfloat16 g_xh[(size_t)NROWS*Dd];
__device__ __nv_bfloat16 g_Wqh[Nn*Dd*Dd];
__device__ __nv_bfloat16 g_Woh[Nn*Dd*Dd];
__device__ float g_Sq[Nn*Dd];
__device__ float g_Cq[Nn*Dd];
__device__ float g_M[Nn*128*Dd];
__device__ __nv_bfloat16 g_Mbh[Nn*128*Dd];
__device__ float g_SM[Nn*128];
__device__ float g_CM[Nn*128];
__device__ float g_kq[(size_t)NROWS*Rr];
__device__ float g_vq[(size_t)NROWS*Rr];
__device__ float g_kdecT[Rr*Dd];
__device__ float g_vdecT[Rr*Dd];
__device__ __nv_bfloat16 g_Kh[(size_t)Bb*Hh*Tt*HDc];
__device__ __nv_bfloat16 g_Vh[(size_t)Bb*Hh*Tt*HDc];
__device__ __nv_bfloat16 g_Qh[(size_t)NROWS*Dd];
__device__ __nv_bfloat16 g_AOh[(size_t)NROWS*Dd];

// ---------------- helpers ----------------
__device__ __forceinline__ uint32_t pk2(float x, float y)
{
    __nv_bfloat162 h = __float22bfloat162_rn(make_float2(x, y));
    return *reinterpret_cast<uint32_t*>(&h);
}

__device__ __forceinline__ void ldsm4(uint32_t* r, const __nv_bfloat16* p)
{
    uint32_t a = (uint32_t)__cvta_generic_to_shared((void*)p);
    asm volatile("ldmatrix.sync.aligned.m8n8.x4.shared.b16 {%0,%1,%2,%3}, [%4];\n"
                 : "=r"(r[0]), "=r"(r[1]), "=r"(r[2]), "=r"(r[3]) : "r"(a));
}

__device__ __forceinline__ void ldsm4t(uint32_t* r, const __nv_bfloat16* p)
{
    uint32_t a = (uint32_t)__cvta_generic_to_shared((void*)p);
    asm volatile("ldmatrix.sync.aligned.m8n8.x4.trans.shared.b16 {%0,%1,%2,%3}, [%4];\n"
                 : "=r"(r[0]), "=r"(r[1]), "=r"(r[2]), "=r"(r[3]) : "r"(a));
}

__device__ __forceinline__ void mmabf(float* d, const uint32_t* a, uint32_t b0, uint32_t b1)
{
    asm volatile("mma.sync.aligned.m16n8k16.row.col.f32.bf16.bf16.f32 "
                 "{%0,%1,%2,%3},{%4,%5,%6,%7},{%8,%9},{%0,%1,%2,%3};\n"
                 : "+f"(d[0]), "+f"(d[1]), "+f"(d[2]), "+f"(d[3])
                 : "r"(a[0]), "r"(a[1]), "r"(a[2]), "r"(a[3]), "r"(b0), "r"(b1));
}

__device__ __forceinline__ void cpa16(const void* smem_dst, const void* gsrc)
{
    uint32_t ds = (uint32_t)__cvta_generic_to_shared((void*)smem_dst);
    asm volatile("cp.async.cg.shared.global [%0], [%1], 16;\n" :: "r"(ds), "l"(gsrc));
}
#define CPCOMMIT() asm volatile("cp.async.commit_group;\n" ::: "memory")
#define CPWAIT0()  asm volatile("cp.async.wait_group 0;\n" ::: "memory")

// ---------------- mask decode ----------------
__global__ void k_mask(const unsigned char* __restrict__ p)
{
    if (threadIdx.x == 0) {
        bool isF = (p[0]==0 && p[1]==0 && p[2]==0x80 && p[3]==0x3f);
        bool isI = (!isF && p[1]==0 && p[2]==0 && p[3]==0 && (p[4]!=0 || p[5]==0));
        float na = 0.f;
        for (int n = 0; n < Nn; n++) {
            bool bit;
            if (isF)      bit = (((const float*)p)[n] != 0.f);
            else if (isI) bit = (((const int*)p)[n]   != 0);
            else          bit = (p[n] != 0);
            g_maskf[n] = bit ? 1.f : 0.f;
            na += bit ? 1.f : 0.f;
        }
        g_invna = 1.f / fmaxf(na, 1.f);
    }
}

// ---------------- LN row stats + bf16 copy of x ----------------
__global__ __launch_bounds__(256) void k_lnstats(const float* __restrict__ x)
{
    int row  = blockIdx.x * 8 + (threadIdx.x >> 5);
    int lane = threadIdx.x & 31;
    const float4* xp = (const float4*)(x + (size_t)row * Dd);
    float s = 0.f, sq = 0.f;
    #pragma unroll
    for (int i = 0; i < 4; i++) {
        int j = lane + 32*i;
        float4 v = xp[j];
        s  += v.x + v.y + v.z + v.w;
        sq += v.x*v.x + v.y*v.y + v.z*v.z + v.w*v.w;
        uint2 uh = make_uint2(pk2(v.x, v.y), pk2(v.z, v.w));
        *(uint2*)(g_xh + (size_t)row*Dd + 4*j) = uh;
    }
    #pragma unroll
    for (int o = 16; o > 0; o >>= 1) {
        s  += __shfl_xor_sync(0xffffffffu, s,  o);
        sq += __shfl_xor_sync(0xffffffffu, sq, o);
    }
    if (lane == 0) {
        float mu  = s * (1.f / Dd);
        float var = sq * (1.f / Dd) - mu * mu;
        g_mu[row] = mu;
        g_rs[row] = rsqrtf(var + EPSV);
    }
}

// ---------------- w_o -> bf16 ----------------
__global__ __launch_bounds__(256) void k_convwo(const float* __restrict__ wo)
{
    int idx = blockIdx.x * 256 + threadIdx.x;
    float4 v = ((const float4*)wo)[idx];
    ((uint2*)g_Woh)[idx] = make_uint2(pk2(v.x, v.y), pk2(v.z, v.w));
}

// ---------------- M_raw[n] = comp @ w ----------------
__global__ __launch_bounds__(256) void k_compgemm(
    const float* __restrict__ kcomp, const float* __restrict__ vcomp,
    const float* __restrict__ wk,    const float* __restrict__ wv)
{
    __shared__ float As[32*68];
    __shared__ float Bs[32*68];
    const int n    = blockIdx.x;
    const int half = blockIdx.y;
    const int i0   = blockIdx.z * 64;
    const float* comp = (half == 0 ? kcomp : vcomp) + (size_t)n * Rr * Dd;
    const float* w    = (half == 0 ? wk    : wv   ) + (size_t)n * Dd * Dd;
    const int tid = threadIdx.x, ty = tid >> 4, tx = tid & 15;
    const int arA = tid & 63, acA = (tid >> 6) * 8;
    const int arB = tid & 31, acB = (tid >> 5) * 8;

    float acc[4][4] = {};
    for (int k0 = 0; k0 < Dd; k0 += 32) {
        float4 a0 = *(const float4*)(comp + (size_t)arA*Dd + k0 + acA);
        float4 a1 = *(const float4*)(comp + (size_t)arA*Dd + k0 + acA + 4);
        float4 b0 = *(const float4*)(w + (size_t)(k0+arB)*Dd + i0 + acB);
        float4 b1 = *(const float4*)(w + (size_t)(k0+arB)*Dd + i0 + acB + 4);
        __syncthreads();
        As[(acA+0)*68+arA]=a0.x; As[(acA+1)*68+arA]=a0.y; As[(acA+2)*68+arA]=a0.z; As[(acA+3)*68+arA]=a0.w;
        As[(acA+4)*68+arA]=a1.x; As[(acA+5)*68+arA]=a1.y; As[(acA+6)*68+arA]=a1.z; As[(acA+7)*68+arA]=a1.w;
        *(float4*)&Bs[arB*68 + acB]     = b0;
        *(float4*)&Bs[arB*68 + acB + 4] = b1;
        __syncthreads();
        #pragma unroll
        for (int kk = 0; kk < 32; kk++) {
            float4 a  = *(const float4*)&As[kk*68 + ty*4];
            float4 bb = *(const float4*)&Bs[kk*68 + tx*4];
            float av[4] = {a.x,a.y,a.z,a.w};
            float bv[4] = {bb.x,bb.y,bb.z,bb.w};
            #pragma unroll
            for (int i = 0; i < 4; i++)
                #pragma unroll
                for (int j = 0; j < 4; j++)
                    acc[i][j] = fmaf(av[i], bv[j], acc[i][j]);
        }
    }
    #pragma unroll
    for (int i = 0; i < 4; i++) {
        int row = n*128 + half*64 + ty*4 + i;
        float4 o = make_float4(acc[i][0], acc[i][1], acc[i][2], acc[i][3]);
        *(float4*)(g_M + (size_t)row*Dd + i0 + tx*4) = o;
    }
}

// ---------------- fold LN(kv) into M -> bf16; SM/CM ----------------
__global__ __launch_bounds__(256) void k_foldM(const float* __restrict__ lnw,
                                               const float* __restrict__ lnb)
{
    int row  = blockIdx.x * 8 + (threadIdx.x >> 5);
    int lane = threadIdx.x & 31;
    int n = row >> 7;
    const float* lw = lnw + n*Dd;
    const float* lb = lnb + n*Dd;
    const float* Mrow = g_M + (size_t)row * Dd;
    float sm = 0.f, cm = 0.f;
    for (int i = lane; i < Dd; i += 32) {
        float m = Mrow[i], w = lw[i], b = lb[i];
        float p = w * m;
        sm += p; cm += b * m;
        g_Mbh[(size_t)row*Dd + i] = __float2bfloat16(p);
    }
    #pragma unroll
    for (int o = 16; o > 0; o >>= 1) {
        sm += __shfl_xor_sync(0xffffffffu, sm, o);
        cm += __shfl_xor_sync(0xffffffffu, cm, o);
    }
    if (lane == 0) { g_SM[row] = sm; g_CM[row] = cm; }
}

// ---------------- fold LN(q) into w_q -> bf16 ----------------
__global__ __launch_bounds__(256) void k_foldQ(const float* __restrict__ lnw,
                                               const float* __restrict__ lnb,
                                               const float* __restrict__ wq)
{
    int row  = blockIdx.x * 8 + (threadIdx.x >> 5);
    int lane = threadIdx.x & 31;
    int n = row >> 9;
    const float* lw = lnw + n*Dd;
    const float* lb = lnb + n*Dd;
    const float* wr = wq + (size_t)row * Dd;
    float sm = 0.f, cm = 0.f;
    for (int i = lane; i < Dd; i += 32) {
        float m = wr[i], w = lw[i], b = lb[i];
        float p = w * m;
        sm += p; cm += b * m;
        g_Wqh[(size_t)row*Dd + i] = __float2bfloat16(p);
    }
    #pragma unroll
    for (int o = 16; o > 0; o >>= 1) {
        sm += __shfl_xor_sync(0xffffffffu, sm, o);
        cm += __shfl_xor_sync(0xffffffffu, cm, o);
    }
    if (lane == 0) { g_Sq[row] = sm; g_Cq[row] = cm; }
}

// ------- bf16 GEMM 128x128xK512 with cp.async pipeline. MODE 0 = Q, 1 = O -------
template<int MODE>
__global__ __launch_bounds__(256, 2) void k_hgemm(const float* __restrict__ X,
                                                  float* __restrict__ Out)
{
    __shared__ __nv_bfloat16 As[2][128*40];
    __shared__ __nv_bfloat16 Bs[2][128*40];
    const int m0 = blockIdx.y * 128;
    const int o0 = blockIdx.x * 128;
    const int n  = m0 >> 12;
    const __nv_bfloat16* A = (MODE == 0) ? g_xh : g_AOh;
    const __nv_bfloat16* B = ((MODE == 0) ? g_Wqh : g_Woh) + (size_t)n * Dd * Dd;

    const int tid = threadIdx.x, lane = tid & 31, warp = tid >> 5;
    const int wm = warp & 3, wn = warp >> 2;

    auto copyAB = [&](int st, int k0) {
        #pragma unroll
        for (int i = 0; i < 2; i++) {
            int idx = tid + i*256;
            int r = idx >> 2, c = (idx & 3) * 8;
            cpa16(&As[st][r*40 + c], A + (size_t)(m0 + r)*Dd + k0 + c);
            cpa16(&Bs[st][r*40 + c], B + (size_t)(o0 + r)*Dd + k0 + c);
        }
    };

    copyAB(0, 0);
    CPCOMMIT();

    float acc[2][8][4];
    #pragma unroll
    for (int i = 0; i < 2; i++)
        #pragma unroll
        for (int j = 0; j < 8; j++)
            #pragma unroll
            for (int k = 0; k < 4; k++) acc[i][j][k] = 0.f;

    const int arow = wm*32 + (lane & 15);
    const int acol = ((lane >> 4) & 1) * 8;
    const int brow = wn*64 + (lane & 7) + ((lane >> 4) & 1) * 8;
    const int bcol = ((lane >> 3) & 1) * 8;

    for (int ks = 0; ks < 16; ks++) {
        int st = ks & 1;
        CPWAIT0();
        __syncthreads();
        if (ks < 15) { copyAB(st ^ 1, (ks+1)*32); CPCOMMIT(); }

        const __nv_bfloat16* Asb = As[st];
        const __nv_bfloat16* Bsb = Bs[st];

        uint32_t af[2][2][4];
        #pragma unroll
        for (int mf = 0; mf < 2; mf++)
            #pragma unroll
            for (int kf = 0; kf < 2; kf++)
                ldsm4(af[mf][kf], Asb + (arow + mf*16)*40 + kf*16 + acol);

        #pragma unroll
        for (int ng = 0; ng < 4; ng++) {
            uint32_t bfr[2][4];
            #pragma unroll
            for (int kf = 0; kf < 2; kf++)
                ldsm4(bfr[kf], Bsb + (brow + ng*16)*40 + kf*16 + bcol);
            #pragma unroll
            for (int s = 0; s < 2; s++) {
                int nf = ng*2 + s;
                #pragma unroll
                for (int mf = 0; mf < 2; mf++) {
                    mmabf(acc[mf][nf], af[mf][0], bfr[0][2*s], bfr[0][2*s+1]);
                    mmabf(acc[mf][nf], af[mf][1], bfr[1][2*s], bfr[1][2*s+1]);
                }
            }
        }
    }

    const int mrow = m0 + wm*32 + (lane >> 2);
    const int ocol = o0 + wn*64 + (lane & 3)*2;
    if (MODE == 0) {
        #pragma unroll
        for (int mf = 0; mf < 2; mf++) {
            int r0 = mrow + mf*16, r1 = r0 + 8;
            float rs0 = g_rs[r0], mr0 = g_mu[r0]*rs0;
            float rs1 = g_rs[r1], mr1 = g_mu[r1]*rs1;
            #pragma unroll
            for (int nf = 0; nf < 8; nf++) {
                int c = ocol + nf*8;
                float sq0 = g_Sq[n*Dd + c], sq1 = g_Sq[n*Dd + c + 1];
                float cq0 = g_Cq[n*Dd + c], cq1 = g_Cq[n*Dd + c + 1];
                float* d = acc[mf][nf];
                *(uint32_t*)(g_Qh + (size_t)r0*Dd + c) =
                    pk2(rs0*d[0] - mr0*sq0 + cq0, rs0*d[1] - mr0*sq1 + cq1);
                *(uint32_t*)(g_Qh + (size_t)r1*Dd + c) =
                    pk2(rs1*d[2] - mr1*sq0 + cq0, rs1*d[3] - mr1*sq1 + cq1);
            }
        }
    } else {
        float mfv = g_maskf[n];
        #pragma unroll
        for (int mf = 0; mf < 2; mf++) {
            int r0 = mrow + mf*16, r1 = r0 + 8;
            #pragma unroll
            for (int nf = 0; nf < 8; nf++) {
                int c = ocol + nf*8;
                float* d = acc[mf][nf];
                float2 x0 = *(const float2*)(X + (size_t)r0*Dd + c);
                float2 x1 = *(const float2*)(X + (size_t)r1*Dd + c);
                *(float2*)(Out + (size_t)r0*Dd + c) =
                    make_float2(x0.x + mfv*d[0], x0.y + mfv*d[1]);
                *(float2*)(Out + (size_t)r1*Dd + c) =
                    make_float2(x1.x + mfv*d[2], x1.y + mfv*d[3]);
            }
        }
    }
}

// ------- kv-compress: single-term bf16 tensor cores (xh x Mh) + quant ----------
__global__ __launch_bounds__(256) void k_kvmma()
{
    extern __shared__ __nv_bfloat16 kvs[];   // 2 stages x 2 operands x 128*40
    const int m0 = blockIdx.x * 128;
    const int n  = m0 >> 12;
    const int tid = threadIdx.x, lane = tid & 31, warp = tid >> 5;
    const int wm = warp & 3, wn = warp >> 2;

    const __nv_bfloat16* srcs[2] = {
        g_xh + (size_t)m0*Dd,
        g_Mbh + (size_t)(n*128)*Dd };

    auto copyS = [&](int st, int k0) {
        __nv_bfloat16* base = kvs + (size_t)st*2*5120;
        #pragma unroll
        for (int op = 0; op < 2; op++) {
            #pragma unroll
            for (int i = 0; i < 2; i++) {
                int idx = tid + i*256;
                int r = idx >> 2, c = (idx & 3) * 8;
                cpa16(base + op*5120 + r*40 + c, srcs[op] + (size_t)r*Dd + k0 + c);
            }
        }
    };

    copyS(0, 0);
    CPCOMMIT();

    float acc[2][8][4];
    #pragma unroll
    for (int i = 0; i < 2; i++)
        #pragma unroll
        for (int j = 0; j < 8; j++)
            #pragma unroll
            for (int k = 0; k < 4; k++) acc[i][j][k] = 0.f;

    const int arow = wm*32 + (lane & 15);
    const int acol = ((lane >> 4) & 1) * 8;
    const int brow = wn*64 + (lane & 7) + ((lane >> 4) & 1) * 8;
    const int bcol = ((lane >> 3) & 1) * 8;

    for (int ks = 0; ks < 16; ks++) {
        int st = ks & 1;
        CPWAIT0();
        __syncthreads();
        if (ks < 15) { copyS(st ^ 1, (ks+1)*32); CPCOMMIT(); }

        const __nv_bfloat16* Ahs = kvs + (size_t)st*2*5120;
        const __nv_bfloat16* Bhs = Ahs + 5120;

        uint32_t ah[2][2][4];
        #pragma unroll
        for (int mf = 0; mf < 2; mf++)
            #pragma unroll
            for (int kf = 0; kf < 2; kf++)
                ldsm4(ah[mf][kf], Ahs + (arow + mf*16)*40 + kf*16 + acol);

        #pragma unroll
        for (int ng = 0; ng < 4; ng++) {
            uint32_t bh[2][4];
            #pragma unroll
            for (int kf = 0; kf < 2; kf++)
                ldsm4(bh[kf], Bhs + (brow + ng*16)*40 + kf*16 + bcol);
            #pragma unroll
            for (int s = 0; s < 2; s++) {
                int nf = ng*2 + s;
                #pragma unroll
                for (int mf = 0; mf < 2; mf++) {
                    mmabf(acc[mf][nf], ah[mf][0], bh[0][2*s], bh[0][2*s+1]);
                    mmabf(acc[mf][nf], ah[mf][1], bh[1][2*s], bh[1][2*s+1]);
                }
            }
        }
    }

    const float mfv = g_maskf[n];
    const int mrow = m0 + wm*32 + (lane >> 2);
    float smv[16], cmv[16];
    #pragma unroll
    for (int nf = 0; nf < 8; nf++) {
        int o = wn*64 + nf*8 + (lane & 3)*2;
        smv[2*nf]   = g_SM[n*128 + o];   smv[2*nf+1] = g_SM[n*128 + o + 1];
        cmv[2*nf]   = g_CM[n*128 + o];   cmv[2*nf+1] = g_CM[n*128 + o + 1];
    }
    float* dstb = (wn == 0) ? g_kq : g_vq;
    #pragma unroll
    for (int mf2 = 0; mf2 < 2; mf2++) {
        #pragma unroll
        for (int rr = 0; rr < 2; rr++) {
            int r = mrow + mf2*16 + rr*8;
            float rsv = g_rs[r], murs = g_mu[r]*rsv;
            float v[16]; float am = 0.f;
            #pragma unroll
            for (int nf = 0; nf < 8; nf++) {
                #pragma unroll
                for (int t = 0; t < 2; t++) {
                    float val = (rsv*acc[mf2][nf][2*rr+t] - murs*smv[2*nf+t] + cmv[2*nf+t]) * mfv;
                    v[2*nf+t] = val;
                    am = fmaxf(am, fabsf(val));
                }
            }
            am = fmaxf(am, __shfl_xor_sync(0xffffffffu, am, 1));
            am = fmaxf(am, __shfl_xor_sync(0xffffffffu, am, 2));
            am = fmaxf(am, 1e-8f);
            float scq = 127.f / am;
            float inv = am * (1.f / 127.f);
            #pragma unroll
            for (int nf = 0; nf < 8; nf++) {
                float q0 = rintf(v[2*nf]   * scq) * inv;
                float q1 = rintf(v[2*nf+1] * scq) * inv;
                *(float2*)(dstb + (size_t)r*64 + nf*8 + (lane & 3)*2) = make_float2(q0, q1);
            }
        }
    }
}

// ---------------- transpose decoders ----------------
__global__ void k_transdec(const float* __restrict__ kd, const float* __restrict__ vd)
{
    int idx = blockIdx.x * 256 + threadIdx.x;
    int d = idx >> 6, r = idx & 63;
    g_kdecT[r*Dd + d] = kd[idx];
    g_vdecT[r*Dd + d] = vd[idx];
}

// ---------------- average over n + decompress -> bf16 K/V ----------------
__global__ __launch_bounds__(256) void k_decomp()
{
    __shared__ float avg[16][64];
    int bt0 = blockIdx.x * 16;
    int isv = blockIdx.y;
    const float* src = isv ? g_vq : g_kq;
    const float* dec = isv ? g_vdecT : g_kdecT;
    __nv_bfloat16* dstb = isv ? g_Vh : g_Kh;
    float invna = g_invna;
    int tid = threadIdx.x;
    #pragma unroll
    for (int j = 0; j < 4; j++) {
        int p = j*256 + tid;
        int row = p >> 6, r = p & 63;
        float s = 0.f;
        #pragma unroll
        for (int n = 0; n < Nn; n++)
            s += src[((size_t)(n*BTc + bt0 + row))*64 + r];
        avg[row][r] = s * invna;
    }
    __syncthreads();
    int d0 = tid * 2;
    float2 acc[16];
    #pragma unroll
    for (int row = 0; row < 16; row++) { acc[row].x = 0.f; acc[row].y = 0.f; }
    for (int r = 0; r < 64; r++) {
        float2 kd = *(const float2*)(dec + r*Dd + d0);
        #pragma unroll
        for (int row = 0; row < 16; row++) {
            float a = avg[row][r];
            acc[row].x = fmaf(a, kd.x, acc[row].x);
            acc[row].y = fmaf(a, kd.y, acc[row].y);
        }
    }
    float sc = isv ? 1.f : INV_SQRT_HD;
    int h = d0 >> 7, hd = d0 & 127;
    #pragma unroll
    for (int row = 0; row < 16; row++) {
        int bt = bt0 + row;
        int b = bt >> 10, t = bt & 1023;
        __nv_bfloat16* dst = dstb + (((size_t)(b*Hh+h)*Tt + t)*HDc + hd);
        *(uint32_t*)dst = pk2(acc[row].x * sc, acc[row].y * sc);
    }
}

// -------- causal flash attention: bf16 mma, paired q-tiles (R6 version) ---------
__global__ __launch_bounds__(128) void k_flash()
{
    extern __shared__ __nv_bfloat16 smb[];
    __nv_bfloat16* Qs = smb;
    __nv_bfloat16* KV = Qs + 64*FSTR;
    const int nbh = blockIdx.y;
    const int n = nbh >> 4, b = (nbh >> 2) & 3, h = nbh & 3;
    const int tid = threadIdx.x, lane = tid & 31, warp = tid >> 5;

    const size_t kvbase = (size_t)(b*Hh + h) * Tt * HDc;
    const int r0q = warp*16 + (lane >> 2);
    const int c0q = (lane & 3) * 2;

    auto copyKV = [&](int buf, int k0) {
        __nv_bfloat16* Kb = KV + (size_t)buf * 2*64*FSTR;
        __nv_bfloat16* Vb = Kb + 64*FSTR;
        #pragma unroll
        for (int i = 0; i < 8; i++) {
            int idx = tid + i*128;
            int r = idx >> 4, c = (idx & 15)*8;
            size_t src = kvbase + (size_t)(k0 + r)*HDc + c;
            cpa16(&Kb[r*FSTR + c], g_Kh + src);
            cpa16(&Vb[r*FSTR + c], g_Vh + src);
        }
    };

    #pragma unroll
    for (int phase = 0; phase < 2; phase++) {
        const int qt = phase ? (NT - 1 - (int)blockIdx.x) : (int)blockIdx.x;
        const int q0 = qt * 64;
        const size_t qbase = ((size_t)(n*Bb + b)*Tt + q0) * Dd + h*HDc;

        if (phase) __syncthreads();

        #pragma unroll
        for (int i = 0; i < 8; i++) {
            int idx = tid + i*128;
            int r = idx >> 4, c = (idx & 15) * 8;
            cpa16(&Qs[r*FSTR + c], g_Qh + qbase + (size_t)r*Dd + c);
        }
        CPCOMMIT();
        copyKV(0, 0);
        CPCOMMIT();
        CPWAIT0();
        __syncthreads();

        uint32_t qf[8][4];
        {
            const __nv_bfloat16* qp = Qs + (warp*16 + (lane & 15))*FSTR + (lane >> 4)*8;
            #pragma unroll
            for (int kf = 0; kf < 8; kf++) ldsm4(qf[kf], qp + kf*16);
        }

        float accO[16][4];
        #pragma unroll
        for (int i = 0; i < 16; i++)
            #pragma unroll
            for (int j = 0; j < 4; j++) accO[i][j] = 0.f;
        float mrow[2] = {-1e30f, -1e30f};
        float lrow[2] = {0.f, 0.f};

        for (int kt = 0; kt <= qt; kt++) {
            if (kt > 0) { CPWAIT0(); __syncthreads(); }
            if (kt < qt) { copyKV((kt+1) & 1, (kt+1)*64); CPCOMMIT(); }

            const __nv_bfloat16* Kb = KV + (size_t)(kt & 1) * 2*64*FSTR;
            const __nv_bfloat16* Vb = Kb + 64*FSTR;

            float sfr[8][4];
            #pragma unroll
            for (int i = 0; i < 8; i++)
                #pragma unroll
                for (int j = 0; j < 4; j++) sfr[i][j] = 0.f;

            {
                const __nv_bfloat16* kp = Kb + ((lane & 7) + ((lane >> 4) & 1)*8)*FSTR
                                             + ((lane >> 3) & 1)*8;
                #pragma unroll
                for (int ng = 0; ng < 4; ng++) {
                    #pragma unroll
                    for (int kf = 0; kf < 8; kf++) {
                        uint32_t bf[4];
                        ldsm4(bf, kp + ng*16*FSTR + kf*16);
                        mmabf(sfr[2*ng],   qf[kf], bf[0], bf[1]);
                        mmabf(sfr[2*ng+1], qf[kf], bf[2], bf[3]);
                    }
                }
            }

            if (kt == qt) {
                #pragma unroll
                for (int j = 0; j < 8; j++) {
                    int cj = 8*j + c0q;
                    #pragma unroll
                    for (int rr = 0; rr < 2; rr++) {
                        int ri = r0q + 8*rr;
                        if (cj     > ri) sfr[j][2*rr]   = -1e30f;
                        if (cj + 1 > ri) sfr[j][2*rr+1] = -1e30f;
                    }
                }
            }

            #pragma unroll
            for (int rr = 0; rr < 2; rr++) {
                float tm = -1e30f;
                #pragma unroll
                for (int j = 0; j < 8; j++)
                    tm = fmaxf(tm, fmaxf(sfr[j][2*rr], sfr[j][2*rr+1]));
                tm = fmaxf(tm, __shfl_xor_sync(0xffffffffu, tm, 1));
                tm = fmaxf(tm, __shfl_xor_sync(0xffffffffu, tm, 2));
                float mnew = fmaxf(mrow[rr], tm);
                float scl = exp2f((mrow[rr] - mnew) * L2E);
                float ps = 0.f;
                #pragma unroll
                for (int j = 0; j < 8; j++) {
                    float e0 = exp2f((sfr[j][2*rr]   - mnew) * L2E);
                    float e1 = exp2f((sfr[j][2*rr+1] - mnew) * L2E);
                    sfr[j][2*rr] = e0; sfr[j][2*rr+1] = e1;
                    ps += e0 + e1;
                }
                ps += __shfl_xor_sync(0xffffffffu, ps, 1);
                ps += __shfl_xor_sync(0xffffffffu, ps, 2);
                lrow[rr] = lrow[rr]*scl + ps;
                mrow[rr] = mnew;
                #pragma unroll
                for (int nf = 0; nf < 16; nf++) {
                    accO[nf][2*rr]   *= scl;
                    accO[nf][2*rr+1] *= scl;
                }
            }

            uint32_t pa[4][4];
            #pragma unroll
            for (int kg = 0; kg < 4; kg++) {
                pa[kg][0] = pk2(sfr[2*kg][0],   sfr[2*kg][1]);
                pa[kg][1] = pk2(sfr[2*kg][2],   sfr[2*kg][3]);
                pa[kg][2] = pk2(sfr[2*kg+1][0], sfr[2*kg+1][1]);
                pa[kg][3] = pk2(sfr[2*kg+1][2], sfr[2*kg+1][3]);
            }

            {
                const __nv_bfloat16* vp = Vb + (lane & 15)*FSTR + (lane >> 4)*8;
                #pragma unroll
                for (int dg = 0; dg < 8; dg++) {
                    #pragma unroll
                    for (int kg = 0; kg < 4; kg++) {
                        uint32_t vb[4];
                        ldsm4t(vb, vp + kg*16*FSTR + dg*16);
                        mmabf(accO[2*dg],   pa[kg], vb[0], vb[1]);
                        mmabf(accO[2*dg+1], pa[kg], vb[2], vb[3]);
                    }
                }
            }
        }

        #pragma unroll
        for (int rr = 0; rr < 2; rr++) {
            float inv = 1.f / lrow[rr];
            size_t row = (size_t)(n*Bb + b)*Tt + q0 + r0q + 8*rr;
            __nv_bfloat16* dst = g_AOh + row*Dd + h*HDc;
            #pragma unroll
            for (int nf = 0; nf < 16; nf++) {
                *(uint32_t*)(dst + 8*nf + c0q) =
                    pk2(accO[nf][2*rr]*inv, accO[nf][2*rr+1]*inv);
            }
        }
    }
}

// ---------------- launch (R6 schedule) ----------------
extern "C" void kernel_launch(void* const* d_in, const int* in_sizes, int n_in,
                              void* d_out, int out_size)
{
    (void)in_sizes; (void)n_in; (void)out_size;
    const float* x     = (const float*)d_in[0];
    const unsigned char* mask = (const unsigned char*)d_in[1];
    const float* lnkw  = (const float*)d_in[2];
    const float* lnkb  = (const float*)d_in[3];
    const float* lnqw  = (const float*)d_in[4];
    const float* lnqb  = (const float*)d_in[5];
    const float* wk    = (const float*)d_in[6];
    const float* wv    = (const float*)d_in[7];
    const float* wq    = (const float*)d_in[8];
    const float* wo    = (const float*)d_in[9];
    const float* kcomp = (const float*)d_in[10];
    const float* vcomp = (const float*)d_in[11];
    const float* kdec  = (const float*)d_in[12];
    const float* vdec  = (const float*)d_in[13];
    float* out = (float*)d_out;

    static cudaStream_t s1 = nullptr, s2 = nullptr;
    static cudaEvent_t eRoot, eLn, eTd, eH0;
    static bool init_done = false;
    if (!init_done) {
        cudaStreamCreateWithFlags(&s1, cudaStreamNonBlocking);
        cudaStreamCreateWithFlags(&s2, cudaStreamNonBlocking);
        cudaEventCreateWithFlags(&eRoot, cudaEventDisableTiming);
        cudaEventCreateWithFlags(&eLn,   cudaEventDisableTiming);
        cudaEventCreateWithFlags(&eTd,   cudaEventDisableTiming);
        cudaEventCreateWithFlags(&eH0,   cudaEventDisableTiming);
        cudaFuncSetAttribute(k_flash, cudaFuncAttributeMaxDynamicSharedMemorySize,
                             5*64*FSTR*2);
        cudaFuncSetAttribute(k_kvmma, cudaFuncAttributeMaxDynamicSharedMemorySize,
                             2*2*5120*2);
        init_done = true;
    }

    // fork
    cudaEventRecord(eRoot, 0);
    cudaStreamWaitEvent(s1, eRoot, 0);
    cudaStreamWaitEvent(s2, eRoot, 0);

    // s1: LN stats + x bf16, decoder transpose, w_o convert
    k_lnstats<<<NROWS/8, 256, 0, s1>>>(x);
    cudaEventRecord(eLn, s1);
    k_transdec<<<128, 256, 0, s1>>>(kdec, vdec);
    k_convwo<<<Nn*Dd*Dd/4/256, 256, 0, s1>>>(wo);
    cudaEventRecord(eTd, s1);

    // s2: Q-branch fold + Q projection
    k_foldQ<<<Nn*Dd/8, 256, 0, s2>>>(lnqw, lnqb, wq);
    cudaStreamWaitEvent(s2, eLn, 0);
    k_hgemm<0><<<dim3(4, NROWS/128), 256, 0, s2>>>(nullptr, nullptr);
    cudaEventRecord(eH0, s2);

    // s0: KV chain
    k_mask<<<1, 32>>>(mask);
    k_compgemm<<<dim3(Nn, 2, 8), 256>>>(kcomp, vcomp, wk, wv);
    k_foldM<<<Nn*128/8, 256>>>(lnkw, lnkb);
    cudaStreamWaitEvent(0, eLn, 0);
    k_kvmma<<<NROWS/128, 256, 2*2*5120*2>>>();
    cudaStreamWaitEvent(0, eTd, 0);
    k_decomp<<<dim3(BTc/16, 2), 256>>>();
    cudaStreamWaitEvent(0, eH0, 0);
    k_flash<<<dim3(NT/2, Nn*Bb*Hh), 128, 5*64*FSTR*2>>>();
    k_hgemm<1><<<dim3(4, NROWS/128), 256>>>(x, out);
}

// round 14
// speedup vs baseline: 1.2053x; 1.0218x over previous
#include <cuda_runtime.h>
#include <cuda_bf16.h>
#include <cstdint>
#include <cstddef>

#define Nn 8
#define Bb 4
#define Tt 1024
#define Dd 512
#define Hh 4
#define HDc 128
#define Rr 64
#define BTc (Bb*Tt)
#define NROWS (Nn*BTc)
#define EPSV 1e-5f
#define INV_SQRT_HD 0.08838834764831845f
#define L2E 1.4426950408889634f
#define FSTR 136
#define NT (Tt/64)

// ---------------- device scratch ----------------
__device__ float g_mu[NROWS];
__device__ float g_rs[NROWS];
__device__ float g_maskf[Nn];
__device__ float g_invna;
__device__ __nv_bfloat16 g_xh[(size_t)NROWS*Dd];
__device__ __nv_bfloat16 g_Wqh[Nn*Dd*Dd];
__device__ __nv_bfloat16 g_Woh[Nn*Dd*Dd];
__device__ float g_Sq[Nn*Dd];
__device__ float g_Cq[Nn*Dd];
__device__ __nv_bfloat16 g_Mbh[Nn*128*Dd];
__device__ float g_SMp[Nn*128*8];
__device__ float g_CMp[Nn*128*8];
__device__ float g_SM[Nn*128];
__device__ float g_CM[Nn*128];
__device__ __nv_bfloat16 g_kq[(size_t)NROWS*Rr];
__device__ __nv_bfloat16 g_vq[(size_t)NROWS*Rr];
__device__ float g_kdecT[Rr*Dd];
__device__ float g_vdecT[Rr*Dd];
__device__ __nv_bfloat16 g_Kh[(size_t)Bb*Hh*Tt*HDc];
__device__ __nv_bfloat16 g_Vh[(size_t)Bb*Hh*Tt*HDc];
__device__ __nv_bfloat16 g_Qh[(size_t)NROWS*Dd];
__device__ __nv_bfloat16 g_AOh[(size_t)NROWS*Dd];

// ---------------- helpers ----------------
__device__ __forceinline__ uint32_t pk2(float x, float y)
{
    __nv_bfloat162 h = __float22bfloat162_rn(make_float2(x, y));
    return *reinterpret_cast<uint32_t*>(&h);
}

__device__ __forceinline__ void ldsm4(uint32_t* r, const __nv_bfloat16* p)
{
    uint32_t a = (uint32_t)__cvta_generic_to_shared((void*)p);
    asm volatile("ldmatrix.sync.aligned.m8n8.x4.shared.b16 {%0,%1,%2,%3}, [%4];\n"
                 : "=r"(r[0]), "=r"(r[1]), "=r"(r[2]), "=r"(r[3]) : "r"(a));
}

__device__ __forceinline__ void ldsm4t(uint32_t* r, const __nv_bfloat16* p)
{
    uint32_t a = (uint32_t)__cvta_generic_to_shared((void*)p);
    asm volatile("ldmatrix.sync.aligned.m8n8.x4.trans.shared.b16 {%0,%1,%2,%3}, [%4];\n"
                 : "=r"(r[0]), "=r"(r[1]), "=r"(r[2]), "=r"(r[3]) : "r"(a));
}

__device__ __forceinline__ void mmabf(float* d, const uint32_t* a, uint32_t b0, uint32_t b1)
{
    asm volatile("mma.sync.aligned.m16n8k16.row.col.f32.bf16.bf16.f32 "
                 "{%0,%1,%2,%3},{%4,%5,%6,%7},{%8,%9},{%0,%1,%2,%3};\n"
                 : "+f"(d[0]), "+f"(d[1]), "+f"(d[2]), "+f"(d[3])
                 : "r"(a[0]), "r"(a[1]), "r"(a[2]), "r"(a[3]), "r"(b0), "r"(b1));
}

__device__ __forceinline__ void cpa16(const void* smem_dst, const void* gsrc)
{
    uint32_t ds = (uint32_t)__cvta_generic_to_shared((void*)smem_dst);
    asm volatile("cp.async.cg.shared.global [%0], [%1], 16;\n" :: "r"(ds), "l"(gsrc));
}
#define CPCOMMIT() asm volatile("cp.async.commit_group;\n" ::: "memory")
#define CPWAIT0()  asm volatile("cp.async.wait_group 0;\n" ::: "memory")

// ---------------- mask decode ----------------
__global__ void k_mask(const unsigned char* __restrict__ p)
{
    if (threadIdx.x == 0) {
        bool isF = (p[0]==0 && p[1]==0 && p[2]==0x80 && p[3]==0x3f);
        bool isI = (!isF && p[1]==0 && p[2]==0 && p[3]==0 && (p[4]!=0 || p[5]==0));
        float na = 0.f;
        for (int n = 0; n < Nn; n++) {
            bool bit;
            if (isF)      bit = (((const float*)p)[n] != 0.f);
            else if (isI) bit = (((const int*)p)[n]   != 0);
            else          bit = (p[n] != 0);
            g_maskf[n] = bit ? 1.f : 0.f;
            na += bit ? 1.f : 0.f;
        }
        g_invna = 1.f / fmaxf(na, 1.f);
    }
}

// ---------------- LN row stats + bf16 copy of x ----------------
__global__ __launch_bounds__(256) void k_lnstats(const float* __restrict__ x)
{
    int row  = blockIdx.x * 8 + (threadIdx.x >> 5);
    int lane = threadIdx.x & 31;
    const float4* xp = (const float4*)(x + (size_t)row * Dd);
    float s = 0.f, sq = 0.f;
    #pragma unroll
    for (int i = 0; i < 4; i++) {
        int j = lane + 32*i;
        float4 v = xp[j];
        s  += v.x + v.y + v.z + v.w;
        sq += v.x*v.x + v.y*v.y + v.z*v.z + v.w*v.w;
        uint2 uh = make_uint2(pk2(v.x, v.y), pk2(v.z, v.w));
        *(uint2*)(g_xh + (size_t)row*Dd + 4*j) = uh;
    }
    #pragma unroll
    for (int o = 16; o > 0; o >>= 1) {
        s  += __shfl_xor_sync(0xffffffffu, s,  o);
        sq += __shfl_xor_sync(0xffffffffu, sq, o);
    }
    if (lane == 0) {
        float mu  = s * (1.f / Dd);
        float var = sq * (1.f / Dd) - mu * mu;
        g_mu[row] = mu;
        g_rs[row] = rsqrtf(var + EPSV);
    }
}

// ---------------- w_o -> bf16 ----------------
__global__ __launch_bounds__(256) void k_convwo(const float* __restrict__ wo)
{
    int idx = blockIdx.x * 256 + threadIdx.x;
    float4 v = ((const float4*)wo)[idx];
    ((uint2*)g_Woh)[idx] = make_uint2(pk2(v.x, v.y), pk2(v.z, v.w));
}

// ------- M[n] = comp @ w, fused LN-fold -> bf16 Mbh + SM/CM partials -----------
__global__ __launch_bounds__(256) void k_compgemm(
    const float* __restrict__ kcomp, const float* __restrict__ vcomp,
    const float* __restrict__ wk,    const float* __restrict__ wv,
    const float* __restrict__ lnw,   const float* __restrict__ lnb)
{
    __shared__ float As[32*68];
    __shared__ float Bs[32*68];
    const int n    = blockIdx.x;
    const int half = blockIdx.y;
    const int i0   = blockIdx.z * 64;
    const float* comp = (half == 0 ? kcomp : vcomp) + (size_t)n * Rr * Dd;
    const float* w    = (half == 0 ? wk    : wv   ) + (size_t)n * Dd * Dd;
    const int tid = threadIdx.x, ty = tid >> 4, tx = tid & 15;
    const int arA = tid & 63, acA = (tid >> 6) * 8;
    const int arB = tid & 31, acB = (tid >> 5) * 8;

    float acc[4][4] = {};
    for (int k0 = 0; k0 < Dd; k0 += 32) {
        float4 a0 = *(const float4*)(comp + (size_t)arA*Dd + k0 + acA);
        float4 a1 = *(const float4*)(comp + (size_t)arA*Dd + k0 + acA + 4);
        float4 b0 = *(const float4*)(w + (size_t)(k0+arB)*Dd + i0 + acB);
        float4 b1 = *(const float4*)(w + (size_t)(k0+arB)*Dd + i0 + acB + 4);
        __syncthreads();
        As[(acA+0)*68+arA]=a0.x; As[(acA+1)*68+arA]=a0.y; As[(acA+2)*68+arA]=a0.z; As[(acA+3)*68+arA]=a0.w;
        As[(acA+4)*68+arA]=a1.x; As[(acA+5)*68+arA]=a1.y; As[(acA+6)*68+arA]=a1.z; As[(acA+7)*68+arA]=a1.w;
        *(float4*)&Bs[arB*68 + acB]     = b0;
        *(float4*)&Bs[arB*68 + acB + 4] = b1;
        __syncthreads();
        #pragma unroll
        for (int kk = 0; kk < 32; kk++) {
            float4 a  = *(const float4*)&As[kk*68 + ty*4];
            float4 bb = *(const float4*)&Bs[kk*68 + tx*4];
            float av[4] = {a.x,a.y,a.z,a.w};
            float bv[4] = {bb.x,bb.y,bb.z,bb.w};
            #pragma unroll
            for (int i = 0; i < 4; i++)
                #pragma unroll
                for (int j = 0; j < 4; j++)
                    acc[i][j] = fmaf(av[i], bv[j], acc[i][j]);
        }
    }

    const float* lw = lnw + n*Dd + i0 + tx*4;
    const float* lb = lnb + n*Dd + i0 + tx*4;
    float wv4[4], bv4[4];
    #pragma unroll
    for (int j = 0; j < 4; j++) { wv4[j] = lw[j]; bv4[j] = lb[j]; }

    #pragma unroll
    for (int i = 0; i < 4; i++) {
        int row = n*128 + half*64 + ty*4 + i;
        float p[4]; float smp = 0.f, cmp = 0.f;
        #pragma unroll
        for (int j = 0; j < 4; j++) {
            float m = acc[i][j];
            p[j] = wv4[j] * m;
            smp += p[j];
            cmp += bv4[j] * m;
        }
        *(uint2*)(g_Mbh + (size_t)row*Dd + i0 + tx*4) =
            make_uint2(pk2(p[0], p[1]), pk2(p[2], p[3]));
        #pragma unroll
        for (int o = 8; o > 0; o >>= 1) {
            smp += __shfl_xor_sync(0xffffffffu, smp, o);
            cmp += __shfl_xor_sync(0xffffffffu, cmp, o);
        }
        if (tx == 0) {
            g_SMp[row*8 + (i0 >> 6)] = smp;
            g_CMp[row*8 + (i0 >> 6)] = cmp;
        }
    }
}

// ---------------- reduce SM/CM partials (deterministic) ----------------
__global__ __launch_bounds__(256) void k_foldSC()
{
    int row = blockIdx.x * 256 + threadIdx.x;   // 1024 rows
    float s = 0.f, c = 0.f;
    #pragma unroll
    for (int j = 0; j < 8; j++) {
        s += g_SMp[row*8 + j];
        c += g_CMp[row*8 + j];
    }
    g_SM[row] = s;
    g_CM[row] = c;
}

// ---------------- fold LN(q) into w_q -> bf16 ----------------
__global__ __launch_bounds__(256) void k_foldQ(const float* __restrict__ lnw,
                                               const float* __restrict__ lnb,
                                               const float* __restrict__ wq)
{
    int row  = blockIdx.x * 8 + (threadIdx.x >> 5);
    int lane = threadIdx.x & 31;
    int n = row >> 9;
    const float* lw = lnw + n*Dd;
    const float* lb = lnb + n*Dd;
    const float* wr = wq + (size_t)row * Dd;
    float sm = 0.f, cm = 0.f;
    for (int i = lane; i < Dd; i += 32) {
        float m = wr[i], w = lw[i], b = lb[i];
        float p = w * m;
        sm += p; cm += b * m;
        g_Wqh[(size_t)row*Dd + i] = __float2bfloat16(p);
    }
    #pragma unroll
    for (int o = 16; o > 0; o >>= 1) {
        sm += __shfl_xor_sync(0xffffffffu, sm, o);
        cm += __shfl_xor_sync(0xffffffffu, cm, o);
    }
    if (lane == 0) { g_Sq[row] = sm; g_Cq[row] = cm; }
}

// ------- bf16 GEMM 128x128xK512 with cp.async pipeline. MODE 0 = Q, 1 = O -------
template<int MODE>
__global__ __launch_bounds__(256, 2) void k_hgemm(const float* __restrict__ X,
                                                  float* __restrict__ Out)
{
    __shared__ __nv_bfloat16 As[2][128*40];
    __shared__ __nv_bfloat16 Bs[2][128*40];
    const int m0 = blockIdx.y * 128;
    const int o0 = blockIdx.x * 128;
    const int n  = m0 >> 12;
    const __nv_bfloat16* A = (MODE == 0) ? g_xh : g_AOh;
    const __nv_bfloat16* B = ((MODE == 0) ? g_Wqh : g_Woh) + (size_t)n * Dd * Dd;

    const int tid = threadIdx.x, lane = tid & 31, warp = tid >> 5;
    const int wm = warp & 3, wn = warp >> 2;

    auto copyAB = [&](int st, int k0) {
        #pragma unroll
        for (int i = 0; i < 2; i++) {
            int idx = tid + i*256;
            int r = idx >> 2, c = (idx & 3) * 8;
            cpa16(&As[st][r*40 + c], A + (size_t)(m0 + r)*Dd + k0 + c);
            cpa16(&Bs[st][r*40 + c], B + (size_t)(o0 + r)*Dd + k0 + c);
        }
    };

    copyAB(0, 0);
    CPCOMMIT();

    float acc[2][8][4];
    #pragma unroll
    for (int i = 0; i < 2; i++)
        #pragma unroll
        for (int j = 0; j < 8; j++)
            #pragma unroll
            for (int k = 0; k < 4; k++) acc[i][j][k] = 0.f;

    const int arow = wm*32 + (lane & 15);
    const int acol = ((lane >> 4) & 1) * 8;
    const int brow = wn*64 + (lane & 7) + ((lane >> 4) & 1) * 8;
    const int bcol = ((lane >> 3) & 1) * 8;

    for (int ks = 0; ks < 16; ks++) {
        int st = ks & 1;
        CPWAIT0();
        __syncthreads();
        if (ks < 15) { copyAB(st ^ 1, (ks+1)*32); CPCOMMIT(); }

        const __nv_bfloat16* Asb = As[st];
        const __nv_bfloat16* Bsb = Bs[st];

        uint32_t af[2][2][4];
        #pragma unroll
        for (int mf = 0; mf < 2; mf++)
            #pragma unroll
            for (int kf = 0; kf < 2; kf++)
                ldsm4(af[mf][kf], Asb + (arow + mf*16)*40 + kf*16 + acol);

        #pragma unroll
        for (int ng = 0; ng < 4; ng++) {
            uint32_t bfr[2][4];
            #pragma unroll
            for (int kf = 0; kf < 2; kf++)
                ldsm4(bfr[kf], Bsb + (brow + ng*16)*40 + kf*16 + bcol);
            #pragma unroll
            for (int s = 0; s < 2; s++) {
                int nf = ng*2 + s;
                #pragma unroll
                for (int mf = 0; mf < 2; mf++) {
                    mmabf(acc[mf][nf], af[mf][0], bfr[0][2*s], bfr[0][2*s+1]);
                    mmabf(acc[mf][nf], af[mf][1], bfr[1][2*s], bfr[1][2*s+1]);
                }
            }
        }
    }

    const int mrow = m0 + wm*32 + (lane >> 2);
    const int ocol = o0 + wn*64 + (lane & 3)*2;
    if (MODE == 0) {
        #pragma unroll
        for (int mf = 0; mf < 2; mf++) {
            int r0 = mrow + mf*16, r1 = r0 + 8;
            float rs0 = g_rs[r0], mr0 = g_mu[r0]*rs0;
            float rs1 = g_rs[r1], mr1 = g_mu[r1]*rs1;
            #pragma unroll
            for (int nf = 0; nf < 8; nf++) {
                int c = ocol + nf*8;
                float sq0 = g_Sq[n*Dd + c], sq1 = g_Sq[n*Dd + c + 1];
                float cq0 = g_Cq[n*Dd + c], cq1 = g_Cq[n*Dd + c + 1];
                float* d = acc[mf][nf];
                *(uint32_t*)(g_Qh + (size_t)r0*Dd + c) =
                    pk2(rs0*d[0] - mr0*sq0 + cq0, rs0*d[1] - mr0*sq1 + cq1);
                *(uint32_t*)(g_Qh + (size_t)r1*Dd + c) =
                    pk2(rs1*d[2] - mr1*sq0 + cq0, rs1*d[3] - mr1*sq1 + cq1);
            }
        }
    } else {
        float mfv = g_maskf[n];
        #pragma unroll
        for (int mf = 0; mf < 2; mf++) {
            int r0 = mrow + mf*16, r1 = r0 + 8;
            #pragma unroll
            for (int nf = 0; nf < 8; nf++) {
                int c = ocol + nf*8;
                float* d = acc[mf][nf];
                float2 x0 = *(const float2*)(X + (size_t)r0*Dd + c);
                float2 x1 = *(const float2*)(X + (size_t)r1*Dd + c);
                *(float2*)(Out + (size_t)r0*Dd + c) =
                    make_float2(x0.x + mfv*d[0], x0.y + mfv*d[1]);
                *(float2*)(Out + (size_t)r1*Dd + c) =
                    make_float2(x1.x + mfv*d[2], x1.y + mfv*d[3]);
            }
        }
    }
}

// ------- kv-compress: single-term bf16 tensor cores (xh x Mh) + quant ----------
__global__ __launch_bounds__(256) void k_kvmma()
{
    extern __shared__ __nv_bfloat16 kvs[];   // 2 stages x 2 operands x 128*40
    const int m0 = blockIdx.x * 128;
    const int n  = m0 >> 12;
    const int tid = threadIdx.x, lane = tid & 31, warp = tid >> 5;
    const int wm = warp & 3, wn = warp >> 2;

    const __nv_bfloat16* srcs[2] = {
        g_xh + (size_t)m0*Dd,
        g_Mbh + (size_t)(n*128)*Dd };

    auto copyS = [&](int st, int k0) {
        __nv_bfloat16* base = kvs + (size_t)st*2*5120;
        #pragma unroll
        for (int op = 0; op < 2; op++) {
            #pragma unroll
            for (int i = 0; i < 2; i++) {
                int idx = tid + i*256;
                int r = idx >> 2, c = (idx & 3) * 8;
                cpa16(base + op*5120 + r*40 + c, srcs[op] + (size_t)r*Dd + k0 + c);
            }
        }
    };

    copyS(0, 0);
    CPCOMMIT();

    float acc[2][8][4];
    #pragma unroll
    for (int i = 0; i < 2; i++)
        #pragma unroll
        for (int j = 0; j < 8; j++)
            #pragma unroll
            for (int k = 0; k < 4; k++) acc[i][j][k] = 0.f;

    const int arow = wm*32 + (lane & 15);
    const int acol = ((lane >> 4) & 1) * 8;
    const int brow = wn*64 + (lane & 7) + ((lane >> 4) & 1) * 8;
    const int bcol = ((lane >> 3) & 1) * 8;

    for (int ks = 0; ks < 16; ks++) {
        int st = ks & 1;
        CPWAIT0();
        __syncthreads();
        if (ks < 15) { copyS(st ^ 1, (ks+1)*32); CPCOMMIT(); }

        const __nv_bfloat16* Ahs = kvs + (size_t)st*2*5120;
        const __nv_bfloat16* Bhs = Ahs + 5120;

        uint32_t ah[2][2][4];
        #pragma unroll
        for (int mf = 0; mf < 2; mf++)
            #pragma unroll
            for (int kf = 0; kf < 2; kf++)
                ldsm4(ah[mf][kf], Ahs + (arow + mf*16)*40 + kf*16 + acol);

        #pragma unroll
        for (int ng = 0; ng < 4; ng++) {
            uint32_t bh[2][4];
            #pragma unroll
            for (int kf = 0; kf < 2; kf++)
                ldsm4(bh[kf], Bhs + (brow + ng*16)*40 + kf*16 + bcol);
            #pragma unroll
            for (int s = 0; s < 2; s++) {
                int nf = ng*2 + s;
                #pragma unroll
                for (int mf = 0; mf < 2; mf++) {
                    mmabf(acc[mf][nf], ah[mf][0], bh[0][2*s], bh[0][2*s+1]);
                    mmabf(acc[mf][nf], ah[mf][1], bh[1][2*s], bh[1][2*s+1]);
                }
            }
        }
    }

    const float mfv = g_maskf[n];
    const int mrow = m0 + wm*32 + (lane >> 2);
    float smv[16], cmv[16];
    #pragma unroll
    for (int nf = 0; nf < 8; nf++) {
        int o = wn*64 + nf*8 + (lane & 3)*2;
        smv[2*nf]   = g_SM[n*128 + o];   smv[2*nf+1] = g_SM[n*128 + o + 1];
        cmv[2*nf]   = g_CM[n*128 + o];   cmv[2*nf+1] = g_CM[n*128 + o + 1];
    }
    __nv_bfloat16* dstb = (wn == 0) ? g_kq : g_vq;
    #pragma unroll
    for (int mf2 = 0; mf2 < 2; mf2++) {
        #pragma unroll
        for (int rr = 0; rr < 2; rr++) {
            int r = mrow + mf2*16 + rr*8;
            float rsv = g_rs[r], murs = g_mu[r]*rsv;
            float v[16]; float am = 0.f;
            #pragma unroll
            for (int nf = 0; nf < 8; nf++) {
                #pragma unroll
                for (int t = 0; t < 2; t++) {
                    float val = (rsv*acc[mf2][nf][2*rr+t] - murs*smv[2*nf+t] + cmv[2*nf+t]) * mfv;
                    v[2*nf+t] = val;
                    am = fmaxf(am, fabsf(val));
                }
            }
            am = fmaxf(am, __shfl_xor_sync(0xffffffffu, am, 1));
            am = fmaxf(am, __shfl_xor_sync(0xffffffffu, am, 2));
            am = fmaxf(am, 1e-8f);
            float scq = 127.f / am;
            float inv = am * (1.f / 127.f);
            #pragma unroll
            for (int nf = 0; nf < 8; nf++) {
                float q0 = rintf(v[2*nf]   * scq) * inv;
                float q1 = rintf(v[2*nf+1] * scq) * inv;
                *(uint32_t*)(dstb + (size_t)r*64 + nf*8 + (lane & 3)*2) = pk2(q0, q1);
            }
        }
    }
}

// ---------------- transpose decoders ----------------
__global__ void k_transdec(const float* __restrict__ kd, const float* __restrict__ vd)
{
    int idx = blockIdx.x * 256 + threadIdx.x;
    int d = idx >> 6, r = idx & 63;
    g_kdecT[r*Dd + d] = kd[idx];
    g_vdecT[r*Dd + d] = vd[idx];
}

// ---------------- average over n + decompress -> bf16 K/V ----------------
__global__ __launch_bounds__(256) void k_decomp()
{
    __shared__ float avg[16][64];
    int bt0 = blockIdx.x * 16;
    int isv = blockIdx.y;
    const __nv_bfloat16* src = isv ? g_vq : g_kq;
    const float* dec = isv ? g_vdecT : g_kdecT;
    __nv_bfloat16* dstb = isv ? g_Vh : g_Kh;
    float invna = g_invna;
    int tid = threadIdx.x;
    #pragma unroll
    for (int j = 0; j < 4; j++) {
        int p = j*256 + tid;
        int row = p >> 6, r = p & 63;
        float s = 0.f;
        #pragma unroll
        for (int n = 0; n < Nn; n++)
            s += __bfloat162float(src[((size_t)(n*BTc + bt0 + row))*64 + r]);
        avg[row][r] = s * invna;
    }
    __syncthreads();
    int d0 = tid * 2;
    float2 acc[16];
    #pragma unroll
    for (int row = 0; row < 16; row++) { acc[row].x = 0.f; acc[row].y = 0.f; }
    for (int r = 0; r < 64; r++) {
        float2 kd = *(const float2*)(dec + r*Dd + d0);
        #pragma unroll
        for (int row = 0; row < 16; row++) {
            float a = avg[row][r];
            acc[row].x = fmaf(a, kd.x, acc[row].x);
            acc[row].y = fmaf(a, kd.y, acc[row].y);
        }
    }
    float sc = isv ? 1.f : INV_SQRT_HD;
    int h = d0 >> 7, hd = d0 & 127;
    #pragma unroll
    for (int row = 0; row < 16; row++) {
        int bt = bt0 + row;
        int b = bt >> 10, t = bt & 1023;
        __nv_bfloat16* dst = dstb + (((size_t)(b*Hh+h)*Tt + t)*HDc + hd);
        *(uint32_t*)dst = pk2(acc[row].x * sc, acc[row].y * sc);
    }
}

// -------- causal flash attention: bf16 mma, paired q-tiles (R6 version) ---------
__global__ __launch_bounds__(128) void k_flash()
{
    extern __shared__ __nv_bfloat16 smb[];
    __nv_bfloat16* Qs = smb;
    __nv_bfloat16* KV = Qs + 64*FSTR;
    const int nbh = blockIdx.y;
    const int n = nbh >> 4, b = (nbh >> 2) & 3, h = nbh & 3;
    const int tid = threadIdx.x, lane = tid & 31, warp = tid >> 5;

    const size_t kvbase = (size_t)(b*Hh + h) * Tt * HDc;
    const int r0q = warp*16 + (lane >> 2);
    const int c0q = (lane & 3) * 2;

    auto copyKV = [&](int buf, int k0) {
        __nv_bfloat16* Kb = KV + (size_t)buf * 2*64*FSTR;
        __nv_bfloat16* Vb = Kb + 64*FSTR;
        #pragma unroll
        for (int i = 0; i < 8; i++) {
            int idx = tid + i*128;
            int r = idx >> 4, c = (idx & 15)*8;
            size_t src = kvbase + (size_t)(k0 + r)*HDc + c;
            cpa16(&Kb[r*FSTR + c], g_Kh + src);
            cpa16(&Vb[r*FSTR + c], g_Vh + src);
        }
    };

    #pragma unroll
    for (int phase = 0; phase < 2; phase++) {
        const int qt = phase ? (NT - 1 - (int)blockIdx.x) : (int)blockIdx.x;
        const int q0 = qt * 64;
        const size_t qbase = ((size_t)(n*Bb + b)*Tt + q0) * Dd + h*HDc;

        if (phase) __syncthreads();

        #pragma unroll
        for (int i = 0; i < 8; i++) {
            int idx = tid + i*128;
            int r = idx >> 4, c = (idx & 15) * 8;
            cpa16(&Qs[r*FSTR + c], g_Qh + qbase + (size_t)r*Dd + c);
        }
        CPCOMMIT();
        copyKV(0, 0);
        CPCOMMIT();
        CPWAIT0();
        __syncthreads();

        uint32_t qf[8][4];
        {
            const __nv_bfloat16* qp = Qs + (warp*16 + (lane & 15))*FSTR + (lane >> 4)*8;
            #pragma unroll
            for (int kf = 0; kf < 8; kf++) ldsm4(qf[kf], qp + kf*16);
        }

        float accO[16][4];
        #pragma unroll
        for (int i = 0; i < 16; i++)
            #pragma unroll
            for (int j = 0; j < 4; j++) accO[i][j] = 0.f;
        float mrow[2] = {-1e30f, -1e30f};
        float lrow[2] = {0.f, 0.f};

        for (int kt = 0; kt <= qt; kt++) {
            if (kt > 0) { CPWAIT0(); __syncthreads(); }
            if (kt < qt) { copyKV((kt+1) & 1, (kt+1)*64); CPCOMMIT(); }

            const __nv_bfloat16* Kb = KV + (size_t)(kt & 1) * 2*64*FSTR;
            const __nv_bfloat16* Vb = Kb + 64*FSTR;

            float sfr[8][4];
            #pragma unroll
            for (int i = 0; i < 8; i++)
                #pragma unroll
                for (int j = 0; j < 4; j++) sfr[i][j] = 0.f;

            {
                const __nv_bfloat16* kp = Kb + ((lane & 7) + ((lane >> 4) & 1)*8)*FSTR
                                             + ((lane >> 3) & 1)*8;
                #pragma unroll
                for (int ng = 0; ng < 4; ng++) {
                    #pragma unroll
                    for (int kf = 0; kf < 8; kf++) {
                        uint32_t bf[4];
                        ldsm4(bf, kp + ng*16*FSTR + kf*16);
                        mmabf(sfr[2*ng],   qf[kf], bf[0], bf[1]);
                        mmabf(sfr[2*ng+1], qf[kf], bf[2], bf[3]);
                    }
                }
            }

            if (kt == qt) {
                #pragma unroll
                for (int j = 0; j < 8; j++) {
                    int cj = 8*j + c0q;
                    #pragma unroll
                    for (int rr = 0; rr < 2; rr++) {
                        int ri = r0q + 8*rr;
                        if (cj     > ri) sfr[j][2*rr]   = -1e30f;
                        if (cj + 1 > ri) sfr[j][2*rr+1] = -1e30f;
                    }
                }
            }

            #pragma unroll
            for (int rr = 0; rr < 2; rr++) {
                float tm = -1e30f;
                #pragma unroll
                for (int j = 0; j < 8; j++)
                    tm = fmaxf(tm, fmaxf(sfr[j][2*rr], sfr[j][2*rr+1]));
                tm = fmaxf(tm, __shfl_xor_sync(0xffffffffu, tm, 1));
                tm = fmaxf(tm, __shfl_xor_sync(0xffffffffu, tm, 2));
                float mnew = fmaxf(mrow[rr], tm);
                float scl = exp2f((mrow[rr] - mnew) * L2E);
                float ps = 0.f;
                #pragma unroll
                for (int j = 0; j < 8; j++) {
                    float e0 = exp2f((sfr[j][2*rr]   - mnew) * L2E);
                    float e1 = exp2f((sfr[j][2*rr+1] - mnew) * L2E);
                    sfr[j][2*rr] = e0; sfr[j][2*rr+1] = e1;
                    ps += e0 + e1;
                }
                ps += __shfl_xor_sync(0xffffffffu, ps, 1);
                ps += __shfl_xor_sync(0xffffffffu, ps, 2);
                lrow[rr] = lrow[rr]*scl + ps;
                mrow[rr] = mnew;
                #pragma unroll
                for (int nf = 0; nf < 16; nf++) {
                    accO[nf][2*rr]   *= scl;
                    accO[nf][2*rr+1] *= scl;
                }
            }

            uint32_t pa[4][4];
            #pragma unroll
            for (int kg = 0; kg < 4; kg++) {
                pa[kg][0] = pk2(sfr[2*kg][0],   sfr[2*kg][1]);
                pa[kg][1] = pk2(sfr[2*kg][2],   sfr[2*kg][3]);
                pa[kg][2] = pk2(sfr[2*kg+1][0], sfr[2*kg+1][1]);
                pa[kg][3] = pk2(sfr[2*kg+1][2], sfr[2*kg+1][3]);
            }

            {
                const __nv_bfloat16* vp = Vb + (lane & 15)*FSTR + (lane >> 4)*8;
                #pragma unroll
                for (int dg = 0; dg < 8; dg++) {
                    #pragma unroll
                    for (int kg = 0; kg < 4; kg++) {
                        uint32_t vb[4];
                        ldsm4t(vb, vp + kg*16*FSTR + dg*16);
                        mmabf(accO[2*dg],   pa[kg], vb[0], vb[1]);
                        mmabf(accO[2*dg+1], pa[kg], vb[2], vb[3]);
                    }
                }
            }
        }

        #pragma unroll
        for (int rr = 0; rr < 2; rr++) {
            float inv = 1.f / lrow[rr];
            size_t row = (size_t)(n*Bb + b)*Tt + q0 + r0q + 8*rr;
            __nv_bfloat16* dst = g_AOh + row*Dd + h*HDc;
            #pragma unroll
            for (int nf = 0; nf < 16; nf++) {
                *(uint32_t*)(dst + 8*nf + c0q) =
                    pk2(accO[nf][2*rr]*inv, accO[nf][2*rr+1]*inv);
            }
        }
    }
}

// ---------------- launch (R6 schedule, fused foldM) ----------------
extern "C" void kernel_launch(void* const* d_in, const int* in_sizes, int n_in,
                              void* d_out, int out_size)
{
    (void)in_sizes; (void)n_in; (void)out_size;
    const float* x     = (const float*)d_in[0];
    const unsigned char* mask = (const unsigned char*)d_in[1];
    const float* lnkw  = (const float*)d_in[2];
    const float* lnkb  = (const float*)d_in[3];
    const float* lnqw  = (const float*)d_in[4];
    const float* lnqb  = (const float*)d_in[5];
    const float* wk    = (const float*)d_in[6];
    const float* wv    = (const float*)d_in[7];
    const float* wq    = (const float*)d_in[8];
    const float* wo    = (const float*)d_in[9];
    const float* kcomp = (const float*)d_in[10];
    const float* vcomp = (const float*)d_in[11];
    const float* kdec  = (const float*)d_in[12];
    const float* vdec  = (const float*)d_in[13];
    float* out = (float*)d_out;

    static cudaStream_t s1 = nullptr, s2 = nullptr;
    static cudaEvent_t eRoot, eLn, eTd, eH0;
    static bool init_done = false;
    if (!init_done) {
        cudaStreamCreateWithFlags(&s1, cudaStreamNonBlocking);
        cudaStreamCreateWithFlags(&s2, cudaStreamNonBlocking);
        cudaEventCreateWithFlags(&eRoot, cudaEventDisableTiming);
        cudaEventCreateWithFlags(&eLn,   cudaEventDisableTiming);
        cudaEventCreateWithFlags(&eTd,   cudaEventDisableTiming);
        cudaEventCreateWithFlags(&eH0,   cudaEventDisableTiming);
        cudaFuncSetAttribute(k_flash, cudaFuncAttributeMaxDynamicSharedMemorySize,
                             5*64*FSTR*2);
        cudaFuncSetAttribute(k_kvmma, cudaFuncAttributeMaxDynamicSharedMemorySize,
                             2*2*5120*2);
        init_done = true;
    }

    // fork
    cudaEventRecord(eRoot, 0);
    cudaStreamWaitEvent(s1, eRoot, 0);
    cudaStreamWaitEvent(s2, eRoot, 0);

    // s1: LN stats + x bf16, decoder transpose, w_o convert
    k_lnstats<<<NROWS/8, 256, 0, s1>>>(x);
    cudaEventRecord(eLn, s1);
    k_transdec<<<128, 256, 0, s1>>>(kdec, vdec);
    k_convwo<<<Nn*Dd*Dd/4/256, 256, 0, s1>>>(wo);
    cudaEventRecord(eTd, s1);

    // s2: Q-branch fold + Q projection
    k_foldQ<<<Nn*Dd/8, 256, 0, s2>>>(lnqw, lnqb, wq);
    cudaStreamWaitEvent(s2, eLn, 0);
    k_hgemm<0><<<dim3(4, NROWS/128), 256, 0, s2>>>(nullptr, nullptr);
    cudaEventRecord(eH0, s2);

    // s0: KV chain (foldM fused into compgemm epilogue + small reduce)
    k_mask<<<1, 32>>>(mask);
    k_compgemm<<<dim3(Nn, 2, 8), 256>>>(kcomp, vcomp, wk, wv, lnkw, lnkb);
    k_foldSC<<<Nn*128/256, 256>>>();
    cudaStreamWaitEvent(0, eLn, 0);
    k_kvmma<<<NROWS/128, 256, 2*2*5120*2>>>();
    cudaStreamWaitEvent(0, eTd, 0);
    k_decomp<<<dim3(BTc/16, 2), 256>>>();
    cudaStreamWaitEvent(0, eH0, 0);
    k_flash<<<dim3(NT/2, Nn*Bb*Hh), 128, 5*64*FSTR*2>>>();
    k_hgemm<1><<<dim3(4, NROWS/128), 256>>>(x, out);
}

// round 15
// speedup vs baseline: 1.7559x; 1.4568x over previous
#include <cuda_runtime.h>
#include <cuda_bf16.h>
#include <cstdint>
#include <cstddef>

#define Nn 8
#define Bb 4
#define Tt 1024
#define Dd 512
#define Hh 4
#define HDc 128
#define Rr 64
#define QW 256                 // Hh * Rr
#define BTc (Bb*Tt)
#define NROWS (Nn*BTc)
#define EPSV 1e-5f
#define INV_SQRT_HD 0.08838834764831845f
#define L2E 1.4426950408889634f
#define FS2 72
#define NT (Tt/64)

// ---------------- device scratch ----------------
__device__ float g_mu[NROWS];
__device__ float g_rs[NROWS];
__device__ float g_maskf[Nn];
__device__ float g_invna;
__device__ __nv_bfloat16 g_xh[(size_t)NROWS*Dd];
__device__ __nv_bfloat16 g_Mbh[Nn*128*Dd];
__device__ float g_SMp[Nn*128*8];
__device__ float g_CMp[Nn*128*8];
__device__ float g_SM[Nn*128];
__device__ float g_CM[Nn*128];
__device__ __nv_bfloat16 g_kq[(size_t)NROWS*Rr];
__device__ __nv_bfloat16 g_vq[(size_t)NROWS*Rr];
__device__ __nv_bfloat16 g_Kc[(size_t)BTc*Rr];
__device__ __nv_bfloat16 g_Vc[(size_t)BTc*Rr];
__device__ __nv_bfloat16 g_Wqt[(size_t)Nn*QW*Dd];   // absorbed Q weights [n][hr][d]
__device__ __nv_bfloat16 g_Wot[(size_t)Nn*Dd*QW];   // absorbed O weights [n][o][hr]
__device__ float g_cq[Nn*Dd];
__device__ float g_SQp[Nn*QW*8];
__device__ float g_Sqt[Nn*QW];
__device__ float g_Cqt[Nn*QW];
__device__ __nv_bfloat16 g_Qh[(size_t)NROWS*QW];
__device__ __nv_bfloat16 g_AOh[(size_t)NROWS*QW];

// ---------------- helpers ----------------
__device__ __forceinline__ uint32_t pk2(float x, float y)
{
    __nv_bfloat162 h = __float22bfloat162_rn(make_float2(x, y));
    return *reinterpret_cast<uint32_t*>(&h);
}

__device__ __forceinline__ void ldsm4(uint32_t* r, const __nv_bfloat16* p)
{
    uint32_t a = (uint32_t)__cvta_generic_to_shared((void*)p);
    asm volatile("ldmatrix.sync.aligned.m8n8.x4.shared.b16 {%0,%1,%2,%3}, [%4];\n"
                 : "=r"(r[0]), "=r"(r[1]), "=r"(r[2]), "=r"(r[3]) : "r"(a));
}

__device__ __forceinline__ void ldsm4t(uint32_t* r, const __nv_bfloat16* p)
{
    uint32_t a = (uint32_t)__cvta_generic_to_shared((void*)p);
    asm volatile("ldmatrix.sync.aligned.m8n8.x4.trans.shared.b16 {%0,%1,%2,%3}, [%4];\n"
                 : "=r"(r[0]), "=r"(r[1]), "=r"(r[2]), "=r"(r[3]) : "r"(a));
}

__device__ __forceinline__ void mmabf(float* d, const uint32_t* a, uint32_t b0, uint32_t b1)
{
    asm volatile("mma.sync.aligned.m16n8k16.row.col.f32.bf16.bf16.f32 "
                 "{%0,%1,%2,%3},{%4,%5,%6,%7},{%8,%9},{%0,%1,%2,%3};\n"
                 : "+f"(d[0]), "+f"(d[1]), "+f"(d[2]), "+f"(d[3])
                 : "r"(a[0]), "r"(a[1]), "r"(a[2]), "r"(a[3]), "r"(b0), "r"(b1));
}

__device__ __forceinline__ void cpa16(const void* smem_dst, const void* gsrc)
{
    uint32_t ds = (uint32_t)__cvta_generic_to_shared((void*)smem_dst);
    asm volatile("cp.async.cg.shared.global [%0], [%1], 16;\n" :: "r"(ds), "l"(gsrc));
}
#define CPCOMMIT() asm volatile("cp.async.commit_group;\n" ::: "memory")
#define CPWAIT0()  asm volatile("cp.async.wait_group 0;\n" ::: "memory")

// ---------------- mask decode ----------------
__global__ void k_mask(const unsigned char* __restrict__ p)
{
    if (threadIdx.x == 0) {
        bool isF = (p[0]==0 && p[1]==0 && p[2]==0x80 && p[3]==0x3f);
        bool isI = (!isF && p[1]==0 && p[2]==0 && p[3]==0 && (p[4]!=0 || p[5]==0));
        float na = 0.f;
        for (int n = 0; n < Nn; n++) {
            bool bit;
            if (isF)      bit = (((const float*)p)[n] != 0.f);
            else if (isI) bit = (((const int*)p)[n]   != 0);
            else          bit = (p[n] != 0);
            g_maskf[n] = bit ? 1.f : 0.f;
            na += bit ? 1.f : 0.f;
        }
        g_invna = 1.f / fmaxf(na, 1.f);
    }
}

// ---------------- LN row stats + bf16 copy of x ----------------
__global__ __launch_bounds__(256) void k_lnstats(const float* __restrict__ x)
{
    int row  = blockIdx.x * 8 + (threadIdx.x >> 5);
    int lane = threadIdx.x & 31;
    const float4* xp = (const float4*)(x + (size_t)row * Dd);
    float s = 0.f, sq = 0.f;
    #pragma unroll
    for (int i = 0; i < 4; i++) {
        int j = lane + 32*i;
        float4 v = xp[j];
        s  += v.x + v.y + v.z + v.w;
        sq += v.x*v.x + v.y*v.y + v.z*v.z + v.w*v.w;
        uint2 uh = make_uint2(pk2(v.x, v.y), pk2(v.z, v.w));
        *(uint2*)(g_xh + (size_t)row*Dd + 4*j) = uh;
    }
    #pragma unroll
    for (int o = 16; o > 0; o >>= 1) {
        s  += __shfl_xor_sync(0xffffffffu, s,  o);
        sq += __shfl_xor_sync(0xffffffffu, sq, o);
    }
    if (lane == 0) {
        float mu  = s * (1.f / Dd);
        float var = sq * (1.f / Dd) - mu * mu;
        g_mu[row] = mu;
        g_rs[row] = rsqrtf(var + EPSV);
    }
}

// ------- M[n] = comp @ w, fused LN-fold -> bf16 Mbh + SM/CM partials -----------
__global__ __launch_bounds__(256) void k_compgemm(
    const float* __restrict__ kcomp, const float* __restrict__ vcomp,
    const float* __restrict__ wk,    const float* __restrict__ wv,
    const float* __restrict__ lnw,   const float* __restrict__ lnb)
{
    __shared__ float As[32*68];
    __shared__ float Bs[32*68];
    const int n    = blockIdx.x;
    const int half = blockIdx.y;
    const int i0   = blockIdx.z * 64;
    const float* comp = (half == 0 ? kcomp : vcomp) + (size_t)n * Rr * Dd;
    const float* w    = (half == 0 ? wk    : wv   ) + (size_t)n * Dd * Dd;
    const int tid = threadIdx.x, ty = tid >> 4, tx = tid & 15;
    const int arA = tid & 63, acA = (tid >> 6) * 8;
    const int arB = tid & 31, acB = (tid >> 5) * 8;

    float acc[4][4] = {};
    for (int k0 = 0; k0 < Dd; k0 += 32) {
        float4 a0 = *(const float4*)(comp + (size_t)arA*Dd + k0 + acA);
        float4 a1 = *(const float4*)(comp + (size_t)arA*Dd + k0 + acA + 4);
        float4 b0 = *(const float4*)(w + (size_t)(k0+arB)*Dd + i0 + acB);
        float4 b1 = *(const float4*)(w + (size_t)(k0+arB)*Dd + i0 + acB + 4);
        __syncthreads();
        As[(acA+0)*68+arA]=a0.x; As[(acA+1)*68+arA]=a0.y; As[(acA+2)*68+arA]=a0.z; As[(acA+3)*68+arA]=a0.w;
        As[(acA+4)*68+arA]=a1.x; As[(acA+5)*68+arA]=a1.y; As[(acA+6)*68+arA]=a1.z; As[(acA+7)*68+arA]=a1.w;
        *(float4*)&Bs[arB*68 + acB]     = b0;
        *(float4*)&Bs[arB*68 + acB + 4] = b1;
        __syncthreads();
        #pragma unroll
        for (int kk = 0; kk < 32; kk++) {
            float4 a  = *(const float4*)&As[kk*68 + ty*4];
            float4 bb = *(const float4*)&Bs[kk*68 + tx*4];
            float av[4] = {a.x,a.y,a.z,a.w};
            float bv[4] = {bb.x,bb.y,bb.z,bb.w};
            #pragma unroll
            for (int i = 0; i < 4; i++)
                #pragma unroll
                for (int j = 0; j < 4; j++)
                    acc[i][j] = fmaf(av[i], bv[j], acc[i][j]);
        }
    }

    const float* lw = lnw + n*Dd + i0 + tx*4;
    const float* lb = lnb + n*Dd + i0 + tx*4;
    float wv4[4], bv4[4];
    #pragma unroll
    for (int j = 0; j < 4; j++) { wv4[j] = lw[j]; bv4[j] = lb[j]; }

    #pragma unroll
    for (int i = 0; i < 4; i++) {
        int row = n*128 + half*64 + ty*4 + i;
        float p[4]; float smp = 0.f, cmp = 0.f;
        #pragma unroll
        for (int j = 0; j < 4; j++) {
            float m = acc[i][j];
            p[j] = wv4[j] * m;
            smp += p[j];
            cmp += bv4[j] * m;
        }
        *(uint2*)(g_Mbh + (size_t)row*Dd + i0 + tx*4) =
            make_uint2(pk2(p[0], p[1]), pk2(p[2], p[3]));
        #pragma unroll
        for (int o = 8; o > 0; o >>= 1) {
            smp += __shfl_xor_sync(0xffffffffu, smp, o);
            cmp += __shfl_xor_sync(0xffffffffu, cmp, o);
        }
        if (tx == 0) {
            g_SMp[row*8 + (i0 >> 6)] = smp;
            g_CMp[row*8 + (i0 >> 6)] = cmp;
        }
    }
}

// ---------------- reduce SM/CM partials ----------------
__global__ __launch_bounds__(256) void k_foldSC()
{
    int row = blockIdx.x * 256 + threadIdx.x;
    float s = 0.f, c = 0.f;
    #pragma unroll
    for (int j = 0; j < 8; j++) {
        s += g_SMp[row*8 + j];
        c += g_CMp[row*8 + j];
    }
    g_SM[row] = s;
    g_CM[row] = c;
}

// ---------------- cq[n,i] = sum_d lnqb[d] * wq[n,i,d] ----------------
__global__ __launch_bounds__(256) void k_cq(const float* __restrict__ lnqb,
                                            const float* __restrict__ wq)
{
    int row  = blockIdx.x * 8 + (threadIdx.x >> 5);   // 0..4095 = n*512+i
    int lane = threadIdx.x & 31;
    int n = row >> 9;
    const float* lb = lnqb + n*Dd;
    const float* wr = wq + (size_t)row * Dd;
    float cm = 0.f;
    for (int i = lane; i < Dd; i += 32) cm += lb[i] * wr[i];
    #pragma unroll
    for (int o = 16; o > 0; o >>= 1)
        cm += __shfl_xor_sync(0xffffffffu, cm, o);
    if (lane == 0) g_cq[row] = cm;
}

// ------- W~q[n][hr][d] = IS * sum_i kdec[h*128+i, r] * lnqw[d]*wq[n, h*128+i, d] --
__global__ __launch_bounds__(256) void k_wq(const float* __restrict__ wq,
                                            const float* __restrict__ lnqw,
                                            const float* __restrict__ kdec)
{
    __shared__ float As[32*68];   // [k=i][r]
    __shared__ float Bs[32*68];   // [k=i][d]
    const int n = blockIdx.x, h = blockIdx.y;
    const int d0g = blockIdx.z * 64;
    const int tid = threadIdx.x, ty = tid >> 4, tx = tid & 15;
    const int ri = tid >> 3, rc = (tid & 7) * 8;

    float lw[8];
    #pragma unroll
    for (int j = 0; j < 8; j++) lw[j] = lnqw[n*Dd + d0g + rc + j];

    float acc[4][4] = {};
    for (int k0 = 0; k0 < 128; k0 += 32) {
        const float* ap = kdec + (size_t)(h*128 + k0 + ri) * Rr + rc;
        const float* bp = wq + (size_t)n*Dd*Dd + (size_t)(h*128 + k0 + ri)*Dd + d0g + rc;
        float4 a0 = *(const float4*)(ap);
        float4 a1 = *(const float4*)(ap + 4);
        float4 b0 = *(const float4*)(bp);
        float4 b1 = *(const float4*)(bp + 4);
        __syncthreads();
        *(float4*)&As[ri*68 + rc]     = a0;
        *(float4*)&As[ri*68 + rc + 4] = a1;
        Bs[ri*68+rc+0]=b0.x*lw[0]; Bs[ri*68+rc+1]=b0.y*lw[1];
        Bs[ri*68+rc+2]=b0.z*lw[2]; Bs[ri*68+rc+3]=b0.w*lw[3];
        Bs[ri*68+rc+4]=b1.x*lw[4]; Bs[ri*68+rc+5]=b1.y*lw[5];
        Bs[ri*68+rc+6]=b1.z*lw[6]; Bs[ri*68+rc+7]=b1.w*lw[7];
        __syncthreads();
        #pragma unroll
        for (int kk = 0; kk < 32; kk++) {
            float4 a  = *(const float4*)&As[kk*68 + ty*4];
            float4 bb = *(const float4*)&Bs[kk*68 + tx*4];
            float av[4] = {a.x,a.y,a.z,a.w};
            float bv[4] = {bb.x,bb.y,bb.z,bb.w};
            #pragma unroll
            for (int i = 0; i < 4; i++)
                #pragma unroll
                for (int j = 0; j < 4; j++)
                    acc[i][j] = fmaf(av[i], bv[j], acc[i][j]);
        }
    }

    #pragma unroll
    for (int i = 0; i < 4; i++) {
        int hr = h*64 + ty*4 + i;
        float p[4]; float smp = 0.f;
        #pragma unroll
        for (int j = 0; j < 4; j++) { p[j] = INV_SQRT_HD * acc[i][j]; smp += p[j]; }
        *(uint2*)(g_Wqt + (size_t)n*QW*Dd + (size_t)hr*Dd + d0g + tx*4) =
            make_uint2(pk2(p[0], p[1]), pk2(p[2], p[3]));
        #pragma unroll
        for (int o = 8; o > 0; o >>= 1)
            smp += __shfl_xor_sync(0xffffffffu, smp, o);
        if (tx == 0) g_SQp[(n*QW + hr)*8 + (d0g >> 6)] = smp;
    }
}

// ---------------- S~q, C~q ----------------
__global__ __launch_bounds__(256) void k_wq2(const float* __restrict__ kdec)
{
    int g = blockIdx.x * 256 + threadIdx.x;   // 0..2047 = n*256+hr
    int n = g >> 8, hr = g & 255;
    int h = hr >> 6, r = hr & 63;
    float s = 0.f;
    #pragma unroll
    for (int j = 0; j < 8; j++) s += g_SQp[g*8 + j];
    g_Sqt[g] = s;
    float cc = 0.f;
    for (int i = 0; i < 128; i++)
        cc += kdec[(size_t)(h*128 + i)*Rr + r] * g_cq[n*Dd + h*128 + i];
    g_Cqt[g] = INV_SQRT_HD * cc;
}

// ------- W~o[n][o][hr] = sum_i wo[n, o, h*128+i] * vdec[h*128+i, r] -------------
__global__ __launch_bounds__(256) void k_wo(const float* __restrict__ wo,
                                            const float* __restrict__ vdec)
{
    __shared__ float As[32*68];   // [k=i][o]
    __shared__ float Bs[32*68];   // [k=i][r]
    const int n = blockIdx.x, h = blockIdx.y;
    const int o0 = blockIdx.z * 64;
    const int tid = threadIdx.x, ty = tid >> 4, tx = tid & 15;
    const int ao = tid >> 2, ic = (tid & 3) * 8;
    const int ri = tid >> 3, rc = (tid & 7) * 8;

    float acc[4][4] = {};
    for (int k0 = 0; k0 < 128; k0 += 32) {
        const float* ap = wo + (size_t)n*Dd*Dd + (size_t)(o0 + ao)*Dd + h*128 + k0 + ic;
        const float* bp = vdec + (size_t)(h*128 + k0 + ri)*Rr + rc;
        float4 a0 = *(const float4*)(ap);
        float4 a1 = *(const float4*)(ap + 4);
        float4 b0 = *(const float4*)(bp);
        float4 b1 = *(const float4*)(bp + 4);
        __syncthreads();
        As[(ic+0)*68+ao]=a0.x; As[(ic+1)*68+ao]=a0.y; As[(ic+2)*68+ao]=a0.z; As[(ic+3)*68+ao]=a0.w;
        As[(ic+4)*68+ao]=a1.x; As[(ic+5)*68+ao]=a1.y; As[(ic+6)*68+ao]=a1.z; As[(ic+7)*68+ao]=a1.w;
        *(float4*)&Bs[ri*68 + rc]     = b0;
        *(float4*)&Bs[ri*68 + rc + 4] = b1;
        __syncthreads();
        #pragma unroll
        for (int kk = 0; kk < 32; kk++) {
            float4 a  = *(const float4*)&As[kk*68 + ty*4];
            float4 bb = *(const float4*)&Bs[kk*68 + tx*4];
            float av[4] = {a.x,a.y,a.z,a.w};
            float bv[4] = {bb.x,bb.y,bb.z,bb.w};
            #pragma unroll
            for (int i = 0; i < 4; i++)
                #pragma unroll
                for (int j = 0; j < 4; j++)
                    acc[i][j] = fmaf(av[i], bv[j], acc[i][j]);
        }
    }

    #pragma unroll
    for (int i = 0; i < 4; i++) {
        int o = o0 + ty*4 + i;
        *(uint2*)(g_Wot + (size_t)n*Dd*QW + (size_t)o*QW + h*64 + tx*4) =
            make_uint2(pk2(acc[i][0], acc[i][1]), pk2(acc[i][2], acc[i][3]));
    }
}

// ------- kv-compress: single-term bf16 tensor cores (xh x Mh) + quant ----------
__global__ __launch_bounds__(256) void k_kvmma()
{
    extern __shared__ __nv_bfloat16 kvs[];
    const int m0 = blockIdx.x * 128;
    const int n  = m0 >> 12;
    const int tid = threadIdx.x, lane = tid & 31, warp = tid >> 5;
    const int wm = warp & 3, wn = warp >> 2;

    const __nv_bfloat16* srcs[2] = {
        g_xh + (size_t)m0*Dd,
        g_Mbh + (size_t)(n*128)*Dd };

    auto copyS = [&](int st, int k0) {
        __nv_bfloat16* base = kvs + (size_t)st*2*5120;
        #pragma unroll
        for (int op = 0; op < 2; op++) {
            #pragma unroll
            for (int i = 0; i < 2; i++) {
                int idx = tid + i*256;
                int r = idx >> 2, c = (idx & 3) * 8;
                cpa16(base + op*5120 + r*40 + c, srcs[op] + (size_t)r*Dd + k0 + c);
            }
        }
    };

    copyS(0, 0);
    CPCOMMIT();

    float acc[2][8][4];
    #pragma unroll
    for (int i = 0; i < 2; i++)
        #pragma unroll
        for (int j = 0; j < 8; j++)
            #pragma unroll
            for (int k = 0; k < 4; k++) acc[i][j][k] = 0.f;

    const int arow = wm*32 + (lane & 15);
    const int acol = ((lane >> 4) & 1) * 8;
    const int brow = wn*64 + (lane & 7) + ((lane >> 4) & 1) * 8;
    const int bcol = ((lane >> 3) & 1) * 8;

    for (int ks = 0; ks < 16; ks++) {
        int st = ks & 1;
        CPWAIT0();
        __syncthreads();
        if (ks < 15) { copyS(st ^ 1, (ks+1)*32); CPCOMMIT(); }

        const __nv_bfloat16* Ahs = kvs + (size_t)st*2*5120;
        const __nv_bfloat16* Bhs = Ahs + 5120;

        uint32_t ah[2][2][4];
        #pragma unroll
        for (int mf = 0; mf < 2; mf++)
            #pragma unroll
            for (int kf = 0; kf < 2; kf++)
                ldsm4(ah[mf][kf], Ahs + (arow + mf*16)*40 + kf*16 + acol);

        #pragma unroll
        for (int ng = 0; ng < 4; ng++) {
            uint32_t bh[2][4];
            #pragma unroll
            for (int kf = 0; kf < 2; kf++)
                ldsm4(bh[kf], Bhs + (brow + ng*16)*40 + kf*16 + bcol);
            #pragma unroll
            for (int s = 0; s < 2; s++) {
                int nf = ng*2 + s;
                #pragma unroll
                for (int mf = 0; mf < 2; mf++) {
                    mmabf(acc[mf][nf], ah[mf][0], bh[0][2*s], bh[0][2*s+1]);
                    mmabf(acc[mf][nf], ah[mf][1], bh[1][2*s], bh[1][2*s+1]);
                }
            }
        }
    }

    const float mfv = g_maskf[n];
    const int mrow = m0 + wm*32 + (lane >> 2);
    float smv[16], cmv[16];
    #pragma unroll
    for (int nf = 0; nf < 8; nf++) {
        int o = wn*64 + nf*8 + (lane & 3)*2;
        smv[2*nf]   = g_SM[n*128 + o];   smv[2*nf+1] = g_SM[n*128 + o + 1];
        cmv[2*nf]   = g_CM[n*128 + o];   cmv[2*nf+1] = g_CM[n*128 + o + 1];
    }
    __nv_bfloat16* dstb = (wn == 0) ? g_kq : g_vq;
    #pragma unroll
    for (int mf2 = 0; mf2 < 2; mf2++) {
        #pragma unroll
        for (int rr = 0; rr < 2; rr++) {
            int r = mrow + mf2*16 + rr*8;
            float rsv = g_rs[r], murs = g_mu[r]*rsv;
            float v[16]; float am = 0.f;
            #pragma unroll
            for (int nf = 0; nf < 8; nf++) {
                #pragma unroll
                for (int t = 0; t < 2; t++) {
                    float val = (rsv*acc[mf2][nf][2*rr+t] - murs*smv[2*nf+t] + cmv[2*nf+t]) * mfv;
                    v[2*nf+t] = val;
                    am = fmaxf(am, fabsf(val));
                }
            }
            am = fmaxf(am, __shfl_xor_sync(0xffffffffu, am, 1));
            am = fmaxf(am, __shfl_xor_sync(0xffffffffu, am, 2));
            am = fmaxf(am, 1e-8f);
            float scq = 127.f / am;
            float inv = am * (1.f / 127.f);
            #pragma unroll
            for (int nf = 0; nf < 8; nf++) {
                float q0 = rintf(v[2*nf]   * scq) * inv;
                float q1 = rintf(v[2*nf+1] * scq) * inv;
                *(uint32_t*)(dstb + (size_t)r*64 + nf*8 + (lane & 3)*2) = pk2(q0, q1);
            }
        }
    }
}

// ---------------- average over n -> compressed K/V [BT,64] bf16 -----------------
__global__ __launch_bounds__(256) void k_avg()
{
    int idx = blockIdx.x * 256 + threadIdx.x;   // BTc*64
    int bt = idx >> 6, r = idx & 63;
    float inv = g_invna;
    float sk = 0.f, sv = 0.f;
    #pragma unroll
    for (int n = 0; n < Nn; n++) {
        sk += __bfloat162float(g_kq[((size_t)(n*BTc + bt))*64 + r]);
        sv += __bfloat162float(g_vq[((size_t)(n*BTc + bt))*64 + r]);
    }
    g_Kc[idx] = __float2bfloat16(sk * inv);
    g_Vc[idx] = __float2bfloat16(sv * inv);
}

// ------- Q-projection: g_Qh = LN-epi( xh @ W~q^T ), out 256-wide ---------------
__global__ __launch_bounds__(256, 2) void k_qproj()
{
    __shared__ __nv_bfloat16 As[2][128*40];
    __shared__ __nv_bfloat16 Bs[2][128*40];
    const int m0 = blockIdx.y * 128;
    const int o0 = blockIdx.x * 128;
    const int n  = m0 >> 12;
    const __nv_bfloat16* A = g_xh;
    const __nv_bfloat16* B = g_Wqt + (size_t)n * QW * Dd;

    const int tid = threadIdx.x, lane = tid & 31, warp = tid >> 5;
    const int wm = warp & 3, wn = warp >> 2;

    auto copyAB = [&](int st, int k0) {
        #pragma unroll
        for (int i = 0; i < 2; i++) {
            int idx = tid + i*256;
            int r = idx >> 2, c = (idx & 3) * 8;
            cpa16(&As[st][r*40 + c], A + (size_t)(m0 + r)*Dd + k0 + c);
            cpa16(&Bs[st][r*40 + c], B + (size_t)(o0 + r)*Dd + k0 + c);
        }
    };

    copyAB(0, 0);
    CPCOMMIT();

    float acc[2][8][4];
    #pragma unroll
    for (int i = 0; i < 2; i++)
        #pragma unroll
        for (int j = 0; j < 8; j++)
            #pragma unroll
            for (int k = 0; k < 4; k++) acc[i][j][k] = 0.f;

    const int arow = wm*32 + (lane & 15);
    const int acol = ((lane >> 4) & 1) * 8;
    const int brow = wn*64 + (lane & 7) + ((lane >> 4) & 1) * 8;
    const int bcol = ((lane >> 3) & 1) * 8;

    for (int ks = 0; ks < 16; ks++) {
        int st = ks & 1;
        CPWAIT0();
        __syncthreads();
        if (ks < 15) { copyAB(st ^ 1, (ks+1)*32); CPCOMMIT(); }

        const __nv_bfloat16* Asb = As[st];
        const __nv_bfloat16* Bsb = Bs[st];

        uint32_t af[2][2][4];
        #pragma unroll
        for (int mf = 0; mf < 2; mf++)
            #pragma unroll
            for (int kf = 0; kf < 2; kf++)
                ldsm4(af[mf][kf], Asb + (arow + mf*16)*40 + kf*16 + acol);

        #pragma unroll
        for (int ng = 0; ng < 4; ng++) {
            uint32_t bfr[2][4];
            #pragma unroll
            for (int kf = 0; kf < 2; kf++)
                ldsm4(bfr[kf], Bsb + (brow + ng*16)*40 + kf*16 + bcol);
            #pragma unroll
            for (int s = 0; s < 2; s++) {
                int nf = ng*2 + s;
                #pragma unroll
                for (int mf = 0; mf < 2; mf++) {
                    mmabf(acc[mf][nf], af[mf][0], bfr[0][2*s], bfr[0][2*s+1]);
                    mmabf(acc[mf][nf], af[mf][1], bfr[1][2*s], bfr[1][2*s+1]);
                }
            }
        }
    }

    const int mrow = m0 + wm*32 + (lane >> 2);
    const int ocol = o0 + wn*64 + (lane & 3)*2;
    #pragma unroll
    for (int mf = 0; mf < 2; mf++) {
        int r0 = mrow + mf*16, r1 = r0 + 8;
        float rs0 = g_rs[r0], mr0 = g_mu[r0]*rs0;
        float rs1 = g_rs[r1], mr1 = g_mu[r1]*rs1;
        #pragma unroll
        for (int nf = 0; nf < 8; nf++) {
            int c = ocol + nf*8;
            float sq0 = g_Sqt[n*QW + c], sq1 = g_Sqt[n*QW + c + 1];
            float cq0 = g_Cqt[n*QW + c], cq1 = g_Cqt[n*QW + c + 1];
            float* d = acc[mf][nf];
            *(uint32_t*)(g_Qh + (size_t)r0*QW + c) =
                pk2(rs0*d[0] - mr0*sq0 + cq0, rs0*d[1] - mr0*sq1 + cq1);
            *(uint32_t*)(g_Qh + (size_t)r1*QW + c) =
                pk2(rs1*d[2] - mr1*sq0 + cq0, rs1*d[3] - mr1*sq1 + cq1);
        }
    }
}

// ------- O-projection: Out = X + mask * (AOh @ W~o^T), K=256 --------------------
__global__ __launch_bounds__(256, 2) void k_oproj(const float* __restrict__ X,
                                                  float* __restrict__ Out)
{
    __shared__ __nv_bfloat16 As[2][128*40];
    __shared__ __nv_bfloat16 Bs[2][128*40];
    const int m0 = blockIdx.y * 128;
    const int o0 = blockIdx.x * 128;
    const int n  = m0 >> 12;
    const __nv_bfloat16* A = g_AOh;
    const __nv_bfloat16* B = g_Wot + (size_t)n * Dd * QW;

    const int tid = threadIdx.x, lane = tid & 31, warp = tid >> 5;
    const int wm = warp & 3, wn = warp >> 2;

    auto copyAB = [&](int st, int k0) {
        #pragma unroll
        for (int i = 0; i < 2; i++) {
            int idx = tid + i*256;
            int r = idx >> 2, c = (idx & 3) * 8;
            cpa16(&As[st][r*40 + c], A + (size_t)(m0 + r)*QW + k0 + c);
            cpa16(&Bs[st][r*40 + c], B + (size_t)(o0 + r)*QW + k0 + c);
        }
    };

    copyAB(0, 0);
    CPCOMMIT();

    float acc[2][8][4];
    #pragma unroll
    for (int i = 0; i < 2; i++)
        #pragma unroll
        for (int j = 0; j < 8; j++)
            #pragma unroll
            for (int k = 0; k < 4; k++) acc[i][j][k] = 0.f;

    const int arow = wm*32 + (lane & 15);
    const int acol = ((lane >> 4) & 1) * 8;
    const int brow = wn*64 + (lane & 7) + ((lane >> 4) & 1) * 8;
    const int bcol = ((lane >> 3) & 1) * 8;

    for (int ks = 0; ks < 8; ks++) {
        int st = ks & 1;
        CPWAIT0();
        __syncthreads();
        if (ks < 7) { copyAB(st ^ 1, (ks+1)*32); CPCOMMIT(); }

        const __nv_bfloat16* Asb = As[st];
        const __nv_bfloat16* Bsb = Bs[st];

        uint32_t af[2][2][4];
        #pragma unroll
        for (int mf = 0; mf < 2; mf++)
            #pragma unroll
            for (int kf = 0; kf < 2; kf++)
                ldsm4(af[mf][kf], Asb + (arow + mf*16)*40 + kf*16 + acol);

        #pragma unroll
        for (int ng = 0; ng < 4; ng++) {
            uint32_t bfr[2][4];
            #pragma unroll
            for (int kf = 0; kf < 2; kf++)
                ldsm4(bfr[kf], Bsb + (brow + ng*16)*40 + kf*16 + bcol);
            #pragma unroll
            for (int s = 0; s < 2; s++) {
                int nf = ng*2 + s;
                #pragma unroll
                for (int mf = 0; mf < 2; mf++) {
                    mmabf(acc[mf][nf], af[mf][0], bfr[0][2*s], bfr[0][2*s+1]);
                    mmabf(acc[mf][nf], af[mf][1], bfr[1][2*s], bfr[1][2*s+1]);
                }
            }
        }
    }

    const int mrow = m0 + wm*32 + (lane >> 2);
    const int ocol = o0 + wn*64 + (lane & 3)*2;
    float mfv = g_maskf[n];
    #pragma unroll
    for (int mf = 0; mf < 2; mf++) {
        int r0 = mrow + mf*16, r1 = r0 + 8;
        #pragma unroll
        for (int nf = 0; nf < 8; nf++) {
            int c = ocol + nf*8;
            float* d = acc[mf][nf];
            float2 x0 = *(const float2*)(X + (size_t)r0*Dd + c);
            float2 x1 = *(const float2*)(X + (size_t)r1*Dd + c);
            *(float2*)(Out + (size_t)r0*Dd + c) =
                make_float2(x0.x + mfv*d[0], x0.y + mfv*d[1]);
            *(float2*)(Out + (size_t)r1*Dd + c) =
                make_float2(x1.x + mfv*d[2], x1.y + mfv*d[3]);
        }
    }
}

// -------- flash attention in compressed space: HD=64, K tile == V tile ----------
__global__ __launch_bounds__(128) void k_flash()
{
    extern __shared__ __nv_bfloat16 smb[];
    __nv_bfloat16* Qs = smb;                       // [64][FS2]
    __nv_bfloat16* KV = Qs + 64*FS2;               // 2 bufs x [64][FS2] (avg tile)
    const int nbh = blockIdx.y;
    const int n = nbh >> 4, b = (nbh >> 2) & 3, h = nbh & 3;
    const int tid = threadIdx.x, lane = tid & 31, warp = tid >> 5;

    const size_t kvbase = (size_t)b * Tt * Rr;
    const int r0q = warp*16 + (lane >> 2);
    const int c0q = (lane & 3) * 2;

    auto copyAV = [&](int buf, int k0) {
        __nv_bfloat16* Sb = KV + (size_t)buf * 64*FS2;
        #pragma unroll
        for (int i = 0; i < 4; i++) {
            int idx = tid + i*128;
            int r = idx >> 3, c = (idx & 7)*8;
            cpa16(&Sb[r*FS2 + c], g_Kc + kvbase + (size_t)(k0 + r)*Rr + c);
        }
    };
    auto copyV2 = [&](int buf, int k0) {
        // V == avg as well: reuse same tile. (g_Vc holds v-avg; K uses g_Kc)
        (void)buf; (void)k0;
    };
    (void)copyV2;

    #pragma unroll
    for (int phase = 0; phase < 2; phase++) {
        const int qt = phase ? (NT - 1 - (int)blockIdx.x) : (int)blockIdx.x;
        const int q0 = qt * 64;
        const size_t qbase = ((size_t)(n*Bb + b)*Tt + q0) * QW + h*Rr;

        if (phase) __syncthreads();

        #pragma unroll
        for (int i = 0; i < 4; i++) {
            int idx = tid + i*128;
            int r = idx >> 3, c = (idx & 7) * 8;
            cpa16(&Qs[r*FS2 + c], g_Qh + qbase + (size_t)r*QW + c);
        }
        CPCOMMIT();
        copyAV(0, 0);
        // V tile for k0=0
        {
            __nv_bfloat16* Vb = KV + (size_t)2 * 64*FS2;
            #pragma unroll
            for (int i = 0; i < 4; i++) {
                int idx = tid + i*128;
                int r = idx >> 3, c = (idx & 7)*8;
                cpa16(&Vb[r*FS2 + c], g_Vc + kvbase + (size_t)(0 + r)*Rr + c);
            }
        }
        CPCOMMIT();
        CPWAIT0();
        __syncthreads();

        uint32_t qf[4][4];
        {
            const __nv_bfloat16* qp = Qs + (warp*16 + (lane & 15))*FS2 + (lane >> 4)*8;
            #pragma unroll
            for (int kf = 0; kf < 4; kf++) ldsm4(qf[kf], qp + kf*16);
        }

        float accO[8][4];
        #pragma unroll
        for (int i = 0; i < 8; i++)
            #pragma unroll
            for (int j = 0; j < 4; j++) accO[i][j] = 0.f;
        float mrow[2] = {-1e30f, -1e30f};
        float lrow[2] = {0.f, 0.f};

        for (int kt = 0; kt <= qt; kt++) {
            if (kt > 0) { CPWAIT0(); __syncthreads(); }
            if (kt < qt) {
                const int nk = (kt+1)*64;
                __nv_bfloat16* Kb2 = KV + (size_t)((kt+1) & 1) * 64*FS2;
                __nv_bfloat16* Vb2 = KV + (size_t)(2 + ((kt+1) & 1)) * 64*FS2;
                #pragma unroll
                for (int i = 0; i < 4; i++) {
                    int idx = tid + i*128;
                    int r = idx >> 3, c = (idx & 7)*8;
                    cpa16(&Kb2[r*FS2 + c], g_Kc + kvbase + (size_t)(nk + r)*Rr + c);
                    cpa16(&Vb2[r*FS2 + c], g_Vc + kvbase + (size_t)(nk + r)*Rr + c);
                }
                CPCOMMIT();
            }

            const __nv_bfloat16* Kb = KV + (size_t)(kt & 1) * 64*FS2;
            const __nv_bfloat16* Vb = KV + (size_t)(2 + (kt & 1)) * 64*FS2;

            float sfr[8][4];
            #pragma unroll
            for (int i = 0; i < 8; i++)
                #pragma unroll
                for (int j = 0; j < 4; j++) sfr[i][j] = 0.f;

            {
                const __nv_bfloat16* kp = Kb + ((lane & 7) + ((lane >> 4) & 1)*8)*FS2
                                             + ((lane >> 3) & 1)*8;
                #pragma unroll
                for (int ng = 0; ng < 4; ng++) {
                    #pragma unroll
                    for (int kf = 0; kf < 4; kf++) {
                        uint32_t bf[4];
                        ldsm4(bf, kp + ng*16*FS2 + kf*16);
                        mmabf(sfr[2*ng],   qf[kf], bf[0], bf[1]);
                        mmabf(sfr[2*ng+1], qf[kf], bf[2], bf[3]);
                    }
                }
            }

            if (kt == qt) {
                #pragma unroll
                for (int j = 0; j < 8; j++) {
                    int cj = 8*j + c0q;
                    #pragma unroll
                    for (int rr = 0; rr < 2; rr++) {
                        int ri = r0q + 8*rr;
                        if (cj     > ri) sfr[j][2*rr]   = -1e30f;
                        if (cj + 1 > ri) sfr[j][2*rr+1] = -1e30f;
                    }
                }
            }

            #pragma unroll
            for (int rr = 0; rr < 2; rr++) {
                float tm = -1e30f;
                #pragma unroll
                for (int j = 0; j < 8; j++)
                    tm = fmaxf(tm, fmaxf(sfr[j][2*rr], sfr[j][2*rr+1]));
                tm = fmaxf(tm, __shfl_xor_sync(0xffffffffu, tm, 1));
                tm = fmaxf(tm, __shfl_xor_sync(0xffffffffu, tm, 2));
                float mnew = fmaxf(mrow[rr], tm);
                float scl = exp2f((mrow[rr] - mnew) * L2E);
                float ps = 0.f;
                #pragma unroll
                for (int j = 0; j < 8; j++) {
                    float e0 = exp2f((sfr[j][2*rr]   - mnew) * L2E);
                    float e1 = exp2f((sfr[j][2*rr+1] - mnew) * L2E);
                    sfr[j][2*rr] = e0; sfr[j][2*rr+1] = e1;
                    ps += e0 + e1;
                }
                ps += __shfl_xor_sync(0xffffffffu, ps, 1);
                ps += __shfl_xor_sync(0xffffffffu, ps, 2);
                lrow[rr] = lrow[rr]*scl + ps;
                mrow[rr] = mnew;
                #pragma unroll
                for (int nf = 0; nf < 8; nf++) {
                    accO[nf][2*rr]   *= scl;
                    accO[nf][2*rr+1] *= scl;
                }
            }

            uint32_t pa[4][4];
            #pragma unroll
            for (int kg = 0; kg < 4; kg++) {
                pa[kg][0] = pk2(sfr[2*kg][0],   sfr[2*kg][1]);
                pa[kg][1] = pk2(sfr[2*kg][2],   sfr[2*kg][3]);
                pa[kg][2] = pk2(sfr[2*kg+1][0], sfr[2*kg+1][1]);
                pa[kg][3] = pk2(sfr[2*kg+1][2], sfr[2*kg+1][3]);
            }

            {
                const __nv_bfloat16* vp = Vb + (lane & 15)*FS2 + (lane >> 4)*8;
                #pragma unroll
                for (int dg = 0; dg < 4; dg++) {
                    #pragma unroll
                    for (int kg = 0; kg < 4; kg++) {
                        uint32_t vb[4];
                        ldsm4t(vb, vp + kg*16*FS2 + dg*16);
                        mmabf(accO[2*dg],   pa[kg], vb[0], vb[1]);
                        mmabf(accO[2*dg+1], pa[kg], vb[2], vb[3]);
                    }
                }
            }
        }

        #pragma unroll
        for (int rr = 0; rr < 2; rr++) {
            float inv = 1.f / lrow[rr];
            size_t row = (size_t)(n*Bb + b)*Tt + q0 + r0q + 8*rr;
            __nv_bfloat16* dst = g_AOh + row*QW + h*Rr;
            #pragma unroll
            for (int nf = 0; nf < 8; nf++) {
                *(uint32_t*)(dst + 8*nf + c0q) =
                    pk2(accO[nf][2*rr]*inv, accO[nf][2*rr+1]*inv);
            }
        }
    }
}

// ---------------- launch ----------------
extern "C" void kernel_launch(void* const* d_in, const int* in_sizes, int n_in,
                              void* d_out, int out_size)
{
    (void)in_sizes; (void)n_in; (void)out_size;
    const float* x     = (const float*)d_in[0];
    const unsigned char* mask = (const unsigned char*)d_in[1];
    const float* lnkw  = (const float*)d_in[2];
    const float* lnkb  = (const float*)d_in[3];
    const float* lnqw  = (const float*)d_in[4];
    const float* lnqb  = (const float*)d_in[5];
    const float* wk    = (const float*)d_in[6];
    const float* wv    = (const float*)d_in[7];
    const float* wq    = (const float*)d_in[8];
    const float* wo    = (const float*)d_in[9];
    const float* kcomp = (const float*)d_in[10];
    const float* vcomp = (const float*)d_in[11];
    const float* kdec  = (const float*)d_in[12];
    const float* vdec  = (const float*)d_in[13];
    float* out = (float*)d_out;

    static cudaStream_t s1 = nullptr, s2 = nullptr;
    static cudaEvent_t eRoot, eLn, eWo, eH0;
    static bool init_done = false;
    if (!init_done) {
        cudaStreamCreateWithFlags(&s1, cudaStreamNonBlocking);
        cudaStreamCreateWithFlags(&s2, cudaStreamNonBlocking);
        cudaEventCreateWithFlags(&eRoot, cudaEventDisableTiming);
        cudaEventCreateWithFlags(&eLn,   cudaEventDisableTiming);
        cudaEventCreateWithFlags(&eWo,   cudaEventDisableTiming);
        cudaEventCreateWithFlags(&eH0,   cudaEventDisableTiming);
        cudaFuncSetAttribute(k_flash, cudaFuncAttributeMaxDynamicSharedMemorySize,
                             5*64*FS2*2);
        cudaFuncSetAttribute(k_kvmma, cudaFuncAttributeMaxDynamicSharedMemorySize,
                             2*2*5120*2);
        init_done = true;
    }

    // fork
    cudaEventRecord(eRoot, 0);
    cudaStreamWaitEvent(s1, eRoot, 0);
    cudaStreamWaitEvent(s2, eRoot, 0);

    // s1: mask + LN stats (+ bf16 x), then absorbed O weights
    k_mask<<<1, 32, 0, s1>>>(mask);
    k_lnstats<<<NROWS/8, 256, 0, s1>>>(x);
    cudaEventRecord(eLn, s1);
    k_wo<<<dim3(Nn, Hh, 8), 256, 0, s1>>>(wo, vdec);
    cudaEventRecord(eWo, s1);

    // s2: absorbed Q weights + Q projection
    k_cq<<<Nn*Dd/8, 256, 0, s2>>>(lnqb, wq);
    k_wq<<<dim3(Nn, Hh, 8), 256, 0, s2>>>(wq, lnqw, kdec);
    k_wq2<<<Nn*QW/256, 256, 0, s2>>>(kdec);
    cudaStreamWaitEvent(s2, eLn, 0);
    k_qproj<<<dim3(2, NROWS/128), 256, 0, s2>>>();
    cudaEventRecord(eH0, s2);

    // s0: KV chain
    k_compgemm<<<dim3(Nn, 2, 8), 256>>>(kcomp, vcomp, wk, wv, lnkw, lnkb);
    k_foldSC<<<Nn*128/256, 256>>>();
    cudaStreamWaitEvent(0, eLn, 0);
    k_kvmma<<<NROWS/128, 256, 2*2*5120*2>>>();
    k_avg<<<BTc*Rr/256, 256>>>();
    cudaStreamWaitEvent(0, eH0, 0);
    k_flash<<<dim3(NT/2, Nn*Bb*Hh), 128, 5*64*FS2*2>>>();
    cudaStreamWaitEvent(0, eWo, 0);
    k_oproj<<<dim3(4, NROWS/128), 256>>>(x, out);
}

// round 16
// speedup vs baseline: 1.8852x; 1.0736x over previous
#include <cuda_runtime.h>
#include <cuda_bf16.h>
#include <cstdint>
#include <cstddef>

#define Nn 8
#define Bb 4
#define Tt 1024
#define Dd 512
#define Hh 4
#define HDc 128
#define Rr 64
#define QW 256
#define BTc (Bb*Tt)
#define NROWS (Nn*BTc)
#define EPSV 1e-5f
#define INV_SQRT_HD 0.08838834764831845f
#define L2E 1.4426950408889634f
#define FS2 72
#define NT (Tt/64)

// ---------------- device scratch ----------------
__device__ float g_mu[NROWS];
__device__ float g_rs[NROWS];
__device__ float g_maskf[Nn];
__device__ float g_invna;
__device__ __nv_bfloat16 g_xh[(size_t)NROWS*Dd];
__device__ __nv_bfloat16 g_Mbh[Nn*128*Dd];
__device__ float g_SMp[Nn*128*8];
__device__ float g_CMp[Nn*128*8];
__device__ float g_SM[Nn*128];
__device__ float g_CM[Nn*128];
__device__ __nv_bfloat16 g_kq[(size_t)NROWS*Rr];
__device__ __nv_bfloat16 g_vq[(size_t)NROWS*Rr];
__device__ __nv_bfloat16 g_Kc[(size_t)BTc*Rr];
__device__ __nv_bfloat16 g_Vc[(size_t)BTc*Rr];
__device__ __nv_bfloat16 g_Wqt[(size_t)Nn*QW*Dd];
__device__ __nv_bfloat16 g_Wot[(size_t)Nn*Dd*QW];
__device__ float g_cq[Nn*Dd];
__device__ float g_SQp[Nn*QW*8];
__device__ float g_Sqt[Nn*QW];
__device__ float g_Cqt[Nn*QW];
__device__ __nv_bfloat16 g_Qh[(size_t)NROWS*QW];
__device__ __nv_bfloat16 g_AOh[(size_t)NROWS*QW];

// ---------------- helpers ----------------
__device__ __forceinline__ uint32_t pk2(float x, float y)
{
    __nv_bfloat162 h = __float22bfloat162_rn(make_float2(x, y));
    return *reinterpret_cast<uint32_t*>(&h);
}

__device__ __forceinline__ void ldsm4(uint32_t* r, const __nv_bfloat16* p)
{
    uint32_t a = (uint32_t)__cvta_generic_to_shared((void*)p);
    asm volatile("ldmatrix.sync.aligned.m8n8.x4.shared.b16 {%0,%1,%2,%3}, [%4];\n"
                 : "=r"(r[0]), "=r"(r[1]), "=r"(r[2]), "=r"(r[3]) : "r"(a));
}

__device__ __forceinline__ void ldsm4t(uint32_t* r, const __nv_bfloat16* p)
{
    uint32_t a = (uint32_t)__cvta_generic_to_shared((void*)p);
    asm volatile("ldmatrix.sync.aligned.m8n8.x4.trans.shared.b16 {%0,%1,%2,%3}, [%4];\n"
                 : "=r"(r[0]), "=r"(r[1]), "=r"(r[2]), "=r"(r[3]) : "r"(a));
}

__device__ __forceinline__ void mmabf(float* d, const uint32_t* a, uint32_t b0, uint32_t b1)
{
    asm volatile("mma.sync.aligned.m16n8k16.row.col.f32.bf16.bf16.f32 "
                 "{%0,%1,%2,%3},{%4,%5,%6,%7},{%8,%9},{%0,%1,%2,%3};\n"
                 : "+f"(d[0]), "+f"(d[1]), "+f"(d[2]), "+f"(d[3])
                 : "r"(a[0]), "r"(a[1]), "r"(a[2]), "r"(a[3]), "r"(b0), "r"(b1));
}

__device__ __forceinline__ void cpa16(const void* smem_dst, const void* gsrc)
{
    uint32_t ds = (uint32_t)__cvta_generic_to_shared((void*)smem_dst);
    asm volatile("cp.async.cg.shared.global [%0], [%1], 16;\n" :: "r"(ds), "l"(gsrc));
}
#define CPCOMMIT() asm volatile("cp.async.commit_group;\n" ::: "memory")
#define CPWAIT0()  asm volatile("cp.async.wait_group 0;\n" ::: "memory")

// ---------------- mask decode ----------------
__global__ void k_mask(const unsigned char* __restrict__ p)
{
    if (threadIdx.x == 0) {
        bool isF = (p[0]==0 && p[1]==0 && p[2]==0x80 && p[3]==0x3f);
        bool isI = (!isF && p[1]==0 && p[2]==0 && p[3]==0 && (p[4]!=0 || p[5]==0));
        float na = 0.f;
        for (int n = 0; n < Nn; n++) {
            bool bit;
            if (isF)      bit = (((const float*)p)[n] != 0.f);
            else if (isI) bit = (((const int*)p)[n]   != 0);
            else          bit = (p[n] != 0);
            g_maskf[n] = bit ? 1.f : 0.f;
            na += bit ? 1.f : 0.f;
        }
        g_invna = 1.f / fmaxf(na, 1.f);
    }
}

// ---------------- LN row stats + bf16 copy of x ----------------
__global__ __launch_bounds__(256) void k_lnstats(const float* __restrict__ x)
{
    int row  = blockIdx.x * 8 + (threadIdx.x >> 5);
    int lane = threadIdx.x & 31;
    const float4* xp = (const float4*)(x + (size_t)row * Dd);
    float s = 0.f, sq = 0.f;
    #pragma unroll
    for (int i = 0; i < 4; i++) {
        int j = lane + 32*i;
        float4 v = xp[j];
        s  += v.x + v.y + v.z + v.w;
        sq += v.x*v.x + v.y*v.y + v.z*v.z + v.w*v.w;
        uint2 uh = make_uint2(pk2(v.x, v.y), pk2(v.z, v.w));
        *(uint2*)(g_xh + (size_t)row*Dd + 4*j) = uh;
    }
    #pragma unroll
    for (int o = 16; o > 0; o >>= 1) {
        s  += __shfl_xor_sync(0xffffffffu, s,  o);
        sq += __shfl_xor_sync(0xffffffffu, sq, o);
    }
    if (lane == 0) {
        float mu  = s * (1.f / Dd);
        float var = sq * (1.f / Dd) - mu * mu;
        g_mu[row] = mu;
        g_rs[row] = rsqrtf(var + EPSV);
    }
}

// ------- M[n] = comp @ w, fused LN-fold -> bf16 Mbh + SM/CM partials -----------
__global__ __launch_bounds__(256) void k_compgemm(
    const float* __restrict__ kcomp, const float* __restrict__ vcomp,
    const float* __restrict__ wk,    const float* __restrict__ wv,
    const float* __restrict__ lnw,   const float* __restrict__ lnb)
{
    __shared__ float As[32*68];
    __shared__ float Bs[32*68];
    const int n    = blockIdx.x;
    const int half = blockIdx.y;
    const int i0   = blockIdx.z * 64;
    const float* comp = (half == 0 ? kcomp : vcomp) + (size_t)n * Rr * Dd;
    const float* w    = (half == 0 ? wk    : wv   ) + (size_t)n * Dd * Dd;
    const int tid = threadIdx.x, ty = tid >> 4, tx = tid & 15;
    const int arA = tid & 63, acA = (tid >> 6) * 8;
    const int arB = tid & 31, acB = (tid >> 5) * 8;

    float acc[4][4] = {};
    for (int k0 = 0; k0 < Dd; k0 += 32) {
        float4 a0 = *(const float4*)(comp + (size_t)arA*Dd + k0 + acA);
        float4 a1 = *(const float4*)(comp + (size_t)arA*Dd + k0 + acA + 4);
        float4 b0 = *(const float4*)(w + (size_t)(k0+arB)*Dd + i0 + acB);
        float4 b1 = *(const float4*)(w + (size_t)(k0+arB)*Dd + i0 + acB + 4);
        __syncthreads();
        As[(acA+0)*68+arA]=a0.x; As[(acA+1)*68+arA]=a0.y; As[(acA+2)*68+arA]=a0.z; As[(acA+3)*68+arA]=a0.w;
        As[(acA+4)*68+arA]=a1.x; As[(acA+5)*68+arA]=a1.y; As[(acA+6)*68+arA]=a1.z; As[(acA+7)*68+arA]=a1.w;
        *(float4*)&Bs[arB*68 + acB]     = b0;
        *(float4*)&Bs[arB*68 + acB + 4] = b1;
        __syncthreads();
        #pragma unroll
        for (int kk = 0; kk < 32; kk++) {
            float4 a  = *(const float4*)&As[kk*68 + ty*4];
            float4 bb = *(const float4*)&Bs[kk*68 + tx*4];
            float av[4] = {a.x,a.y,a.z,a.w};
            float bv[4] = {bb.x,bb.y,bb.z,bb.w};
            #pragma unroll
            for (int i = 0; i < 4; i++)
                #pragma unroll
                for (int j = 0; j < 4; j++)
                    acc[i][j] = fmaf(av[i], bv[j], acc[i][j]);
        }
    }

    const float* lw = lnw + n*Dd + i0 + tx*4;
    const float* lb = lnb + n*Dd + i0 + tx*4;
    float wv4[4], bv4[4];
    #pragma unroll
    for (int j = 0; j < 4; j++) { wv4[j] = lw[j]; bv4[j] = lb[j]; }

    #pragma unroll
    for (int i = 0; i < 4; i++) {
        int row = n*128 + half*64 + ty*4 + i;
        float p[4]; float smp = 0.f, cmp = 0.f;
        #pragma unroll
        for (int j = 0; j < 4; j++) {
            float m = acc[i][j];
            p[j] = wv4[j] * m;
            smp += p[j];
            cmp += bv4[j] * m;
        }
        *(uint2*)(g_Mbh + (size_t)row*Dd + i0 + tx*4) =
            make_uint2(pk2(p[0], p[1]), pk2(p[2], p[3]));
        #pragma unroll
        for (int o = 8; o > 0; o >>= 1) {
            smp += __shfl_xor_sync(0xffffffffu, smp, o);
            cmp += __shfl_xor_sync(0xffffffffu, cmp, o);
        }
        if (tx == 0) {
            g_SMp[row*8 + (i0 >> 6)] = smp;
            g_CMp[row*8 + (i0 >> 6)] = cmp;
        }
    }
}

// ---------------- reduce SM/CM partials ----------------
__global__ __launch_bounds__(256) void k_foldSC()
{
    int row = blockIdx.x * 256 + threadIdx.x;
    float s = 0.f, c = 0.f;
    #pragma unroll
    for (int j = 0; j < 8; j++) {
        s += g_SMp[row*8 + j];
        c += g_CMp[row*8 + j];
    }
    g_SM[row] = s;
    g_CM[row] = c;
}

// ---------------- cq[n,i] = sum_d lnqb[d] * wq[n,i,d] ----------------
__global__ __launch_bounds__(256) void k_cq(const float* __restrict__ lnqb,
                                            const float* __restrict__ wq)
{
    int row  = blockIdx.x * 8 + (threadIdx.x >> 5);
    int lane = threadIdx.x & 31;
    int n = row >> 9;
    const float* lb = lnqb + n*Dd;
    const float* wr = wq + (size_t)row * Dd;
    float cm = 0.f;
    for (int i = lane; i < Dd; i += 32) cm += lb[i] * wr[i];
    #pragma unroll
    for (int o = 16; o > 0; o >>= 1)
        cm += __shfl_xor_sync(0xffffffffu, cm, o);
    if (lane == 0) g_cq[row] = cm;
}

// ------- W~q[n][hr][d] = IS * sum_i kdec[h*128+i, r] * lnqw[d]*wq[n, h*128+i, d] --
__global__ __launch_bounds__(256) void k_wq(const float* __restrict__ wq,
                                            const float* __restrict__ lnqw,
                                            const float* __restrict__ kdec)
{
    __shared__ float As[32*68];
    __shared__ float Bs[32*68];
    const int n = blockIdx.x, h = blockIdx.y;
    const int d0g = blockIdx.z * 64;
    const int tid = threadIdx.x, ty = tid >> 4, tx = tid & 15;
    const int ri = tid >> 3, rc = (tid & 7) * 8;

    float lw[8];
    #pragma unroll
    for (int j = 0; j < 8; j++) lw[j] = lnqw[n*Dd + d0g + rc + j];

    float acc[4][4] = {};
    for (int k0 = 0; k0 < 128; k0 += 32) {
        const float* ap = kdec + (size_t)(h*128 + k0 + ri) * Rr + rc;
        const float* bp = wq + (size_t)n*Dd*Dd + (size_t)(h*128 + k0 + ri)*Dd + d0g + rc;
        float4 a0 = *(const float4*)(ap);
        float4 a1 = *(const float4*)(ap + 4);
        float4 b0 = *(const float4*)(bp);
        float4 b1 = *(const float4*)(bp + 4);
        __syncthreads();
        *(float4*)&As[ri*68 + rc]     = a0;
        *(float4*)&As[ri*68 + rc + 4] = a1;
        Bs[ri*68+rc+0]=b0.x*lw[0]; Bs[ri*68+rc+1]=b0.y*lw[1];
        Bs[ri*68+rc+2]=b0.z*lw[2]; Bs[ri*68+rc+3]=b0.w*lw[3];
        Bs[ri*68+rc+4]=b1.x*lw[4]; Bs[ri*68+rc+5]=b1.y*lw[5];
        Bs[ri*68+rc+6]=b1.z*lw[6]; Bs[ri*68+rc+7]=b1.w*lw[7];
        __syncthreads();
        #pragma unroll
        for (int kk = 0; kk < 32; kk++) {
            float4 a  = *(const float4*)&As[kk*68 + ty*4];
            float4 bb = *(const float4*)&Bs[kk*68 + tx*4];
            float av[4] = {a.x,a.y,a.z,a.w};
            float bv[4] = {bb.x,bb.y,bb.z,bb.w};
            #pragma unroll
            for (int i = 0; i < 4; i++)
                #pragma unroll
                for (int j = 0; j < 4; j++)
                    acc[i][j] = fmaf(av[i], bv[j], acc[i][j]);
        }
    }

    #pragma unroll
    for (int i = 0; i < 4; i++) {
        int hr = h*64 + ty*4 + i;
        float p[4]; float smp = 0.f;
        #pragma unroll
        for (int j = 0; j < 4; j++) { p[j] = INV_SQRT_HD * acc[i][j]; smp += p[j]; }
        *(uint2*)(g_Wqt + (size_t)n*QW*Dd + (size_t)hr*Dd + d0g + tx*4) =
            make_uint2(pk2(p[0], p[1]), pk2(p[2], p[3]));
        #pragma unroll
        for (int o = 8; o > 0; o >>= 1)
            smp += __shfl_xor_sync(0xffffffffu, smp, o);
        if (tx == 0) g_SQp[(n*QW + hr)*8 + (d0g >> 6)] = smp;
    }
}

// ---------------- S~q, C~q ----------------
__global__ __launch_bounds__(256) void k_wq2(const float* __restrict__ kdec)
{
    int g = blockIdx.x * 256 + threadIdx.x;
    int n = g >> 8, hr = g & 255;
    int h = hr >> 6, r = hr & 63;
    float s = 0.f;
    #pragma unroll
    for (int j = 0; j < 8; j++) s += g_SQp[g*8 + j];
    g_Sqt[g] = s;
    float cc = 0.f;
    for (int i = 0; i < 128; i++)
        cc += kdec[(size_t)(h*128 + i)*Rr + r] * g_cq[n*Dd + h*128 + i];
    g_Cqt[g] = INV_SQRT_HD * cc;
}

// ------- W~o[n][o][hr] = sum_i wo[n, o, h*128+i] * vdec[h*128+i, r] -------------
__global__ __launch_bounds__(256) void k_wo(const float* __restrict__ wo,
                                            const float* __restrict__ vdec)
{
    __shared__ float As[32*68];
    __shared__ float Bs[32*68];
    const int n = blockIdx.x, h = blockIdx.y;
    const int o0 = blockIdx.z * 64;
    const int tid = threadIdx.x, ty = tid >> 4, tx = tid & 15;
    const int ao = tid >> 2, ic = (tid & 3) * 8;
    const int ri = tid >> 3, rc = (tid & 7) * 8;

    float acc[4][4] = {};
    for (int k0 = 0; k0 < 128; k0 += 32) {
        const float* ap = wo + (size_t)n*Dd*Dd + (size_t)(o0 + ao)*Dd + h*128 + k0 + ic;
        const float* bp = vdec + (size_t)(h*128 + k0 + ri)*Rr + rc;
        float4 a0 = *(const float4*)(ap);
        float4 a1 = *(const float4*)(ap + 4);
        float4 b0 = *(const float4*)(bp);
        float4 b1 = *(const float4*)(bp + 4);
        __syncthreads();
        As[(ic+0)*68+ao]=a0.x; As[(ic+1)*68+ao]=a0.y; As[(ic+2)*68+ao]=a0.z; As[(ic+3)*68+ao]=a0.w;
        As[(ic+4)*68+ao]=a1.x; As[(ic+5)*68+ao]=a1.y; As[(ic+6)*68+ao]=a1.z; As[(ic+7)*68+ao]=a1.w;
        *(float4*)&Bs[ri*68 + rc]     = b0;
        *(float4*)&Bs[ri*68 + rc + 4] = b1;
        __syncthreads();
        #pragma unroll
        for (int kk = 0; kk < 32; kk++) {
            float4 a  = *(const float4*)&As[kk*68 + ty*4];
            float4 bb = *(const float4*)&Bs[kk*68 + tx*4];
            float av[4] = {a.x,a.y,a.z,a.w};
            float bv[4] = {bb.x,bb.y,bb.z,bb.w};
            #pragma unroll
            for (int i = 0; i < 4; i++)
                #pragma unroll
                for (int j = 0; j < 4; j++)
                    acc[i][j] = fmaf(av[i], bv[j], acc[i][j]);
        }
    }

    #pragma unroll
    for (int i = 0; i < 4; i++) {
        int o = o0 + ty*4 + i;
        *(uint2*)(g_Wot + (size_t)n*Dd*QW + (size_t)o*QW + h*64 + tx*4) =
            make_uint2(pk2(acc[i][0], acc[i][1]), pk2(acc[i][2], acc[i][3]));
    }
}

// ------- kv-compress: single-term bf16 tensor cores (xh x Mh) + quant ----------
__global__ __launch_bounds__(256, 2) void k_kvmma()
{
    extern __shared__ __nv_bfloat16 kvs[];
    const int m0 = blockIdx.x * 128;
    const int n  = m0 >> 12;
    const int tid = threadIdx.x, lane = tid & 31, warp = tid >> 5;
    const int wm = warp & 3, wn = warp >> 2;

    const __nv_bfloat16* srcs[2] = {
        g_xh + (size_t)m0*Dd,
        g_Mbh + (size_t)(n*128)*Dd };

    auto copyS = [&](int st, int k0) {
        __nv_bfloat16* base = kvs + (size_t)st*2*5120;
        #pragma unroll
        for (int op = 0; op < 2; op++) {
            #pragma unroll
            for (int i = 0; i < 2; i++) {
                int idx = tid + i*256;
                int r = idx >> 2, c = (idx & 3) * 8;
                cpa16(base + op*5120 + r*40 + c, srcs[op] + (size_t)r*Dd + k0 + c);
            }
        }
    };

    copyS(0, 0);
    CPCOMMIT();

    float acc[2][8][4];
    #pragma unroll
    for (int i = 0; i < 2; i++)
        #pragma unroll
        for (int j = 0; j < 8; j++)
            #pragma unroll
            for (int k = 0; k < 4; k++) acc[i][j][k] = 0.f;

    const int arow = wm*32 + (lane & 15);
    const int acol = ((lane >> 4) & 1) * 8;
    const int brow = wn*64 + (lane & 7) + ((lane >> 4) & 1) * 8;
    const int bcol = ((lane >> 3) & 1) * 8;

    for (int ks = 0; ks < 16; ks++) {
        int st = ks & 1;
        CPWAIT0();
        __syncthreads();
        if (ks < 15) { copyS(st ^ 1, (ks+1)*32); CPCOMMIT(); }

        const __nv_bfloat16* Ahs = kvs + (size_t)st*2*5120;
        const __nv_bfloat16* Bhs = Ahs + 5120;

        uint32_t ah[2][2][4];
        #pragma unroll
        for (int mf = 0; mf < 2; mf++)
            #pragma unroll
            for (int kf = 0; kf < 2; kf++)
                ldsm4(ah[mf][kf], Ahs + (arow + mf*16)*40 + kf*16 + acol);

        #pragma unroll
        for (int ng = 0; ng < 4; ng++) {
            uint32_t bh[2][4];
            #pragma unroll
            for (int kf = 0; kf < 2; kf++)
                ldsm4(bh[kf], Bhs + (brow + ng*16)*40 + kf*16 + bcol);
            #pragma unroll
            for (int s = 0; s < 2; s++) {
                int nf = ng*2 + s;
                #pragma unroll
                for (int mf = 0; mf < 2; mf++) {
                    mmabf(acc[mf][nf], ah[mf][0], bh[0][2*s], bh[0][2*s+1]);
                    mmabf(acc[mf][nf], ah[mf][1], bh[1][2*s], bh[1][2*s+1]);
                }
            }
        }
    }

    const float mfv = g_maskf[n];
    const int mrow = m0 + wm*32 + (lane >> 2);
    float smv[16], cmv[16];
    #pragma unroll
    for (int nf = 0; nf < 8; nf++) {
        int o = wn*64 + nf*8 + (lane & 3)*2;
        smv[2*nf]   = g_SM[n*128 + o];   smv[2*nf+1] = g_SM[n*128 + o + 1];
        cmv[2*nf]   = g_CM[n*128 + o];   cmv[2*nf+1] = g_CM[n*128 + o + 1];
    }
    __nv_bfloat16* dstb = (wn == 0) ? g_kq : g_vq;
    #pragma unroll
    for (int mf2 = 0; mf2 < 2; mf2++) {
        #pragma unroll
        for (int rr = 0; rr < 2; rr++) {
            int r = mrow + mf2*16 + rr*8;
            float rsv = g_rs[r], murs = g_mu[r]*rsv;
            float v[16]; float am = 0.f;
            #pragma unroll
            for (int nf = 0; nf < 8; nf++) {
                #pragma unroll
                for (int t = 0; t < 2; t++) {
                    float val = (rsv*acc[mf2][nf][2*rr+t] - murs*smv[2*nf+t] + cmv[2*nf+t]) * mfv;
                    v[2*nf+t] = val;
                    am = fmaxf(am, fabsf(val));
                }
            }
            am = fmaxf(am, __shfl_xor_sync(0xffffffffu, am, 1));
            am = fmaxf(am, __shfl_xor_sync(0xffffffffu, am, 2));
            am = fmaxf(am, 1e-8f);
            float scq = 127.f / am;
            float inv = am * (1.f / 127.f);
            #pragma unroll
            for (int nf = 0; nf < 8; nf++) {
                float q0 = rintf(v[2*nf]   * scq) * inv;
                float q1 = rintf(v[2*nf+1] * scq) * inv;
                *(uint32_t*)(dstb + (size_t)r*64 + nf*8 + (lane & 3)*2) = pk2(q0, q1);
            }
        }
    }
}

// ------- average over n -> compressed K/V [BT,64] bf16, vectorized -------------
__global__ __launch_bounds__(256) void k_avg()
{
    int idx = blockIdx.x * 256 + threadIdx.x;   // BTc*Rr/8 = 32768
    int bt = idx >> 3, c = (idx & 7) * 8;
    float inv = g_invna;
    float sk[8] = {0,0,0,0,0,0,0,0}, sv[8] = {0,0,0,0,0,0,0,0};
    #pragma unroll
    for (int n = 0; n < Nn; n++) {
        uint4 uk = *(const uint4*)(g_kq + ((size_t)(n*BTc + bt))*64 + c);
        uint4 uv = *(const uint4*)(g_vq + ((size_t)(n*BTc + bt))*64 + c);
        const __nv_bfloat162* pk = (const __nv_bfloat162*)&uk;
        const __nv_bfloat162* pv = (const __nv_bfloat162*)&uv;
        #pragma unroll
        for (int j = 0; j < 4; j++) {
            float2 fk = __bfloat1622float2(pk[j]);
            float2 fv = __bfloat1622float2(pv[j]);
            sk[2*j]   += fk.x; sk[2*j+1] += fk.y;
            sv[2*j]   += fv.x; sv[2*j+1] += fv.y;
        }
    }
    uint4 ok, ov;
    ok.x = pk2(sk[0]*inv, sk[1]*inv); ok.y = pk2(sk[2]*inv, sk[3]*inv);
    ok.z = pk2(sk[4]*inv, sk[5]*inv); ok.w = pk2(sk[6]*inv, sk[7]*inv);
    ov.x = pk2(sv[0]*inv, sv[1]*inv); ov.y = pk2(sv[2]*inv, sv[3]*inv);
    ov.z = pk2(sv[4]*inv, sv[5]*inv); ov.w = pk2(sv[6]*inv, sv[7]*inv);
    *(uint4*)(g_Kc + (size_t)bt*64 + c) = ok;
    *(uint4*)(g_Vc + (size_t)bt*64 + c) = ov;
}

// ------- Q-projection: g_Qh = LN-epi( xh @ W~q^T ), out 256-wide ---------------
__global__ __launch_bounds__(256, 2) void k_qproj()
{
    __shared__ __nv_bfloat16 As[2][128*40];
    __shared__ __nv_bfloat16 Bs[2][128*40];
    const int m0 = blockIdx.y * 128;
    const int o0 = blockIdx.x * 128;
    const int n  = m0 >> 12;
    const __nv_bfloat16* A = g_xh;
    const __nv_bfloat16* B = g_Wqt + (size_t)n * QW * Dd;

    const int tid = threadIdx.x, lane = tid & 31, warp = tid >> 5;
    const int wm = warp & 3, wn = warp >> 2;

    auto copyAB = [&](int st, int k0) {
        #pragma unroll
        for (int i = 0; i < 2; i++) {
            int idx = tid + i*256;
            int r = idx >> 2, c = (idx & 3) * 8;
            cpa16(&As[st][r*40 + c], A + (size_t)(m0 + r)*Dd + k0 + c);
            cpa16(&Bs[st][r*40 + c], B + (size_t)(o0 + r)*Dd + k0 + c);
        }
    };

    copyAB(0, 0);
    CPCOMMIT();

    float acc[2][8][4];
    #pragma unroll
    for (int i = 0; i < 2; i++)
        #pragma unroll
        for (int j = 0; j < 8; j++)
            #pragma unroll
            for (int k = 0; k < 4; k++) acc[i][j][k] = 0.f;

    const int arow = wm*32 + (lane & 15);
    const int acol = ((lane >> 4) & 1) * 8;
    const int brow = wn*64 + (lane & 7) + ((lane >> 4) & 1) * 8;
    const int bcol = ((lane >> 3) & 1) * 8;

    for (int ks = 0; ks < 16; ks++) {
        int st = ks & 1;
        CPWAIT0();
        __syncthreads();
        if (ks < 15) { copyAB(st ^ 1, (ks+1)*32); CPCOMMIT(); }

        const __nv_bfloat16* Asb = As[st];
        const __nv_bfloat16* Bsb = Bs[st];

        uint32_t af[2][2][4];
        #pragma unroll
        for (int mf = 0; mf < 2; mf++)
            #pragma unroll
            for (int kf = 0; kf < 2; kf++)
                ldsm4(af[mf][kf], Asb + (arow + mf*16)*40 + kf*16 + acol);

        #pragma unroll
        for (int ng = 0; ng < 4; ng++) {
            uint32_t bfr[2][4];
            #pragma unroll
            for (int kf = 0; kf < 2; kf++)
                ldsm4(bfr[kf], Bsb + (brow + ng*16)*40 + kf*16 + bcol);
            #pragma unroll
            for (int s = 0; s < 2; s++) {
                int nf = ng*2 + s;
                #pragma unroll
                for (int mf = 0; mf < 2; mf++) {
                    mmabf(acc[mf][nf], af[mf][0], bfr[0][2*s], bfr[0][2*s+1]);
                    mmabf(acc[mf][nf], af[mf][1], bfr[1][2*s], bfr[1][2*s+1]);
                }
            }
        }
    }

    const int mrow = m0 + wm*32 + (lane >> 2);
    const int ocol = o0 + wn*64 + (lane & 3)*2;
    #pragma unroll
    for (int mf = 0; mf < 2; mf++) {
        int r0 = mrow + mf*16, r1 = r0 + 8;
        float rs0 = g_rs[r0], mr0 = g_mu[r0]*rs0;
        float rs1 = g_rs[r1], mr1 = g_mu[r1]*rs1;
        #pragma unroll
        for (int nf = 0; nf < 8; nf++) {
            int c = ocol + nf*8;
            float sq0 = g_Sqt[n*QW + c], sq1 = g_Sqt[n*QW + c + 1];
            float cq0 = g_Cqt[n*QW + c], cq1 = g_Cqt[n*QW + c + 1];
            float* d = acc[mf][nf];
            *(uint32_t*)(g_Qh + (size_t)r0*QW + c) =
                pk2(rs0*d[0] - mr0*sq0 + cq0, rs0*d[1] - mr0*sq1 + cq1);
            *(uint32_t*)(g_Qh + (size_t)r1*QW + c) =
                pk2(rs1*d[2] - mr1*sq0 + cq0, rs1*d[3] - mr1*sq1 + cq1);
        }
    }
}

// ------- O-projection: Out = X + mask * (AOh @ W~o^T), K=256 --------------------
__global__ __launch_bounds__(256, 2) void k_oproj(const float* __restrict__ X,
                                                  float* __restrict__ Out)
{
    __shared__ __nv_bfloat16 As[2][128*40];
    __shared__ __nv_bfloat16 Bs[2][128*40];
    const int m0 = blockIdx.y * 128;
    const int o0 = blockIdx.x * 128;
    const int n  = m0 >> 12;
    const __nv_bfloat16* A = g_AOh;
    const __nv_bfloat16* B = g_Wot + (size_t)n * Dd * QW;

    const int tid = threadIdx.x, lane = tid & 31, warp = tid >> 5;
    const int wm = warp & 3, wn = warp >> 2;

    auto copyAB = [&](int st, int k0) {
        #pragma unroll
        for (int i = 0; i < 2; i++) {
            int idx = tid + i*256;
            int r = idx >> 2, c = (idx & 3) * 8;
            cpa16(&As[st][r*40 + c], A + (size_t)(m0 + r)*QW + k0 + c);
            cpa16(&Bs[st][r*40 + c], B + (size_t)(o0 + r)*QW + k0 + c);
        }
    };

    copyAB(0, 0);
    CPCOMMIT();

    float acc[2][8][4];
    #pragma unroll
    for (int i = 0; i < 2; i++)
        #pragma unroll
        for (int j = 0; j < 8; j++)
            #pragma unroll
            for (int k = 0; k < 4; k++) acc[i][j][k] = 0.f;

    const int arow = wm*32 + (lane & 15);
    const int acol = ((lane >> 4) & 1) * 8;
    const int brow = wn*64 + (lane & 7) + ((lane >> 4) & 1) * 8;
    const int bcol = ((lane >> 3) & 1) * 8;

    for (int ks = 0; ks < 8; ks++) {
        int st = ks & 1;
        CPWAIT0();
        __syncthreads();
        if (ks < 7) { copyAB(st ^ 1, (ks+1)*32); CPCOMMIT(); }

        const __nv_bfloat16* Asb = As[st];
        const __nv_bfloat16* Bsb = Bs[st];

        uint32_t af[2][2][4];
        #pragma unroll
        for (int mf = 0; mf < 2; mf++)
            #pragma unroll
            for (int kf = 0; kf < 2; kf++)
                ldsm4(af[mf][kf], Asb + (arow + mf*16)*40 + kf*16 + acol);

        #pragma unroll
        for (int ng = 0; ng < 4; ng++) {
            uint32_t bfr[2][4];
            #pragma unroll
            for (int kf = 0; kf < 2; kf++)
                ldsm4(bfr[kf], Bsb + (brow + ng*16)*40 + kf*16 + bcol);
            #pragma unroll
            for (int s = 0; s < 2; s++) {
                int nf = ng*2 + s;
                #pragma unroll
                for (int mf = 0; mf < 2; mf++) {
                    mmabf(acc[mf][nf], af[mf][0], bfr[0][2*s], bfr[0][2*s+1]);
                    mmabf(acc[mf][nf], af[mf][1], bfr[1][2*s], bfr[1][2*s+1]);
                }
            }
        }
    }

    const int mrow = m0 + wm*32 + (lane >> 2);
    const int ocol = o0 + wn*64 + (lane & 3)*2;
    float mfv = g_maskf[n];
    #pragma unroll
    for (int mf = 0; mf < 2; mf++) {
        int r0 = mrow + mf*16, r1 = r0 + 8;
        #pragma unroll
        for (int nf = 0; nf < 8; nf++) {
            int c = ocol + nf*8;
            float* d = acc[mf][nf];
            float2 x0 = *(const float2*)(X + (size_t)r0*Dd + c);
            float2 x1 = *(const float2*)(X + (size_t)r1*Dd + c);
            *(float2*)(Out + (size_t)r0*Dd + c) =
                make_float2(x0.x + mfv*d[0], x0.y + mfv*d[1]);
            *(float2*)(Out + (size_t)r1*Dd + c) =
                make_float2(x1.x + mfv*d[2], x1.y + mfv*d[3]);
        }
    }
}

// -------- flash attention in compressed space, 2 nbh + 2 q-tiles per block ------
__global__ __launch_bounds__(128) void k_flash()
{
    extern __shared__ __nv_bfloat16 smb[];
    __nv_bfloat16* Qs = smb;                       // [64][FS2]
    __nv_bfloat16* KV = Qs + 64*FS2;               // 2 K bufs + 2 V bufs
    const int tid = threadIdx.x, lane = tid & 31, warp = tid >> 5;
    const int r0q = warp*16 + (lane >> 2);
    const int c0q = (lane & 3) * 2;

    #pragma unroll 1
    for (int pp = 0; pp < 4; pp++) {
        const int grp = pp >> 1, phase = pp & 1;
        const int nbh = blockIdx.y + 64*grp;
        const int n = nbh >> 4, b = (nbh >> 2) & 3, h = nbh & 3;
        const size_t kvbase = (size_t)b * Tt * Rr;
        const int qt = phase ? (NT - 1 - (int)blockIdx.x) : (int)blockIdx.x;
        const int q0 = qt * 64;
        const size_t qbase = ((size_t)(n*Bb + b)*Tt + q0) * QW + h*Rr;

        if (pp) __syncthreads();

        #pragma unroll
        for (int i = 0; i < 4; i++) {
            int idx = tid + i*128;
            int r = idx >> 3, c = (idx & 7) * 8;
            cpa16(&Qs[r*FS2 + c], g_Qh + qbase + (size_t)r*QW + c);
        }
        CPCOMMIT();
        {
            __nv_bfloat16* Kb0 = KV;
            __nv_bfloat16* Vb0 = KV + (size_t)2 * 64*FS2;
            #pragma unroll
            for (int i = 0; i < 4; i++) {
                int idx = tid + i*128;
                int r = idx >> 3, c = (idx & 7)*8;
                cpa16(&Kb0[r*FS2 + c], g_Kc + kvbase + (size_t)r*Rr + c);
                cpa16(&Vb0[r*FS2 + c], g_Vc + kvbase + (size_t)r*Rr + c);
            }
        }
        CPCOMMIT();
        CPWAIT0();
        __syncthreads();

        uint32_t qf[4][4];
        {
            const __nv_bfloat16* qp = Qs + (warp*16 + (lane & 15))*FS2 + (lane >> 4)*8;
            #pragma unroll
            for (int kf = 0; kf < 4; kf++) ldsm4(qf[kf], qp + kf*16);
        }

        float accO[8][4];
        #pragma unroll
        for (int i = 0; i < 8; i++)
            #pragma unroll
            for (int j = 0; j < 4; j++) accO[i][j] = 0.f;
        float mrow[2] = {-1e30f, -1e30f};
        float lrow[2] = {0.f, 0.f};

        for (int kt = 0; kt <= qt; kt++) {
            if (kt > 0) { CPWAIT0(); __syncthreads(); }
            if (kt < qt) {
                const int nk = (kt+1)*64;
                __nv_bfloat16* Kb2 = KV + (size_t)((kt+1) & 1) * 64*FS2;
                __nv_bfloat16* Vb2 = KV + (size_t)(2 + ((kt+1) & 1)) * 64*FS2;
                #pragma unroll
                for (int i = 0; i < 4; i++) {
                    int idx = tid + i*128;
                    int r = idx >> 3, c = (idx & 7)*8;
                    cpa16(&Kb2[r*FS2 + c], g_Kc + kvbase + (size_t)(nk + r)*Rr + c);
                    cpa16(&Vb2[r*FS2 + c], g_Vc + kvbase + (size_t)(nk + r)*Rr + c);
                }
                CPCOMMIT();
            }

            const __nv_bfloat16* Kb = KV + (size_t)(kt & 1) * 64*FS2;
            const __nv_bfloat16* Vb = KV + (size_t)(2 + (kt & 1)) * 64*FS2;

            float sfr[8][4];
            #pragma unroll
            for (int i = 0; i < 8; i++)
                #pragma unroll
                for (int j = 0; j < 4; j++) sfr[i][j] = 0.f;

            {
                const __nv_bfloat16* kp = Kb + ((lane & 7) + ((lane >> 4) & 1)*8)*FS2
                                             + ((lane >> 3) & 1)*8;
                #pragma unroll
                for (int ng = 0; ng < 4; ng++) {
                    #pragma unroll
                    for (int kf = 0; kf < 4; kf++) {
                        uint32_t bf[4];
                        ldsm4(bf, kp + ng*16*FS2 + kf*16);
                        mmabf(sfr[2*ng],   qf[kf], bf[0], bf[1]);
                        mmabf(sfr[2*ng+1], qf[kf], bf[2], bf[3]);
                    }
                }
            }

            if (kt == qt) {
                #pragma unroll
                for (int j = 0; j < 8; j++) {
                    int cj = 8*j + c0q;
                    #pragma unroll
                    for (int rr = 0; rr < 2; rr++) {
                        int ri = r0q + 8*rr;
                        if (cj     > ri) sfr[j][2*rr]   = -1e30f;
                        if (cj + 1 > ri) sfr[j][2*rr+1] = -1e30f;
                    }
                }
            }

            #pragma unroll
            for (int rr = 0; rr < 2; rr++) {
                float tm = -1e30f;
                #pragma unroll
                for (int j = 0; j < 8; j++)
                    tm = fmaxf(tm, fmaxf(sfr[j][2*rr], sfr[j][2*rr+1]));
                tm = fmaxf(tm, __shfl_xor_sync(0xffffffffu, tm, 1));
                tm = fmaxf(tm, __shfl_xor_sync(0xffffffffu, tm, 2));
                float mnew = fmaxf(mrow[rr], tm);
                float scl = exp2f((mrow[rr] - mnew) * L2E);
                float ps = 0.f;
                #pragma unroll
                for (int j = 0; j < 8; j++) {
                    float e0 = exp2f((sfr[j][2*rr]   - mnew) * L2E);
                    float e1 = exp2f((sfr[j][2*rr+1] - mnew) * L2E);
                    sfr[j][2*rr] = e0; sfr[j][2*rr+1] = e1;
                    ps += e0 + e1;
                }
                ps += __shfl_xor_sync(0xffffffffu, ps, 1);
                ps += __shfl_xor_sync(0xffffffffu, ps, 2);
                lrow[rr] = lrow[rr]*scl + ps;
                mrow[rr] = mnew;
                #pragma unroll
                for (int nf = 0; nf < 8; nf++) {
                    accO[nf][2*rr]   *= scl;
                    accO[nf][2*rr+1] *= scl;
                }
            }

            uint32_t pa[4][4];
            #pragma unroll
            for (int kg = 0; kg < 4; kg++) {
                pa[kg][0] = pk2(sfr[2*kg][0],   sfr[2*kg][1]);
                pa[kg][1] = pk2(sfr[2*kg][2],   sfr[2*kg][3]);
                pa[kg][2] = pk2(sfr[2*kg+1][0], sfr[2*kg+1][1]);
                pa[kg][3] = pk2(sfr[2*kg+1][2], sfr[2*kg+1][3]);
            }

            {
                const __nv_bfloat16* vp = Vb + (lane & 15)*FS2 + (lane >> 4)*8;
                #pragma unroll
                for (int dg = 0; dg < 4; dg++) {
                    #pragma unroll
                    for (int kg = 0; kg < 4; kg++) {
                        uint32_t vb[4];
                        ldsm4t(vb, vp + kg*16*FS2 + dg*16);
                        mmabf(accO[2*dg],   pa[kg], vb[0], vb[1]);
                        mmabf(accO[2*dg+1], pa[kg], vb[2], vb[3]);
                    }
                }
            }
        }

        #pragma unroll
        for (int rr = 0; rr < 2; rr++) {
            float inv = 1.f / lrow[rr];
            size_t row = (size_t)(n*Bb + b)*Tt + q0 + r0q + 8*rr;
            __nv_bfloat16* dst = g_AOh + row*QW + h*Rr;
            #pragma unroll
            for (int nf = 0; nf < 8; nf++) {
                *(uint32_t*)(dst + 8*nf + c0q) =
                    pk2(accO[nf][2*rr]*inv, accO[nf][2*rr+1]*inv);
            }
        }
    }
}

// ---------------- launch ----------------
extern "C" void kernel_launch(void* const* d_in, const int* in_sizes, int n_in,
                              void* d_out, int out_size)
{
    (void)in_sizes; (void)n_in; (void)out_size;
    const float* x     = (const float*)d_in[0];
    const unsigned char* mask = (const unsigned char*)d_in[1];
    const float* lnkw  = (const float*)d_in[2];
    const float* lnkb  = (const float*)d_in[3];
    const float* lnqw  = (const float*)d_in[4];
    const float* lnqb  = (const float*)d_in[5];
    const float* wk    = (const float*)d_in[6];
    const float* wv    = (const float*)d_in[7];
    const float* wq    = (const float*)d_in[8];
    const float* wo    = (const float*)d_in[9];
    const float* kcomp = (const float*)d_in[10];
    const float* vcomp = (const float*)d_in[11];
    const float* kdec  = (const float*)d_in[12];
    const float* vdec  = (const float*)d_in[13];
    float* out = (float*)d_out;

    static cudaStream_t s1 = nullptr, s2 = nullptr;
    static cudaEvent_t eRoot, eLn, eWo, eH0;
    static bool init_done = false;
    if (!init_done) {
        cudaStreamCreateWithFlags(&s1, cudaStreamNonBlocking);
        cudaStreamCreateWithFlags(&s2, cudaStreamNonBlocking);
        cudaEventCreateWithFlags(&eRoot, cudaEventDisableTiming);
        cudaEventCreateWithFlags(&eLn,   cudaEventDisableTiming);
        cudaEventCreateWithFlags(&eWo,   cudaEventDisableTiming);
        cudaEventCreateWithFlags(&eH0,   cudaEventDisableTiming);
        cudaFuncSetAttribute(k_flash, cudaFuncAttributeMaxDynamicSharedMemorySize,
                             5*64*FS2*2);
        cudaFuncSetAttribute(k_kvmma, cudaFuncAttributeMaxDynamicSharedMemorySize,
                             2*2*5120*2);
        init_done = true;
    }

    // fork
    cudaEventRecord(eRoot, 0);
    cudaStreamWaitEvent(s1, eRoot, 0);
    cudaStreamWaitEvent(s2, eRoot, 0);

    // s1: mask + LN stats (+ bf16 x), then absorbed O weights
    k_mask<<<1, 32, 0, s1>>>(mask);
    k_lnstats<<<NROWS/8, 256, 0, s1>>>(x);
    cudaEventRecord(eLn, s1);
    k_wo<<<dim3(Nn, Hh, 8), 256, 0, s1>>>(wo, vdec);
    cudaEventRecord(eWo, s1);

    // s2: absorbed Q weights + Q projection
    k_cq<<<Nn*Dd/8, 256, 0, s2>>>(lnqb, wq);
    k_wq<<<dim3(Nn, Hh, 8), 256, 0, s2>>>(wq, lnqw, kdec);
    k_wq2<<<Nn*QW/256, 256, 0, s2>>>(kdec);
    cudaStreamWaitEvent(s2, eLn, 0);
    k_qproj<<<dim3(2, NROWS/128), 256, 0, s2>>>();
    cudaEventRecord(eH0, s2);

    // s0: KV chain
    k_compgemm<<<dim3(Nn, 2, 8), 256>>>(kcomp, vcomp, wk, wv, lnkw, lnkb);
    k_foldSC<<<Nn*128/256, 256>>>();
    cudaStreamWaitEvent(0, eLn, 0);
    k_kvmma<<<NROWS/128, 256, 2*2*5120*2>>>();
    k_avg<<<BTc*Rr/8/256, 256>>>();
    cudaStreamWaitEvent(0, eH0, 0);
    k_flash<<<dim3(NT/2, Nn*Bb*Hh/2), 128, 5*64*FS2*2>>>();
    cudaStreamWaitEvent(0, eWo, 0);
    k_oproj<<<dim3(4, NROWS/128), 256>>>(x, out);
}